// round 2
// baseline (speedup 1.0000x reference)
#include <cuda_runtime.h>

// Problem constants (fixed by the dataset)
#define BATCH   8192
#define INDIM   768
#define NC      64      // concepts
#define HD      64      // hidden
#define ED      16      // embedding
#define TILE_R  128     // batch rows per CTA
#define KC      32      // k-chunk for weight staging
#define NTHREADS 256

#define XS_S 36         // xs row stride (32 + 4 pad, keeps float4 alignment)
#define HB_S 65         // hb row stride (64 + 1 pad, scalar access)

__device__ __forceinline__ float relu_(float v) { return v > 0.f ? v : 0.f; }

// In-place 64->64 dense layer: hb = act(hb @ W[c] + b[c])
// W: [NC][HD][HD] row-major (k rows, j cols). wb: smem scratch [KC][HD].
__device__ __forceinline__ void dense64(
    const float* __restrict__ W, const float* __restrict__ bias, int c,
    float* __restrict__ hb, float* __restrict__ wb,
    int tid, int tx, int rbase, bool do_relu)
{
    float acc[8][4];
#pragma unroll
    for (int i = 0; i < 8; i++)
#pragma unroll
        for (int j = 0; j < 4; j++) acc[i][j] = 0.f;

    for (int kb = 0; kb < HD; kb += KC) {
        __syncthreads();   // protect wb from previous readers
        for (int t = tid; t < KC * (HD / 4); t += NTHREADS) {
            int k = t >> 4, q = t & 15;
            *(float4*)(wb + k * HD + q * 4) =
                *(const float4*)(W + ((size_t)c * HD + kb + k) * HD + q * 4);
        }
        __syncthreads();
#pragma unroll 4
        for (int k = 0; k < KC; ++k) {
            float4 wv = *(const float4*)(wb + k * HD + tx * 4);
#pragma unroll
            for (int i = 0; i < 8; ++i) {
                float xv = hb[(rbase + i) * HB_S + kb + k];
                acc[i][0] = fmaf(xv, wv.x, acc[i][0]);
                acc[i][1] = fmaf(xv, wv.y, acc[i][1]);
                acc[i][2] = fmaf(xv, wv.z, acc[i][2]);
                acc[i][3] = fmaf(xv, wv.w, acc[i][3]);
            }
        }
    }
    __syncthreads();       // all reads of hb done -> safe to overwrite in place
    float4 bv = *(const float4*)(bias + c * HD + tx * 4);
#pragma unroll
    for (int i = 0; i < 8; ++i) {
        float v0 = acc[i][0] + bv.x;
        float v1 = acc[i][1] + bv.y;
        float v2 = acc[i][2] + bv.z;
        float v3 = acc[i][3] + bv.w;
        if (do_relu) { v0 = relu_(v0); v1 = relu_(v1); v2 = relu_(v2); v3 = relu_(v3); }
        hb[(rbase + i) * HB_S + tx * 4 + 0] = v0;
        hb[(rbase + i) * HB_S + tx * 4 + 1] = v1;
        hb[(rbase + i) * HB_S + tx * 4 + 2] = v2;
        hb[(rbase + i) * HB_S + tx * 4 + 3] = v3;
    }
    __syncthreads();
}

__global__ __launch_bounds__(NTHREADS, 2)
void cb_kernel(
    const float* __restrict__ x,
    const float* __restrict__ posW1, const float* __restrict__ posb1,
    const float* __restrict__ posW2, const float* __restrict__ posb2,
    const float* __restrict__ posW3, const float* __restrict__ posb3,
    const float* __restrict__ negW1, const float* __restrict__ negb1,
    const float* __restrict__ negW2, const float* __restrict__ negb2,
    const float* __restrict__ negW3, const float* __restrict__ negb3,
    const float* __restrict__ cpW1,  const float* __restrict__ cpb1,
    const float* __restrict__ cpW2,  const float* __restrict__ cpb2,
    const float* __restrict__ cpW3,  const float* __restrict__ cpb3,
    float* __restrict__ out)
{
    extern __shared__ float sm[];
    float* xs   = sm;                       // [128][XS_S]   4608 f
    float* wb   = xs + TILE_R * XS_S;       // [KC][HD]      2048 f
    float* hb   = wb + KC * HD;             // [128][HB_S]   8320 f
    float* ps   = hb + TILE_R * HB_S;       // [128][ED]     2048 f
    float* ns   = ps + TILE_R * ED;         // [128][ED]     2048 f
    float* gate = ns + TILE_R * ED;         // [128]          128 f

    const int tid   = threadIdx.x;
    const int c     = blockIdx.y;            // concept
    const int r0    = blockIdx.x * TILE_R;   // batch row base
    const int tx    = tid & 15;              // col group (4 cols / 1 e-col)
    const int ty    = tid >> 4;              // row group (8 rows)
    const int rbase = ty * 8;

    // ---------- pos / neg banks ----------
    for (int bank = 0; bank < 2; ++bank) {
        const float* W1 = bank ? negW1 : posW1;
        const float* b1 = bank ? negb1 : posb1;
        const float* W2 = bank ? negW2 : posW2;
        const float* b2 = bank ? negb2 : posb2;
        const float* W3 = bank ? negW3 : posW3;
        const float* b3 = bank ? negb3 : posb3;
        float* obuf = bank ? ns : ps;

        // ----- layer 1: [128 x 768] @ [768 x 64], k-chunked streaming -----
        float acc[8][4];
#pragma unroll
        for (int i = 0; i < 8; i++)
#pragma unroll
            for (int j = 0; j < 4; j++) acc[i][j] = 0.f;

        for (int kb = 0; kb < INDIM; kb += KC) {
            __syncthreads();
            // stage x chunk: 128 rows x 32 cols (8 float4 per row)
            for (int t = tid; t < TILE_R * (KC / 4); t += NTHREADS) {
                int r = t >> 3, q = t & 7;
                *(float4*)(xs + r * XS_S + q * 4) =
                    *(const float4*)(x + (size_t)(r0 + r) * INDIM + kb + q * 4);
            }
            // stage W1 chunk: [KC][HD]
            for (int t = tid; t < KC * (HD / 4); t += NTHREADS) {
                int k = t >> 4, q = t & 15;
                *(float4*)(wb + k * HD + q * 4) =
                    *(const float4*)(W1 + ((size_t)c * INDIM + kb + k) * HD + q * 4);
            }
            __syncthreads();
#pragma unroll 4
            for (int k = 0; k < KC; ++k) {
                float4 wv = *(const float4*)(wb + k * HD + tx * 4);
#pragma unroll
                for (int i = 0; i < 8; ++i) {
                    float xv = xs[(rbase + i) * XS_S + k];
                    acc[i][0] = fmaf(xv, wv.x, acc[i][0]);
                    acc[i][1] = fmaf(xv, wv.y, acc[i][1]);
                    acc[i][2] = fmaf(xv, wv.z, acc[i][2]);
                    acc[i][3] = fmaf(xv, wv.w, acc[i][3]);
                }
            }
        }
        __syncthreads();
        {
            float4 bv = *(const float4*)(b1 + c * HD + tx * 4);
#pragma unroll
            for (int i = 0; i < 8; ++i) {
                hb[(rbase + i) * HB_S + tx * 4 + 0] = relu_(acc[i][0] + bv.x);
                hb[(rbase + i) * HB_S + tx * 4 + 1] = relu_(acc[i][1] + bv.y);
                hb[(rbase + i) * HB_S + tx * 4 + 2] = relu_(acc[i][2] + bv.z);
                hb[(rbase + i) * HB_S + tx * 4 + 3] = relu_(acc[i][3] + bv.w);
            }
        }
        __syncthreads();

        // ----- layer 2: 64 -> 64, relu, in place -----
        dense64(W2, b2, c, hb, wb, tid, tx, rbase, true);

        // ----- layer 3: 64 -> 16 (no relu) -----
        for (int t = tid; t < HD * ED / 4; t += NTHREADS) {
            *(float4*)(wb + t * 4) =
                *(const float4*)(W3 + (size_t)c * HD * ED + t * 4);
        }
        __syncthreads();
        {
            float a3[8];
#pragma unroll
            for (int i = 0; i < 8; i++) a3[i] = 0.f;
#pragma unroll 4
            for (int k = 0; k < HD; ++k) {
                float w = wb[k * ED + tx];   // tx = e column here
#pragma unroll
                for (int i = 0; i < 8; ++i)
                    a3[i] = fmaf(hb[(rbase + i) * HB_S + k], w, a3[i]);
            }
            float bv = b3[c * ED + tx];
#pragma unroll
            for (int i = 0; i < 8; ++i)
                obuf[(rbase + i) * ED + tx] = a3[i] + bv;
        }
        __syncthreads();
    }

    // ---------- cp bank ----------
    // layer 1: [128 x 32] (ps||ns) @ [32 x 64], relu
    {
        float acc[8][4];
#pragma unroll
        for (int i = 0; i < 8; i++)
#pragma unroll
            for (int j = 0; j < 4; j++) acc[i][j] = 0.f;

        for (int t = tid; t < (2 * ED) * (HD / 4); t += NTHREADS) {  // 512 float4
            *(float4*)(wb + t * 4) =
                *(const float4*)(cpW1 + (size_t)c * 2 * ED * HD + t * 4);
        }
        __syncthreads();
#pragma unroll 4
        for (int k = 0; k < ED; ++k) {           // first 16 k: pos
            float4 wv = *(const float4*)(wb + k * HD + tx * 4);
#pragma unroll
            for (int i = 0; i < 8; ++i) {
                float xv = ps[(rbase + i) * ED + k];
                acc[i][0] = fmaf(xv, wv.x, acc[i][0]);
                acc[i][1] = fmaf(xv, wv.y, acc[i][1]);
                acc[i][2] = fmaf(xv, wv.z, acc[i][2]);
                acc[i][3] = fmaf(xv, wv.w, acc[i][3]);
            }
        }
#pragma unroll 4
        for (int k = 0; k < ED; ++k) {           // next 16 k: neg
            float4 wv = *(const float4*)(wb + (k + ED) * HD + tx * 4);
#pragma unroll
            for (int i = 0; i < 8; ++i) {
                float xv = ns[(rbase + i) * ED + k];
                acc[i][0] = fmaf(xv, wv.x, acc[i][0]);
                acc[i][1] = fmaf(xv, wv.y, acc[i][1]);
                acc[i][2] = fmaf(xv, wv.z, acc[i][2]);
                acc[i][3] = fmaf(xv, wv.w, acc[i][3]);
            }
        }
        __syncthreads();
        float4 bv = *(const float4*)(cpb1 + c * HD + tx * 4);
#pragma unroll
        for (int i = 0; i < 8; ++i) {
            hb[(rbase + i) * HB_S + tx * 4 + 0] = relu_(acc[i][0] + bv.x);
            hb[(rbase + i) * HB_S + tx * 4 + 1] = relu_(acc[i][1] + bv.y);
            hb[(rbase + i) * HB_S + tx * 4 + 2] = relu_(acc[i][2] + bv.z);
            hb[(rbase + i) * HB_S + tx * 4 + 3] = relu_(acc[i][3] + bv.w);
        }
        __syncthreads();
    }

    // cp layer 2: 64 -> 64, relu, in place
    dense64(cpW2, cpb2, c, hb, wb, tid, tx, rbase, true);

    // cp layer 3: 64 -> 1, then gate
    if (tid < HD) wb[tid] = cpW3[(size_t)c * HD + tid];
    __syncthreads();
    if (tid < TILE_R) {
        float s = cpb3[c];
#pragma unroll 4
        for (int k = 0; k < HD; ++k)
            s = fmaf(hb[tid * HB_S + k], wb[k], s);
        // concepts output: offset after emb_flat block
        out[(size_t)BATCH * ED * NC + (size_t)(r0 + tid) * NC + c] = s;
        float g = fminf(fmaxf(s * 0.5f + 0.5f, 0.f), 1.f);
        gate[tid] = g;
    }
    __syncthreads();

    // gated embedding, torch layout: emb_flat[b, e*C + c] = emb[b, c, e]
    for (int t = tid; t < TILE_R * ED; t += NTHREADS) {
        int r = t >> 4, e = t & 15;
        float g = gate[r];
        float v = ps[r * ED + e] * g + ns[r * ED + e] * (1.f - g);
        out[(size_t)(r0 + r) * (ED * NC) + e * NC + c] = v;
    }
}

extern "C" void kernel_launch(void* const* d_in, const int* in_sizes, int n_in,
                              void* d_out, int out_size) {
    (void)in_sizes; (void)n_in; (void)out_size;
    const int smem_bytes = (TILE_R * XS_S + KC * HD + TILE_R * HB_S +
                            2 * TILE_R * ED + TILE_R) * sizeof(float);  // 76800 B
    cudaFuncSetAttribute(cb_kernel, cudaFuncAttributeMaxDynamicSharedMemorySize,
                         smem_bytes);
    dim3 grid(BATCH / TILE_R, NC);   // 64 x 64 = 4096 CTAs
    cb_kernel<<<grid, NTHREADS, smem_bytes>>>(
        (const float*)d_in[0],
        (const float*)d_in[1],  (const float*)d_in[2],
        (const float*)d_in[3],  (const float*)d_in[4],
        (const float*)d_in[5],  (const float*)d_in[6],
        (const float*)d_in[7],  (const float*)d_in[8],
        (const float*)d_in[9],  (const float*)d_in[10],
        (const float*)d_in[11], (const float*)d_in[12],
        (const float*)d_in[13], (const float*)d_in[14],
        (const float*)d_in[15], (const float*)d_in[16],
        (const float*)d_in[17], (const float*)d_in[18],
        (float*)d_out);
}

// round 5
// speedup vs baseline: 2.3968x; 2.3968x over previous
#include <cuda_runtime.h>
#include <cstdint>

// Problem constants
#define BATCH   8192
#define INDIM   768
#define NC      64
#define HD      64
#define ED      16
#define TILE_R  128
#define NTHREADS 256

#define HB_S 65

// layer-1 staging: 24 stages of K=32
#define KC_T   32
#define NSTAGE (INDIM / KC_T)
#define STG_F  8192            // floats per stage buffer: A 4096 + Bpos 2048 + Bneg 2048

// SMEM float offsets.  Stage buffers [0, 16384) are reused by the tail
// workspace after layer 1 (mma accumulators live in registers, so stage
// memory is dead once the k-loop finishes).
#define HBN_OFF   0            // hb_neg   [128][65] = 8320   (aliases stage bufs)
#define WB_OFF    8320         // wb       2048
#define PS_OFF    10368        // ps       [128][16] = 2048
#define NS_OFF    12416        // ns       2048
#define GATE_OFF  14464        // gate     128
#define HBP_OFF   16384        // hb_pos   8320
#define BIAS_OFF  24704        // pos b1 | neg b1 = 128
#define SMEM_FLOATS 24832      // 99328 bytes -> 2 CTAs/SM

__device__ __forceinline__ float relu_(float v) { return v > 0.f ? v : 0.f; }

__device__ __forceinline__ float tf32r(float v) {
    uint32_t u;
    asm("cvt.rna.tf32.f32 %0, %1;" : "=r"(u) : "f"(v));
    return __uint_as_float(u);
}

// m16n8k8 tf32 mma (arch-agnostic PTX, compiles for sm_103 target)
__device__ __forceinline__ void mma8(float* d, const float4& a, const float2& b) {
    asm volatile(
        "mma.sync.aligned.m16n8k8.row.col.f32.tf32.tf32.f32 "
        "{%0,%1,%2,%3}, {%4,%5,%6,%7}, {%8,%9}, {%0,%1,%2,%3};"
        : "+f"(d[0]), "+f"(d[1]), "+f"(d[2]), "+f"(d[3])
        : "r"(__float_as_uint(a.x)), "r"(__float_as_uint(a.y)),
          "r"(__float_as_uint(a.z)), "r"(__float_as_uint(a.w)),
          "r"(__float_as_uint(b.x)), "r"(__float_as_uint(b.y)));
}

// ---------------- SIMT tail pieces (proven in R1) ----------------
__device__ __forceinline__ void dense64(
    const float* __restrict__ W, const float* __restrict__ bias, int c,
    float* __restrict__ hb, float* __restrict__ wb,
    int tid, int tx, int rbase, bool do_relu)
{
    float acc[8][4];
#pragma unroll
    for (int i = 0; i < 8; i++)
#pragma unroll
        for (int j = 0; j < 4; j++) acc[i][j] = 0.f;

    for (int kb = 0; kb < HD; kb += 32) {
        __syncthreads();
        for (int t = tid; t < 32 * (HD / 4); t += NTHREADS) {
            int k = t >> 4, q = t & 15;
            *(float4*)(wb + k * HD + q * 4) =
                *(const float4*)(W + ((size_t)c * HD + kb + k) * HD + q * 4);
        }
        __syncthreads();
#pragma unroll 4
        for (int k = 0; k < 32; ++k) {
            float4 wv = *(const float4*)(wb + k * HD + tx * 4);
#pragma unroll
            for (int i = 0; i < 8; ++i) {
                float xv = hb[(rbase + i) * HB_S + kb + k];
                acc[i][0] = fmaf(xv, wv.x, acc[i][0]);
                acc[i][1] = fmaf(xv, wv.y, acc[i][1]);
                acc[i][2] = fmaf(xv, wv.z, acc[i][2]);
                acc[i][3] = fmaf(xv, wv.w, acc[i][3]);
            }
        }
    }
    __syncthreads();
    float4 bv = *(const float4*)(bias + c * HD + tx * 4);
#pragma unroll
    for (int i = 0; i < 8; ++i) {
        float v0 = acc[i][0] + bv.x, v1 = acc[i][1] + bv.y;
        float v2 = acc[i][2] + bv.z, v3 = acc[i][3] + bv.w;
        if (do_relu) { v0 = relu_(v0); v1 = relu_(v1); v2 = relu_(v2); v3 = relu_(v3); }
        hb[(rbase + i) * HB_S + tx * 4 + 0] = v0;
        hb[(rbase + i) * HB_S + tx * 4 + 1] = v1;
        hb[(rbase + i) * HB_S + tx * 4 + 2] = v2;
        hb[(rbase + i) * HB_S + tx * 4 + 3] = v3;
    }
    __syncthreads();
}

__device__ __forceinline__ void layer3(
    const float* __restrict__ W3, const float* __restrict__ b3, int c,
    const float* __restrict__ hb, float* __restrict__ wb, float* __restrict__ obuf,
    int tid, int tx, int rbase)
{
    for (int t = tid; t < HD * ED / 4; t += NTHREADS)
        *(float4*)(wb + t * 4) = *(const float4*)(W3 + (size_t)c * HD * ED + t * 4);
    __syncthreads();
    float a3[8];
#pragma unroll
    for (int i = 0; i < 8; i++) a3[i] = 0.f;
#pragma unroll 4
    for (int k = 0; k < HD; ++k) {
        float w = wb[k * ED + tx];
#pragma unroll
        for (int i = 0; i < 8; ++i)
            a3[i] = fmaf(hb[(rbase + i) * HB_S + k], w, a3[i]);
    }
    float bv = b3[c * ED + tx];
#pragma unroll
    for (int i = 0; i < 8; ++i)
        obuf[(rbase + i) * ED + tx] = a3[i] + bv;
    __syncthreads();
}

// ---------------- layer-1 staging (LDG side / STS side split for pipelining) ----------------
// A fragment storage: (tile_m, tile_k) tile of 128 floats: slot = (lane^tile_k)*4 + reg
//   reg order [a0,a1,a2,a3]; a0/a1 = rows r/r+8, a2/a3 = cols +4.
// B fragment storage (per bank, base +4096 [+2048 for neg]):
//   (tile_n, tile_k) tile of 64 floats: slot = (lane^((tile_k^tile_n)&3))*2 + reg,
//   reg order [b0,b1] = k / k+4.

__device__ __forceinline__ void stage_ldg(
    const float* __restrict__ x, const float* __restrict__ Wp,
    const float* __restrict__ Wn, int r0, int c, int kb, int tid,
    float4* xa /*4*/, float4* wv /*4*/)
{
#pragma unroll
    for (int i = 0; i < 2; ++i) {
        int item = tid + i * NTHREADS;      // 0..511
        int rp = item >> 3, cg = item & 7;
        int r = ((rp >> 3) << 4) | (rp & 7);
        const float* p = x + (size_t)(r0 + r) * INDIM + kb + cg * 4;
        xa[2 * i + 0] = *(const float4*)p;
        xa[2 * i + 1] = *(const float4*)(p + 8 * INDIM);
    }
    int kp = tid >> 4, ng = tid & 15;
    int k = (kp & 3) | ((kp >> 2) << 3);
    {
        const float* p = Wp + ((size_t)c * INDIM + kb + k) * HD + ng * 4;
        wv[0] = *(const float4*)p;
        wv[1] = *(const float4*)(p + 4 * HD);
        const float* q = Wn + ((size_t)c * INDIM + kb + k) * HD + ng * 4;
        wv[2] = *(const float4*)q;
        wv[3] = *(const float4*)(q + 4 * HD);
    }
}

__device__ __forceinline__ void stage_sts(
    float* __restrict__ stg, int tid, const float4* xa, const float4* wv)
{
    // A: 16 floats -> 8 x STS.64
#pragma unroll
    for (int i = 0; i < 2; ++i) {
        int item = tid + i * NTHREADS;
        int rp = item >> 3, cg = item & 7;
        int tile_m = rp >> 3;
        int tile_k = cg >> 1, ckhi = cg & 1;
        int lane_base = (rp & 7) * 4;
        const float* lo = (const float*)&xa[2 * i + 0];
        const float* hi = (const float*)&xa[2 * i + 1];
#pragma unroll
        for (int j = 0; j < 4; ++j) {
            int lane_s = (lane_base + j) ^ tile_k;
            int off = (tile_m * 4 + tile_k) * 128 + lane_s * 4 + ckhi * 2;
            *(float2*)(stg + off) = make_float2(tf32r(lo[j]), tf32r(hi[j]));
        }
    }
    // B: 2 banks x 8 floats -> 8 x STS.64
    int kp = tid >> 4, ng = tid & 15;
    int tile_k = kp >> 2;
#pragma unroll
    for (int bw = 0; bw < 2; ++bw) {
        const float* lo = (const float*)&wv[2 * bw + 0];
        const float* hi = (const float*)&wv[2 * bw + 1];
#pragma unroll
        for (int j = 0; j < 4; ++j) {
            int n = ng * 4 + j;
            int tile_n = n >> 3, nn = n & 7;
            int lane = nn * 4 + (kp & 3);
            int lane_s = lane ^ ((tile_k ^ tile_n) & 3);
            int off = 4096 + bw * 2048 + (tile_n * 4 + tile_k) * 64 + lane_s * 2;
            *(float2*)(stg + off) = make_float2(tf32r(lo[j]), tf32r(hi[j]));
        }
    }
}

// ---------------- main kernel ----------------
__global__ __launch_bounds__(NTHREADS, 2)
void cb_kernel(
    const float* __restrict__ x,
    const float* __restrict__ posW1, const float* __restrict__ posb1,
    const float* __restrict__ posW2, const float* __restrict__ posb2,
    const float* __restrict__ posW3, const float* __restrict__ posb3,
    const float* __restrict__ negW1, const float* __restrict__ negb1,
    const float* __restrict__ negW2, const float* __restrict__ negb2,
    const float* __restrict__ negW3, const float* __restrict__ negb3,
    const float* __restrict__ cpW1,  const float* __restrict__ cpb1,
    const float* __restrict__ cpW2,  const float* __restrict__ cpb2,
    const float* __restrict__ cpW3,  const float* __restrict__ cpb3,
    float* __restrict__ out)
{
    extern __shared__ float sm[];
    float* hb_neg = sm + HBN_OFF;
    float* wb     = sm + WB_OFF;
    float* ps     = sm + PS_OFF;
    float* ns     = sm + NS_OFF;
    float* gate   = sm + GATE_OFF;
    float* hb_pos = sm + HBP_OFF;
    float* bias_s = sm + BIAS_OFF;

    const int tid  = threadIdx.x;
    const int wid  = tid >> 5, lane = tid & 31;
    const int c    = blockIdx.y;
    const int r0   = blockIdx.x * TILE_R;
    const int tx    = tid & 15;
    const int rbase = (tid >> 4) * 8;

    if (tid < 64)       bias_s[tid] = posb1[c * HD + tid];
    else if (tid < 128) bias_s[tid] = negb1[c * HD + tid - 64];

    // ---- layer 1 on tensor cores (tf32 mma.sync) ----
    const int bank = wid >> 2;             // 0: pos, 1: neg
    const int tmA  = (wid & 3) * 2;        // two m16 tiles per warp (32 rows)
    const int tmB  = tmA + 1;

    float acc[2][8][4];
#pragma unroll
    for (int m = 0; m < 2; m++)
#pragma unroll
        for (int n = 0; n < 8; n++)
#pragma unroll
            for (int j = 0; j < 4; j++) acc[m][n][j] = 0.f;

    float4 xa[4], wv[4];
    stage_ldg(x, posW1, negW1, r0, c, 0, tid, xa, wv);
    stage_sts(sm, tid, xa, wv);
    __syncthreads();

    for (int s = 0; s < NSTAGE; ++s) {
        if (s + 1 < NSTAGE)
            stage_ldg(x, posW1, negW1, r0, c, (s + 1) * KC_T, tid, xa, wv);

        const float* A  = sm + (s & 1) * STG_F;
        const float* Bb = A + 4096 + bank * 2048;
#pragma unroll
        for (int tk = 0; tk < 4; ++tk) {
            float4 a0 = *(const float4*)(A + (tmA * 4 + tk) * 128 + (lane ^ tk) * 4);
            float4 a1 = *(const float4*)(A + (tmB * 4 + tk) * 128 + (lane ^ tk) * 4);
#pragma unroll
            for (int tn = 0; tn < 8; ++tn) {
                float2 bv = *(const float2*)(Bb + (tn * 4 + tk) * 64 +
                                             (lane ^ ((tk ^ tn) & 3)) * 2);
                mma8(acc[0][tn], a0, bv);
                mma8(acc[1][tn], a1, bv);
            }
        }
        __syncthreads();
        if (s + 1 < NSTAGE) {
            stage_sts(sm + ((s + 1) & 1) * STG_F, tid, xa, wv);
            __syncthreads();
        }
    }

    // ---- epilogue: bias + relu, regs -> hb_pos / hb_neg (aliases stage bufs) ----
    {
        float* hbT = bank ? hb_neg : hb_pos;
        const float* bs = bias_s + bank * 64;
        const int gid = lane >> 2, qid = lane & 3;
#pragma unroll
        for (int m = 0; m < 2; ++m) {
            int row = (wid & 3) * 32 + m * 16 + gid;
#pragma unroll
            for (int tn = 0; tn < 8; ++tn) {
                int col = tn * 8 + qid * 2;
                hbT[row * HB_S + col]           = relu_(acc[m][tn][0] + bs[col]);
                hbT[row * HB_S + col + 1]       = relu_(acc[m][tn][1] + bs[col + 1]);
                hbT[(row + 8) * HB_S + col]     = relu_(acc[m][tn][2] + bs[col]);
                hbT[(row + 8) * HB_S + col + 1] = relu_(acc[m][tn][3] + bs[col + 1]);
            }
        }
    }
    __syncthreads();

    // ---- SIMT tails ----
    dense64(posW2, posb2, c, hb_pos, wb, tid, tx, rbase, true);
    layer3(posW3, posb3, c, hb_pos, wb, ps, tid, tx, rbase);
    dense64(negW2, negb2, c, hb_neg, wb, tid, tx, rbase, true);
    layer3(negW3, negb3, c, hb_neg, wb, ns, tid, tx, rbase);

    // cp layer 1: [128 x 32] (ps||ns) @ [32 x 64], relu -> hb_pos
    {
        float acc1[8][4];
#pragma unroll
        for (int i = 0; i < 8; i++)
#pragma unroll
            for (int j = 0; j < 4; j++) acc1[i][j] = 0.f;

        for (int t = tid; t < (2 * ED) * (HD / 4); t += NTHREADS)
            *(float4*)(wb + t * 4) =
                *(const float4*)(cpW1 + (size_t)c * 2 * ED * HD + t * 4);
        __syncthreads();
#pragma unroll 4
        for (int k = 0; k < ED; ++k) {
            float4 w4 = *(const float4*)(wb + k * HD + tx * 4);
#pragma unroll
            for (int i = 0; i < 8; ++i) {
                float xv = ps[(rbase + i) * ED + k];
                acc1[i][0] = fmaf(xv, w4.x, acc1[i][0]);
                acc1[i][1] = fmaf(xv, w4.y, acc1[i][1]);
                acc1[i][2] = fmaf(xv, w4.z, acc1[i][2]);
                acc1[i][3] = fmaf(xv, w4.w, acc1[i][3]);
            }
        }
#pragma unroll 4
        for (int k = 0; k < ED; ++k) {
            float4 w4 = *(const float4*)(wb + (k + ED) * HD + tx * 4);
#pragma unroll
            for (int i = 0; i < 8; ++i) {
                float xv = ns[(rbase + i) * ED + k];
                acc1[i][0] = fmaf(xv, w4.x, acc1[i][0]);
                acc1[i][1] = fmaf(xv, w4.y, acc1[i][1]);
                acc1[i][2] = fmaf(xv, w4.z, acc1[i][2]);
                acc1[i][3] = fmaf(xv, w4.w, acc1[i][3]);
            }
        }
        __syncthreads();
        float4 bv = *(const float4*)(cpb1 + c * HD + tx * 4);
#pragma unroll
        for (int i = 0; i < 8; ++i) {
            hb_pos[(rbase + i) * HB_S + tx * 4 + 0] = relu_(acc1[i][0] + bv.x);
            hb_pos[(rbase + i) * HB_S + tx * 4 + 1] = relu_(acc1[i][1] + bv.y);
            hb_pos[(rbase + i) * HB_S + tx * 4 + 2] = relu_(acc1[i][2] + bv.z);
            hb_pos[(rbase + i) * HB_S + tx * 4 + 3] = relu_(acc1[i][3] + bv.w);
        }
        __syncthreads();
    }

    dense64(cpW2, cpb2, c, hb_pos, wb, tid, tx, rbase, true);

    // cp layer 3: 64 -> 1, gate
    if (tid < HD) wb[tid] = cpW3[(size_t)c * HD + tid];
    __syncthreads();
    if (tid < TILE_R) {
        float s = cpb3[c];
#pragma unroll 4
        for (int k = 0; k < HD; ++k)
            s = fmaf(hb_pos[tid * HB_S + k], wb[k], s);
        out[(size_t)BATCH * ED * NC + (size_t)(r0 + tid) * NC + c] = s;
        gate[tid] = fminf(fmaxf(s * 0.5f + 0.5f, 0.f), 1.f);
    }
    __syncthreads();

    for (int t = tid; t < TILE_R * ED; t += NTHREADS) {
        int r = t >> 4, e = t & 15;
        float g = gate[r];
        float v = ps[r * ED + e] * g + ns[r * ED + e] * (1.f - g);
        out[(size_t)(r0 + r) * (ED * NC) + e * NC + c] = v;
    }
}

extern "C" void kernel_launch(void* const* d_in, const int* in_sizes, int n_in,
                              void* d_out, int out_size) {
    (void)in_sizes; (void)n_in; (void)out_size;
    const int smem_bytes = SMEM_FLOATS * sizeof(float);   // 99328
    cudaFuncSetAttribute(cb_kernel, cudaFuncAttributeMaxDynamicSharedMemorySize, smem_bytes);
    dim3 grid(BATCH / TILE_R, NC);
    cb_kernel<<<grid, NTHREADS, smem_bytes>>>(
        (const float*)d_in[0],
        (const float*)d_in[1],  (const float*)d_in[2],
        (const float*)d_in[3],  (const float*)d_in[4],
        (const float*)d_in[5],  (const float*)d_in[6],
        (const float*)d_in[7],  (const float*)d_in[8],
        (const float*)d_in[9],  (const float*)d_in[10],
        (const float*)d_in[11], (const float*)d_in[12],
        (const float*)d_in[13], (const float*)d_in[14],
        (const float*)d_in[15], (const float*)d_in[16],
        (const float*)d_in[17], (const float*)d_in[18],
        (float*)d_out);
}

// round 6
// speedup vs baseline: 2.6261x; 1.0957x over previous
#include <cuda_runtime.h>
#include <cstdint>

// Problem constants
#define BATCH   8192
#define INDIM   768
#define NC      64
#define HD      64
#define ED      16
#define TILE_R  128
#define NTHREADS 256

#define HB_S 65

// layer-1 staging: 24 stages of K=32
#define KC_T   32
#define NSTAGE (INDIM / KC_T)
#define STG_F  8192            // floats per stage buffer: A 4096 + Bpos 2048 + Bneg 2048

// SMEM float offsets (phased aliasing):
// Phase A (layer1 mma): stage bufs [0,16384), bias1 [24704,24832)
// Phase B (epilogue1+stage2): ha_pos [0,8192), ha_neg [8192,16384),
//                             wb2 [16384,24576), bias2 [24576,24704)
// Phase C (layer2 mma): reads ha/wb2
// Phase D (tails): hb_neg [0,8320), hb_pos [8320,16640), wb [16640,18688),
//                  ps [18688,20736), ns [20736,22784), gate [22784,22912)
#define HA_OFF    0
#define WB2_OFF   16384
#define BIAS2_OFF 24576
#define BIAS1_OFF 24704
#define HBN_OFF   0
#define HBP_OFF   8320
#define WB_OFF    16640
#define PS_OFF    18688
#define NS_OFF    20736
#define GATE_OFF  22784
#define SMEM_FLOATS 24832      // 99328 bytes -> 2 CTAs/SM

__device__ __forceinline__ float relu_(float v) { return v > 0.f ? v : 0.f; }

__device__ __forceinline__ float tf32r(float v) {
    uint32_t u;
    asm("cvt.rna.tf32.f32 %0, %1;" : "=r"(u) : "f"(v));
    return __uint_as_float(u);
}

// m16n8k8 tf32 mma (arch-agnostic PTX, compiles for plain sm_103 target)
__device__ __forceinline__ void mma8(float* d, const float4& a, const float2& b) {
    asm volatile(
        "mma.sync.aligned.m16n8k8.row.col.f32.tf32.tf32.f32 "
        "{%0,%1,%2,%3}, {%4,%5,%6,%7}, {%8,%9}, {%0,%1,%2,%3};"
        : "+f"(d[0]), "+f"(d[1]), "+f"(d[2]), "+f"(d[3])
        : "r"(__float_as_uint(a.x)), "r"(__float_as_uint(a.y)),
          "r"(__float_as_uint(a.z)), "r"(__float_as_uint(a.w)),
          "r"(__float_as_uint(b.x)), "r"(__float_as_uint(b.y)));
}

// ---------------- SIMT tail pieces (proven) ----------------
__device__ __forceinline__ void dense64(
    const float* __restrict__ W, const float* __restrict__ bias, int c,
    float* __restrict__ hb, float* __restrict__ wb,
    int tid, int tx, int rbase, bool do_relu)
{
    float acc[8][4];
#pragma unroll
    for (int i = 0; i < 8; i++)
#pragma unroll
        for (int j = 0; j < 4; j++) acc[i][j] = 0.f;

    for (int kb = 0; kb < HD; kb += 32) {
        __syncthreads();
        for (int t = tid; t < 32 * (HD / 4); t += NTHREADS) {
            int k = t >> 4, q = t & 15;
            *(float4*)(wb + k * HD + q * 4) =
                *(const float4*)(W + ((size_t)c * HD + kb + k) * HD + q * 4);
        }
        __syncthreads();
#pragma unroll 4
        for (int k = 0; k < 32; ++k) {
            float4 wv = *(const float4*)(wb + k * HD + tx * 4);
#pragma unroll
            for (int i = 0; i < 8; ++i) {
                float xv = hb[(rbase + i) * HB_S + kb + k];
                acc[i][0] = fmaf(xv, wv.x, acc[i][0]);
                acc[i][1] = fmaf(xv, wv.y, acc[i][1]);
                acc[i][2] = fmaf(xv, wv.z, acc[i][2]);
                acc[i][3] = fmaf(xv, wv.w, acc[i][3]);
            }
        }
    }
    __syncthreads();
    float4 bv = *(const float4*)(bias + c * HD + tx * 4);
#pragma unroll
    for (int i = 0; i < 8; ++i) {
        float v0 = acc[i][0] + bv.x, v1 = acc[i][1] + bv.y;
        float v2 = acc[i][2] + bv.z, v3 = acc[i][3] + bv.w;
        if (do_relu) { v0 = relu_(v0); v1 = relu_(v1); v2 = relu_(v2); v3 = relu_(v3); }
        hb[(rbase + i) * HB_S + tx * 4 + 0] = v0;
        hb[(rbase + i) * HB_S + tx * 4 + 1] = v1;
        hb[(rbase + i) * HB_S + tx * 4 + 2] = v2;
        hb[(rbase + i) * HB_S + tx * 4 + 3] = v3;
    }
    __syncthreads();
}

__device__ __forceinline__ void layer3(
    const float* __restrict__ W3, const float* __restrict__ b3, int c,
    const float* __restrict__ hb, float* __restrict__ wb, float* __restrict__ obuf,
    int tid, int tx, int rbase)
{
    for (int t = tid; t < HD * ED / 4; t += NTHREADS)
        *(float4*)(wb + t * 4) = *(const float4*)(W3 + (size_t)c * HD * ED + t * 4);
    __syncthreads();
    float a3[8];
#pragma unroll
    for (int i = 0; i < 8; i++) a3[i] = 0.f;
#pragma unroll 4
    for (int k = 0; k < HD; ++k) {
        float w = wb[k * ED + tx];
#pragma unroll
        for (int i = 0; i < 8; ++i)
            a3[i] = fmaf(hb[(rbase + i) * HB_S + k], w, a3[i]);
    }
    float bv = b3[c * ED + tx];
#pragma unroll
    for (int i = 0; i < 8; ++i)
        obuf[(rbase + i) * ED + tx] = a3[i] + bv;
    __syncthreads();
}

// ---------------- layer-1 staging ----------------
__device__ __forceinline__ void stage_ldg(
    const float* __restrict__ x, const float* __restrict__ Wp,
    const float* __restrict__ Wn, int r0, int c, int kb, int tid,
    float4* xa /*4*/, float4* wv /*4*/)
{
#pragma unroll
    for (int i = 0; i < 2; ++i) {
        int item = tid + i * NTHREADS;      // 0..511
        int rp = item >> 3, cg = item & 7;
        int r = ((rp >> 3) << 4) | (rp & 7);
        const float* p = x + (size_t)(r0 + r) * INDIM + kb + cg * 4;
        xa[2 * i + 0] = *(const float4*)p;
        xa[2 * i + 1] = *(const float4*)(p + 8 * INDIM);
    }
    int kp = tid >> 4, ng = tid & 15;
    int k = (kp & 3) | ((kp >> 2) << 3);
    {
        const float* p = Wp + ((size_t)c * INDIM + kb + k) * HD + ng * 4;
        wv[0] = *(const float4*)p;
        wv[1] = *(const float4*)(p + 4 * HD);
        const float* q = Wn + ((size_t)c * INDIM + kb + k) * HD + ng * 4;
        wv[2] = *(const float4*)q;
        wv[3] = *(const float4*)(q + 4 * HD);
    }
}

__device__ __forceinline__ void stage_sts(
    float* __restrict__ stg, int tid, const float4* xa, const float4* wv)
{
#pragma unroll
    for (int i = 0; i < 2; ++i) {
        int item = tid + i * NTHREADS;
        int rp = item >> 3, cg = item & 7;
        int tile_m = rp >> 3;
        int tile_k = cg >> 1, ckhi = cg & 1;
        int lane_base = (rp & 7) * 4;
        const float* lo = (const float*)&xa[2 * i + 0];
        const float* hi = (const float*)&xa[2 * i + 1];
#pragma unroll
        for (int j = 0; j < 4; ++j) {
            int lane_s = (lane_base + j) ^ tile_k;
            int off = (tile_m * 4 + tile_k) * 128 + lane_s * 4 + ckhi * 2;
            *(float2*)(stg + off) = make_float2(tf32r(lo[j]), tf32r(hi[j]));
        }
    }
    int kp = tid >> 4, ng = tid & 15;
    int tile_k = kp >> 2;
#pragma unroll
    for (int bw = 0; bw < 2; ++bw) {
        const float* lo = (const float*)&wv[2 * bw + 0];
        const float* hi = (const float*)&wv[2 * bw + 1];
#pragma unroll
        for (int j = 0; j < 4; ++j) {
            int n = ng * 4 + j;
            int tile_n = n >> 3, nn = n & 7;
            int lane = nn * 4 + (kp & 3);
            int lane_s = lane ^ ((tile_k ^ tile_n) & 3);
            int off = 4096 + bw * 2048 + (tile_n * 4 + tile_k) * 64 + lane_s * 2;
            *(float2*)(stg + off) = make_float2(tf32r(lo[j]), tf32r(hi[j]));
        }
    }
}

// ---------------- main kernel ----------------
__global__ __launch_bounds__(NTHREADS, 2)
void cb_kernel(
    const float* __restrict__ x,
    const float* __restrict__ posW1, const float* __restrict__ posb1,
    const float* __restrict__ posW2, const float* __restrict__ posb2,
    const float* __restrict__ posW3, const float* __restrict__ posb3,
    const float* __restrict__ negW1, const float* __restrict__ negb1,
    const float* __restrict__ negW2, const float* __restrict__ negb2,
    const float* __restrict__ negW3, const float* __restrict__ negb3,
    const float* __restrict__ cpW1,  const float* __restrict__ cpb1,
    const float* __restrict__ cpW2,  const float* __restrict__ cpb2,
    const float* __restrict__ cpW3,  const float* __restrict__ cpb3,
    float* __restrict__ out)
{
    extern __shared__ float sm[];
    float* hb_neg = sm + HBN_OFF;
    float* hb_pos = sm + HBP_OFF;
    float* wb     = sm + WB_OFF;
    float* ps     = sm + PS_OFF;
    float* ns     = sm + NS_OFF;
    float* gate   = sm + GATE_OFF;
    float* bias1  = sm + BIAS1_OFF;
    float* bias2  = sm + BIAS2_OFF;

    const int tid  = threadIdx.x;
    const int wid  = tid >> 5, lane = tid & 31;
    const int c    = blockIdx.y;
    const int r0   = blockIdx.x * TILE_R;
    const int tx    = tid & 15;
    const int rbase = (tid >> 4) * 8;

    if (tid < 64)       bias1[tid] = posb1[c * HD + tid];
    else if (tid < 128) bias1[tid] = negb1[c * HD + tid - 64];

    // ---- layer 1 on tensor cores (tf32 mma.sync) ----
    const int bank = wid >> 2;             // 0: pos, 1: neg
    const int tmA  = (wid & 3) * 2;
    const int tmB  = tmA + 1;
    const int gid  = lane >> 2, qid = lane & 3;

    float acc[2][8][4];
#pragma unroll
    for (int m = 0; m < 2; m++)
#pragma unroll
        for (int n = 0; n < 8; n++)
#pragma unroll
            for (int j = 0; j < 4; j++) acc[m][n][j] = 0.f;

    float4 xa[4], wv[4];
    stage_ldg(x, posW1, negW1, r0, c, 0, tid, xa, wv);
    stage_sts(sm, tid, xa, wv);
    __syncthreads();

    for (int s = 0; s < NSTAGE; ++s) {
        if (s + 1 < NSTAGE)
            stage_ldg(x, posW1, negW1, r0, c, (s + 1) * KC_T, tid, xa, wv);

        const float* A  = sm + (s & 1) * STG_F;
        const float* Bb = A + 4096 + bank * 2048;
#pragma unroll
        for (int tk = 0; tk < 4; ++tk) {
            float4 a0 = *(const float4*)(A + (tmA * 4 + tk) * 128 + (lane ^ tk) * 4);
            float4 a1 = *(const float4*)(A + (tmB * 4 + tk) * 128 + (lane ^ tk) * 4);
#pragma unroll
            for (int tn = 0; tn < 8; ++tn) {
                float2 bv = *(const float2*)(Bb + (tn * 4 + tk) * 64 +
                                             (lane ^ ((tk ^ tn) & 3)) * 2);
                mma8(acc[0][tn], a0, bv);
                mma8(acc[1][tn], a1, bv);
            }
        }
        __syncthreads();
        if (s + 1 < NSTAGE) {
            stage_sts(sm + ((s + 1) & 1) * STG_F, tid, xa, wv);
            __syncthreads();
        }
    }
    __syncthreads();   // all stage-buffer reads done before ha overwrite

    // ---- epilogue1: bias+relu, tf32-round, write h in A-fragment layout ----
    // ha[bank][row][col ^ 4*(row&7)], stride 64
    {
        float* haT = sm + HA_OFF + bank * 8192;
        const float* bs = bias1 + bank * 64;
#pragma unroll
        for (int m = 0; m < 2; ++m) {
            int row = (wid & 3) * 32 + m * 16 + gid;
            int xr = 4 * (row & 7);     // same for row and row+8
#pragma unroll
            for (int tn = 0; tn < 8; ++tn) {
                int col = tn * 8 + qid * 2;
                int cs = col ^ xr;
                float v0 = tf32r(relu_(acc[m][tn][0] + bs[col]));
                float v1 = tf32r(relu_(acc[m][tn][1] + bs[col + 1]));
                float v2 = tf32r(relu_(acc[m][tn][2] + bs[col]));
                float v3 = tf32r(relu_(acc[m][tn][3] + bs[col + 1]));
                *(float2*)(haT + row * 64 + cs)       = make_float2(v0, v1);
                *(float2*)(haT + (row + 8) * 64 + cs) = make_float2(v2, v3);
            }
        }
    }
    // ---- stage W2 (both banks) tf32-rounded into b-frag-friendly layout ----
    // wb2[bank][k][n ^ 8*(k&3)], stride 64
    {
        float* wb2 = sm + WB2_OFF;
        for (int t = tid; t < 2 * HD * (HD / 4); t += NTHREADS) {  // 2048 items
            int bw = t >> 10;
            int tt = t & 1023;
            int k = tt >> 4, ng = tt & 15;
            const float* W = bw ? negW2 : posW2;
            float4 v = *(const float4*)(W + ((size_t)c * HD + k) * HD + ng * 4);
            int n0 = (ng * 4) ^ (8 * (k & 3));
            *(float4*)(wb2 + bw * 4096 + k * 64 + n0) =
                make_float4(tf32r(v.x), tf32r(v.y), tf32r(v.z), tf32r(v.w));
        }
        if (tid < 64)       bias2[tid] = posb2[c * HD + tid];
        else if (tid < 128) bias2[tid] = negb2[c * HD + tid - 64];
    }
    __syncthreads();

    // ---- layer 2 on tensor cores: h[128x64] @ W2[64x64] per bank ----
    float acc2[2][8][4];
#pragma unroll
    for (int m = 0; m < 2; m++)
#pragma unroll
        for (int n = 0; n < 8; n++)
#pragma unroll
            for (int j = 0; j < 4; j++) acc2[m][n][j] = 0.f;
    {
        const float* haT = sm + HA_OFF + bank * 8192;
        const float* w2  = sm + WB2_OFF + bank * 4096;
        const int rb0 = (wid & 3) * 32 + gid;
        const int xA  = 4 * gid;
        const int xB  = 8 * qid;
#pragma unroll
        for (int tk = 0; tk < 8; ++tk) {
            int c0 = tk * 8 + qid;
            int c1 = c0 + 4;
            float4 a0, a1;
            a0.x = haT[rb0 * 64 + (c0 ^ xA)];
            a0.y = haT[(rb0 + 8) * 64 + (c0 ^ xA)];
            a0.z = haT[rb0 * 64 + (c1 ^ xA)];
            a0.w = haT[(rb0 + 8) * 64 + (c1 ^ xA)];
            a1.x = haT[(rb0 + 16) * 64 + (c0 ^ xA)];
            a1.y = haT[(rb0 + 24) * 64 + (c0 ^ xA)];
            a1.z = haT[(rb0 + 16) * 64 + (c1 ^ xA)];
            a1.w = haT[(rb0 + 24) * 64 + (c1 ^ xA)];
#pragma unroll
            for (int tn = 0; tn < 8; ++tn) {
                int n = tn * 8 + gid;
                float2 bv;
                bv.x = w2[c0 * 64 + (n ^ xB)];
                bv.y = w2[c1 * 64 + (n ^ xB)];
                mma8(acc2[0][tn], a0, bv);
                mma8(acc2[1][tn], a1, bv);
            }
        }
    }
    __syncthreads();   // ha/wb2 reads done before hb overwrite

    // ---- epilogue2: bias+relu -> hb row-major for SIMT tails ----
    {
        float* hbT = bank ? hb_neg : hb_pos;
        const float* bs = bias2 + bank * 64;
#pragma unroll
        for (int m = 0; m < 2; ++m) {
            int row = (wid & 3) * 32 + m * 16 + gid;
#pragma unroll
            for (int tn = 0; tn < 8; ++tn) {
                int col = tn * 8 + qid * 2;
                hbT[row * HB_S + col]           = relu_(acc2[m][tn][0] + bs[col]);
                hbT[row * HB_S + col + 1]       = relu_(acc2[m][tn][1] + bs[col + 1]);
                hbT[(row + 8) * HB_S + col]     = relu_(acc2[m][tn][2] + bs[col]);
                hbT[(row + 8) * HB_S + col + 1] = relu_(acc2[m][tn][3] + bs[col + 1]);
            }
        }
    }
    __syncthreads();

    // ---- SIMT tails ----
    layer3(posW3, posb3, c, hb_pos, wb, ps, tid, tx, rbase);
    layer3(negW3, negb3, c, hb_neg, wb, ns, tid, tx, rbase);

    // cp layer 1: [128 x 32] (ps||ns) @ [32 x 64], relu -> hb_pos
    {
        float acc1[8][4];
#pragma unroll
        for (int i = 0; i < 8; i++)
#pragma unroll
            for (int j = 0; j < 4; j++) acc1[i][j] = 0.f;

        for (int t = tid; t < (2 * ED) * (HD / 4); t += NTHREADS)
            *(float4*)(wb + t * 4) =
                *(const float4*)(cpW1 + (size_t)c * 2 * ED * HD + t * 4);
        __syncthreads();
#pragma unroll 4
        for (int k = 0; k < ED; ++k) {
            float4 w4 = *(const float4*)(wb + k * HD + tx * 4);
#pragma unroll
            for (int i = 0; i < 8; ++i) {
                float xv = ps[(rbase + i) * ED + k];
                acc1[i][0] = fmaf(xv, w4.x, acc1[i][0]);
                acc1[i][1] = fmaf(xv, w4.y, acc1[i][1]);
                acc1[i][2] = fmaf(xv, w4.z, acc1[i][2]);
                acc1[i][3] = fmaf(xv, w4.w, acc1[i][3]);
            }
        }
#pragma unroll 4
        for (int k = 0; k < ED; ++k) {
            float4 w4 = *(const float4*)(wb + (k + ED) * HD + tx * 4);
#pragma unroll
            for (int i = 0; i < 8; ++i) {
                float xv = ns[(rbase + i) * ED + k];
                acc1[i][0] = fmaf(xv, w4.x, acc1[i][0]);
                acc1[i][1] = fmaf(xv, w4.y, acc1[i][1]);
                acc1[i][2] = fmaf(xv, w4.z, acc1[i][2]);
                acc1[i][3] = fmaf(xv, w4.w, acc1[i][3]);
            }
        }
        __syncthreads();
        float4 bv = *(const float4*)(cpb1 + c * HD + tx * 4);
#pragma unroll
        for (int i = 0; i < 8; ++i) {
            hb_pos[(rbase + i) * HB_S + tx * 4 + 0] = relu_(acc1[i][0] + bv.x);
            hb_pos[(rbase + i) * HB_S + tx * 4 + 1] = relu_(acc1[i][1] + bv.y);
            hb_pos[(rbase + i) * HB_S + tx * 4 + 2] = relu_(acc1[i][2] + bv.z);
            hb_pos[(rbase + i) * HB_S + tx * 4 + 3] = relu_(acc1[i][3] + bv.w);
        }
        __syncthreads();
    }

    dense64(cpW2, cpb2, c, hb_pos, wb, tid, tx, rbase, true);

    // cp layer 3: 64 -> 1, gate
    if (tid < HD) wb[tid] = cpW3[(size_t)c * HD + tid];
    __syncthreads();
    if (tid < TILE_R) {
        float s = cpb3[c];
#pragma unroll 4
        for (int k = 0; k < HD; ++k)
            s = fmaf(hb_pos[tid * HB_S + k], wb[k], s);
        out[(size_t)BATCH * ED * NC + (size_t)(r0 + tid) * NC + c] = s;
        gate[tid] = fminf(fmaxf(s * 0.5f + 0.5f, 0.f), 1.f);
    }
    __syncthreads();

    for (int t = tid; t < TILE_R * ED; t += NTHREADS) {
        int r = t >> 4, e = t & 15;
        float g = gate[r];
        float v = ps[r * ED + e] * g + ns[r * ED + e] * (1.f - g);
        out[(size_t)(r0 + r) * (ED * NC) + e * NC + c] = v;
    }
}

extern "C" void kernel_launch(void* const* d_in, const int* in_sizes, int n_in,
                              void* d_out, int out_size) {
    (void)in_sizes; (void)n_in; (void)out_size;
    const int smem_bytes = SMEM_FLOATS * sizeof(float);   // 99328
    cudaFuncSetAttribute(cb_kernel, cudaFuncAttributeMaxDynamicSharedMemorySize, smem_bytes);
    dim3 grid(BATCH / TILE_R, NC);
    cb_kernel<<<grid, NTHREADS, smem_bytes>>>(
        (const float*)d_in[0],
        (const float*)d_in[1],  (const float*)d_in[2],
        (const float*)d_in[3],  (const float*)d_in[4],
        (const float*)d_in[5],  (const float*)d_in[6],
        (const float*)d_in[7],  (const float*)d_in[8],
        (const float*)d_in[9],  (const float*)d_in[10],
        (const float*)d_in[11], (const float*)d_in[12],
        (const float*)d_in[13], (const float*)d_in[14],
        (const float*)d_in[15], (const float*)d_in[16],
        (const float*)d_in[17], (const float*)d_in[18],
        (float*)d_out);
}

// round 7
// speedup vs baseline: 2.7554x; 1.0492x over previous
#include <cuda_runtime.h>
#include <cstdint>

// Problem constants
#define BATCH   8192
#define INDIM   768
#define NC      64
#define HD      64
#define ED      16
#define TILE_R  128
#define NTHREADS 256

#define HB2_S 68        // hb row stride (float4-aligned)
#define CPH_S 65        // cp h2 row stride (scalar reads, conflict-free)

// layer-1 staging: 24 stages of K=32
#define KC_T   32
#define NSTAGE (INDIM / KC_T)
#define STG_F  8192            // floats per stage buffer: A 4096 + Bpos 2048 + Bneg 2048

// SMEM float offsets (phased aliasing):
// Phase A (layer1): stage bufs [0,16384), bias1 [24704,24832)
// Phase B (l2): ha [0,16384), wb2 [16384,24576), bias2 [24576,24704)
// Phase C (tails): hb_neg [0,8704), hb_pos [8704,17408), wb [17408,19456),
//                  ps [19456,21504), ns [21504,23552), gate [23552,23680)
// Phase D (cp): cp_ha [0,8192), cpW2 [8192,12288), then cph2 [0,8320)
#define HA_OFF    0
#define WB2_OFF   16384
#define BIAS2_OFF 24576
#define BIAS1_OFF 24704
#define HBN_OFF   0
#define HBP_OFF   8704
#define WB_OFF    17408
#define PS_OFF    19456
#define NS_OFF    21504
#define GATE_OFF  23552
#define CPA_OFF   0
#define CPW2_OFF  8192
#define CPH2_OFF  0
#define SMEM_FLOATS 24832      // 99328 bytes -> 2 CTAs/SM

__device__ __forceinline__ float relu_(float v) { return v > 0.f ? v : 0.f; }

__device__ __forceinline__ float tf32r(float v) {
    uint32_t u;
    asm("cvt.rna.tf32.f32 %0, %1;" : "=r"(u) : "f"(v));
    return __uint_as_float(u);
}

// m16n8k8 tf32 mma (arch-agnostic PTX, compiles for plain sm_103 target)
__device__ __forceinline__ void mma8(float* d, const float4& a, const float2& b) {
    asm volatile(
        "mma.sync.aligned.m16n8k8.row.col.f32.tf32.tf32.f32 "
        "{%0,%1,%2,%3}, {%4,%5,%6,%7}, {%8,%9}, {%0,%1,%2,%3};"
        : "+f"(d[0]), "+f"(d[1]), "+f"(d[2]), "+f"(d[3])
        : "r"(__float_as_uint(a.x)), "r"(__float_as_uint(a.y)),
          "r"(__float_as_uint(a.z)), "r"(__float_as_uint(a.w)),
          "r"(__float_as_uint(b.x)), "r"(__float_as_uint(b.y)));
}

// ---------------- layer 3 (64 -> 16), vectorized broadcast reads ----------------
__device__ __forceinline__ void layer3v(
    const float* __restrict__ W3, const float* __restrict__ b3, int c,
    const float* __restrict__ hb, float* __restrict__ wb, float* __restrict__ obuf,
    int tid, int tx, int rbase)
{
    for (int t = tid; t < HD * ED / 4; t += NTHREADS)
        *(float4*)(wb + t * 4) = *(const float4*)(W3 + (size_t)c * HD * ED + t * 4);
    __syncthreads();
    float a3[8];
#pragma unroll
    for (int i = 0; i < 8; i++) a3[i] = 0.f;
#pragma unroll
    for (int kc = 0; kc < 16; ++kc) {
        float4 pv[8];
#pragma unroll
        for (int i = 0; i < 8; ++i)
            pv[i] = *(const float4*)(hb + (rbase + i) * HB2_S + kc * 4);
#pragma unroll
        for (int j = 0; j < 4; ++j) {
            float w = wb[(kc * 4 + j) * ED + tx];
#pragma unroll
            for (int i = 0; i < 8; ++i)
                a3[i] = fmaf(((const float*)&pv[i])[j], w, a3[i]);
        }
    }
    float bv = b3[c * ED + tx];
#pragma unroll
    for (int i = 0; i < 8; ++i)
        obuf[(rbase + i) * ED + tx] = a3[i] + bv;
    __syncthreads();
}

// ---------------- layer-1 staging ----------------
__device__ __forceinline__ void stage_ldg(
    const float* __restrict__ x, const float* __restrict__ Wp,
    const float* __restrict__ Wn, int r0, int c, int kb, int tid,
    float4* xa /*4*/, float4* wv /*4*/)
{
#pragma unroll
    for (int i = 0; i < 2; ++i) {
        int item = tid + i * NTHREADS;      // 0..511
        int rp = item >> 3, cg = item & 7;
        int r = ((rp >> 3) << 4) | (rp & 7);
        const float* p = x + (size_t)(r0 + r) * INDIM + kb + cg * 4;
        xa[2 * i + 0] = *(const float4*)p;
        xa[2 * i + 1] = *(const float4*)(p + 8 * INDIM);
    }
    int kp = tid >> 4, ng = tid & 15;
    int k = (kp & 3) | ((kp >> 2) << 3);
    {
        const float* p = Wp + ((size_t)c * INDIM + kb + k) * HD + ng * 4;
        wv[0] = *(const float4*)p;
        wv[1] = *(const float4*)(p + 4 * HD);
        const float* q = Wn + ((size_t)c * INDIM + kb + k) * HD + ng * 4;
        wv[2] = *(const float4*)q;
        wv[3] = *(const float4*)(q + 4 * HD);
    }
}

__device__ __forceinline__ void stage_sts(
    float* __restrict__ stg, int tid, const float4* xa, const float4* wv)
{
#pragma unroll
    for (int i = 0; i < 2; ++i) {
        int item = tid + i * NTHREADS;
        int rp = item >> 3, cg = item & 7;
        int tile_m = rp >> 3;
        int tile_k = cg >> 1, ckhi = cg & 1;
        int lane_base = (rp & 7) * 4;
        const float* lo = (const float*)&xa[2 * i + 0];
        const float* hi = (const float*)&xa[2 * i + 1];
#pragma unroll
        for (int j = 0; j < 4; ++j) {
            int lane_s = (lane_base + j) ^ tile_k;
            int off = (tile_m * 4 + tile_k) * 128 + lane_s * 4 + ckhi * 2;
            *(float2*)(stg + off) = make_float2(tf32r(lo[j]), tf32r(hi[j]));
        }
    }
    int kp = tid >> 4, ng = tid & 15;
    int tile_k = kp >> 2;
#pragma unroll
    for (int bw = 0; bw < 2; ++bw) {
        const float* lo = (const float*)&wv[2 * bw + 0];
        const float* hi = (const float*)&wv[2 * bw + 1];
#pragma unroll
        for (int j = 0; j < 4; ++j) {
            int n = ng * 4 + j;
            int tile_n = n >> 3, nn = n & 7;
            int lane = nn * 4 + (kp & 3);
            int lane_s = lane ^ ((tile_k ^ tile_n) & 3);
            int off = 4096 + bw * 2048 + (tile_n * 4 + tile_k) * 64 + lane_s * 2;
            *(float2*)(stg + off) = make_float2(tf32r(lo[j]), tf32r(hi[j]));
        }
    }
}

// ---------------- main kernel ----------------
__global__ __launch_bounds__(NTHREADS, 2)
void cb_kernel(
    const float* __restrict__ x,
    const float* __restrict__ posW1, const float* __restrict__ posb1,
    const float* __restrict__ posW2, const float* __restrict__ posb2,
    const float* __restrict__ posW3, const float* __restrict__ posb3,
    const float* __restrict__ negW1, const float* __restrict__ negb1,
    const float* __restrict__ negW2, const float* __restrict__ negb2,
    const float* __restrict__ negW3, const float* __restrict__ negb3,
    const float* __restrict__ cpW1,  const float* __restrict__ cpb1,
    const float* __restrict__ cpW2,  const float* __restrict__ cpb2,
    const float* __restrict__ cpW3,  const float* __restrict__ cpb3,
    float* __restrict__ out)
{
    extern __shared__ float sm[];
    float* hb_neg = sm + HBN_OFF;
    float* hb_pos = sm + HBP_OFF;
    float* wb     = sm + WB_OFF;
    float* ps     = sm + PS_OFF;
    float* ns     = sm + NS_OFF;
    float* gate   = sm + GATE_OFF;
    float* bias1  = sm + BIAS1_OFF;
    float* bias2  = sm + BIAS2_OFF;

    const int tid  = threadIdx.x;
    const int wid  = tid >> 5, lane = tid & 31;
    const int c    = blockIdx.y;
    const int r0   = blockIdx.x * TILE_R;
    const int tx    = tid & 15;
    const int rbase = (tid >> 4) * 8;

    if (tid < 64)       bias1[tid] = posb1[c * HD + tid];
    else if (tid < 128) bias1[tid] = negb1[c * HD + tid - 64];

    // ---- layer 1 on tensor cores (tf32 mma.sync) ----
    const int bank = wid >> 2;             // 0: pos, 1: neg
    const int tmA  = (wid & 3) * 2;
    const int tmB  = tmA + 1;
    const int gid  = lane >> 2, qid = lane & 3;

    float acc[2][8][4];
#pragma unroll
    for (int m = 0; m < 2; m++)
#pragma unroll
        for (int n = 0; n < 8; n++)
#pragma unroll
            for (int j = 0; j < 4; j++) acc[m][n][j] = 0.f;

    float4 xa[4], wv[4];
    stage_ldg(x, posW1, negW1, r0, c, 0, tid, xa, wv);
    stage_sts(sm, tid, xa, wv);
    __syncthreads();

    for (int s = 0; s < NSTAGE; ++s) {
        if (s + 1 < NSTAGE)
            stage_ldg(x, posW1, negW1, r0, c, (s + 1) * KC_T, tid, xa, wv);

        const float* A  = sm + (s & 1) * STG_F;
        const float* Bb = A + 4096 + bank * 2048;
#pragma unroll
        for (int tk = 0; tk < 4; ++tk) {
            float4 a0 = *(const float4*)(A + (tmA * 4 + tk) * 128 + (lane ^ tk) * 4);
            float4 a1 = *(const float4*)(A + (tmB * 4 + tk) * 128 + (lane ^ tk) * 4);
#pragma unroll
            for (int tn = 0; tn < 8; ++tn) {
                float2 bv = *(const float2*)(Bb + (tn * 4 + tk) * 64 +
                                             (lane ^ ((tk ^ tn) & 3)) * 2);
                mma8(acc[0][tn], a0, bv);
                mma8(acc[1][tn], a1, bv);
            }
        }
        __syncthreads();
        if (s + 1 < NSTAGE) {
            stage_sts(sm + ((s + 1) & 1) * STG_F, tid, xa, wv);
            __syncthreads();
        }
    }
    __syncthreads();   // all stage-buffer reads done before ha overwrite

    // ---- epilogue1: bias+relu, tf32-round, write h in A-fragment layout ----
    {
        float* haT = sm + HA_OFF + bank * 8192;
        const float* bs = bias1 + bank * 64;
#pragma unroll
        for (int m = 0; m < 2; ++m) {
            int row = (wid & 3) * 32 + m * 16 + gid;
            int xr = 4 * (row & 7);
#pragma unroll
            for (int tn = 0; tn < 8; ++tn) {
                int col = tn * 8 + qid * 2;
                int cs = col ^ xr;
                float v0 = tf32r(relu_(acc[m][tn][0] + bs[col]));
                float v1 = tf32r(relu_(acc[m][tn][1] + bs[col + 1]));
                float v2 = tf32r(relu_(acc[m][tn][2] + bs[col]));
                float v3 = tf32r(relu_(acc[m][tn][3] + bs[col + 1]));
                *(float2*)(haT + row * 64 + cs)       = make_float2(v0, v1);
                *(float2*)(haT + (row + 8) * 64 + cs) = make_float2(v2, v3);
            }
        }
    }
    // ---- stage W2 (both banks) tf32-rounded, b-frag layout ----
    {
        float* wb2 = sm + WB2_OFF;
        for (int t = tid; t < 2 * HD * (HD / 4); t += NTHREADS) {
            int bw = t >> 10;
            int tt = t & 1023;
            int k = tt >> 4, ng = tt & 15;
            const float* W = bw ? negW2 : posW2;
            float4 v = *(const float4*)(W + ((size_t)c * HD + k) * HD + ng * 4);
            int n0 = (ng * 4) ^ (8 * (k & 3));
            *(float4*)(wb2 + bw * 4096 + k * 64 + n0) =
                make_float4(tf32r(v.x), tf32r(v.y), tf32r(v.z), tf32r(v.w));
        }
        if (tid < 64)       bias2[tid] = posb2[c * HD + tid];
        else if (tid < 128) bias2[tid] = negb2[c * HD + tid - 64];
    }
    __syncthreads();

    // ---- layer 2 on tensor cores ----
    float acc2[2][8][4];
#pragma unroll
    for (int m = 0; m < 2; m++)
#pragma unroll
        for (int n = 0; n < 8; n++)
#pragma unroll
            for (int j = 0; j < 4; j++) acc2[m][n][j] = 0.f;
    {
        const float* haT = sm + HA_OFF + bank * 8192;
        const float* w2  = sm + WB2_OFF + bank * 4096;
        const int rb0 = (wid & 3) * 32 + gid;
        const int xA  = 4 * gid;
        const int xB  = 8 * qid;
#pragma unroll
        for (int tk = 0; tk < 8; ++tk) {
            int c0 = tk * 8 + qid;
            int c1 = c0 + 4;
            float4 a0, a1;
            a0.x = haT[rb0 * 64 + (c0 ^ xA)];
            a0.y = haT[(rb0 + 8) * 64 + (c0 ^ xA)];
            a0.z = haT[rb0 * 64 + (c1 ^ xA)];
            a0.w = haT[(rb0 + 8) * 64 + (c1 ^ xA)];
            a1.x = haT[(rb0 + 16) * 64 + (c0 ^ xA)];
            a1.y = haT[(rb0 + 24) * 64 + (c0 ^ xA)];
            a1.z = haT[(rb0 + 16) * 64 + (c1 ^ xA)];
            a1.w = haT[(rb0 + 24) * 64 + (c1 ^ xA)];
#pragma unroll
            for (int tn = 0; tn < 8; ++tn) {
                int n = tn * 8 + gid;
                float2 bv;
                bv.x = w2[c0 * 64 + (n ^ xB)];
                bv.y = w2[c1 * 64 + (n ^ xB)];
                mma8(acc2[0][tn], a0, bv);
                mma8(acc2[1][tn], a1, bv);
            }
        }
    }
    __syncthreads();   // ha/wb2 reads done before hb overwrite

    // ---- epilogue2: bias+relu -> hb row-major (stride 68) ----
    {
        float* hbT = bank ? hb_neg : hb_pos;
        const float* bs = bias2 + bank * 64;
#pragma unroll
        for (int m = 0; m < 2; ++m) {
            int row = (wid & 3) * 32 + m * 16 + gid;
#pragma unroll
            for (int tn = 0; tn < 8; ++tn) {
                int col = tn * 8 + qid * 2;
                hbT[row * HB2_S + col]           = relu_(acc2[m][tn][0] + bs[col]);
                hbT[row * HB2_S + col + 1]       = relu_(acc2[m][tn][1] + bs[col + 1]);
                hbT[(row + 8) * HB2_S + col]     = relu_(acc2[m][tn][2] + bs[col]);
                hbT[(row + 8) * HB2_S + col + 1] = relu_(acc2[m][tn][3] + bs[col + 1]);
            }
        }
    }
    __syncthreads();

    // ---- layer 3 (pos, neg) vectorized ----
    layer3v(posW3, posb3, c, hb_pos, wb, ps, tid, tx, rbase);
    layer3v(negW3, negb3, c, hb_neg, wb, ns, tid, tx, rbase);

    // ---- cp layer 1: [128 x 32] @ [32 x 64], relu, write to cp-frag layout ----
    {
        float acc1[8][4];
#pragma unroll
        for (int i = 0; i < 8; i++)
#pragma unroll
            for (int j = 0; j < 4; j++) acc1[i][j] = 0.f;

        for (int t = tid; t < (2 * ED) * (HD / 4); t += NTHREADS)
            *(float4*)(wb + t * 4) =
                *(const float4*)(cpW1 + (size_t)c * 2 * ED * HD + t * 4);
        __syncthreads();

#pragma unroll
        for (int half = 0; half < 2; ++half) {
            const float* src = half ? ns : ps;
#pragma unroll
            for (int kc = 0; kc < 4; ++kc) {
                float4 pv[8];
#pragma unroll
                for (int i = 0; i < 8; ++i)
                    pv[i] = *(const float4*)(src + (rbase + i) * ED + kc * 4);
#pragma unroll
                for (int j = 0; j < 4; ++j) {
                    int k = half * ED + kc * 4 + j;
                    float4 w4 = *(const float4*)(wb + k * HD + tx * 4);
#pragma unroll
                    for (int i = 0; i < 8; ++i) {
                        float xv = ((const float*)&pv[i])[j];
                        acc1[i][0] = fmaf(xv, w4.x, acc1[i][0]);
                        acc1[i][1] = fmaf(xv, w4.y, acc1[i][1]);
                        acc1[i][2] = fmaf(xv, w4.z, acc1[i][2]);
                        acc1[i][3] = fmaf(xv, w4.w, acc1[i][3]);
                    }
                }
            }
        }
        __syncthreads();   // wb reads done; cp_ha region (dead hb_neg) writable

        // bias + relu + tf32 round -> cp_ha fragment layout
        float* cpa = sm + CPA_OFF;
        float4 bv = *(const float4*)(cpb1 + c * HD + tx * 4);
#pragma unroll
        for (int i = 0; i < 8; ++i) {
            int row = rbase + i;
            int xr = 4 * (row & 7);
            float4 v;
            v.x = tf32r(relu_(acc1[i][0] + bv.x));
            v.y = tf32r(relu_(acc1[i][1] + bv.y));
            v.z = tf32r(relu_(acc1[i][2] + bv.z));
            v.w = tf32r(relu_(acc1[i][3] + bv.w));
            *(float4*)(cpa + row * 64 + ((tx * 4) ^ xr)) = v;
        }
        // stage cpW2 tf32 b-frag layout + cp bias2
        float* cw2 = sm + CPW2_OFF;
        for (int t = tid; t < HD * (HD / 4); t += NTHREADS) {
            int k = t >> 4, ng = t & 15;
            float4 v = *(const float4*)(cpW2 + ((size_t)c * HD + k) * HD + ng * 4);
            int n0 = (ng * 4) ^ (8 * (k & 3));
            *(float4*)(cw2 + k * 64 + n0) =
                make_float4(tf32r(v.x), tf32r(v.y), tf32r(v.z), tf32r(v.w));
        }
        if (tid < 64) bias2[tid] = cpb2[c * HD + tid];
    }
    __syncthreads();

    // ---- cp layer 2 on tensor cores: 8 warps x m16n64k64 ----
    {
        float accc[8][4];
#pragma unroll
        for (int n = 0; n < 8; n++)
#pragma unroll
            for (int j = 0; j < 4; j++) accc[n][j] = 0.f;

        const float* cpa = sm + CPA_OFF;
        const float* cw2 = sm + CPW2_OFF;
        const int rb0 = wid * 16 + gid;
        const int xA  = 4 * gid;
        const int xB  = 8 * qid;
#pragma unroll
        for (int tk = 0; tk < 8; ++tk) {
            int c0 = tk * 8 + qid;
            int c1 = c0 + 4;
            float4 a0;
            a0.x = cpa[rb0 * 64 + (c0 ^ xA)];
            a0.y = cpa[(rb0 + 8) * 64 + (c0 ^ xA)];
            a0.z = cpa[rb0 * 64 + (c1 ^ xA)];
            a0.w = cpa[(rb0 + 8) * 64 + (c1 ^ xA)];
#pragma unroll
            for (int tn = 0; tn < 8; ++tn) {
                int n = tn * 8 + gid;
                float2 bv;
                bv.x = cw2[c0 * 64 + (n ^ xB)];
                bv.y = cw2[c1 * 64 + (n ^ xB)];
                mma8(accc[tn], a0, bv);
            }
        }
        __syncthreads();   // cpa/cw2 reads done before cph2 overwrite

        // epilogue: bias+relu -> cph2 row-major (stride 65)
        float* cph2 = sm + CPH2_OFF;
#pragma unroll
        for (int tn = 0; tn < 8; ++tn) {
            int col = tn * 8 + qid * 2;
            cph2[rb0 * CPH_S + col]           = relu_(accc[tn][0] + bias2[col]);
            cph2[rb0 * CPH_S + col + 1]       = relu_(accc[tn][1] + bias2[col + 1]);
            cph2[(rb0 + 8) * CPH_S + col]     = relu_(accc[tn][2] + bias2[col]);
            cph2[(rb0 + 8) * CPH_S + col + 1] = relu_(accc[tn][3] + bias2[col + 1]);
        }
    }
    __syncthreads();

    // ---- cp layer 3: 64 -> 1, gate ----
    if (tid < HD) wb[tid] = cpW3[(size_t)c * HD + tid];
    __syncthreads();
    if (tid < TILE_R) {
        const float* cph2 = sm + CPH2_OFF;
        float s = cpb3[c];
#pragma unroll 4
        for (int k = 0; k < HD; ++k)
            s = fmaf(cph2[tid * CPH_S + k], wb[k], s);
        out[(size_t)BATCH * ED * NC + (size_t)(r0 + tid) * NC + c] = s;
        gate[tid] = fminf(fmaxf(s * 0.5f + 0.5f, 0.f), 1.f);
    }
    __syncthreads();

    // ---- gated embedding output ----
    for (int t = tid; t < TILE_R * ED; t += NTHREADS) {
        int r = t >> 4, e = t & 15;
        float g = gate[r];
        float v = ps[r * ED + e] * g + ns[r * ED + e] * (1.f - g);
        out[(size_t)(r0 + r) * (ED * NC) + e * NC + c] = v;
    }
}

extern "C" void kernel_launch(void* const* d_in, const int* in_sizes, int n_in,
                              void* d_out, int out_size) {
    (void)in_sizes; (void)n_in; (void)out_size;
    const int smem_bytes = SMEM_FLOATS * sizeof(float);   // 99328
    cudaFuncSetAttribute(cb_kernel, cudaFuncAttributeMaxDynamicSharedMemorySize, smem_bytes);
    dim3 grid(BATCH / TILE_R, NC);
    cb_kernel<<<grid, NTHREADS, smem_bytes>>>(
        (const float*)d_in[0],
        (const float*)d_in[1],  (const float*)d_in[2],
        (const float*)d_in[3],  (const float*)d_in[4],
        (const float*)d_in[5],  (const float*)d_in[6],
        (const float*)d_in[7],  (const float*)d_in[8],
        (const float*)d_in[9],  (const float*)d_in[10],
        (const float*)d_in[11], (const float*)d_in[12],
        (const float*)d_in[13], (const float*)d_in[14],
        (const float*)d_in[15], (const float*)d_in[16],
        (const float*)d_in[17], (const float*)d_in[18],
        (float*)d_out);
}

// round 8
// speedup vs baseline: 4.0319x; 1.4633x over previous
#include <cuda_runtime.h>
#include <cuda_fp16.h>
#include <cstdint>

// Problem constants
#define BATCH   8192
#define INDIM   768
#define NC      64
#define HD      64
#define ED      16
#define TILE_R  128
#define NTHREADS 256

#define HB2_S 68        // hb row stride (float4-aligned)
#define CPH_S 65        // cp h2 row stride

// layer-1 staging: 24 stages of K=32, fp16
#define KC_T   32
#define NSTAGE (INDIM / KC_T)
// stage buffer in half2 units: A 2048 + Bpos 1024 + Bneg 1024 = 4096 h2 (16KB)
#define STG_H2 4096

// SMEM float offsets (phased aliasing):
// Phase A (layer1): stage bufs as h2 [0,8192) float-slots, bias1 [24704,24832)
// Phase B (layer2): W2F h2 [0,4096) float-slots, bias2 [24576,24704)
// Phase C (tails): hb_neg [0,8704), hb_pos [8704,17408), wb [17408,19456),
//                  ps [19456,21504), ns [21504,23552), gate [23552,23680)
// Phase D (cp): cpa [0,8192), cpw2 [8192,12288), then cph2 [0,8320)
#define BIAS2_OFF 24576
#define BIAS1_OFF 24704
#define HBN_OFF   0
#define HBP_OFF   8704
#define WB_OFF    17408
#define PS_OFF    19456
#define NS_OFF    21504
#define GATE_OFF  23552
#define CPA_OFF   0
#define CPW2_OFF  8192
#define CPH2_OFF  0
#define SMEM_FLOATS 24832      // 99328 bytes -> 2 CTAs/SM

typedef unsigned uh2;   // packed half2

__device__ __forceinline__ float relu_(float v) { return v > 0.f ? v : 0.f; }

__device__ __forceinline__ float tf32r(float v) {
    uint32_t u;
    asm("cvt.rna.tf32.f32 %0, %1;" : "=r"(u) : "f"(v));
    return __uint_as_float(u);
}
__device__ __forceinline__ uh2 h2p(float a, float b) {
    __half2 h = __floats2half2_rn(a, b);   // x (low) = a = smaller k
    return *(uh2*)&h;
}

// fp16 m16n8k16 mma (arch-agnostic PTX)
__device__ __forceinline__ void mma16(float* d, const uint4& a, const uint2& b) {
    asm volatile(
        "mma.sync.aligned.m16n8k16.row.col.f32.f16.f16.f32 "
        "{%0,%1,%2,%3}, {%4,%5,%6,%7}, {%8,%9}, {%0,%1,%2,%3};"
        : "+f"(d[0]), "+f"(d[1]), "+f"(d[2]), "+f"(d[3])
        : "r"(a.x), "r"(a.y), "r"(a.z), "r"(a.w), "r"(b.x), "r"(b.y));
}
// tf32 m16n8k8 mma (cp path)
__device__ __forceinline__ void mma8(float* d, const float4& a, const float2& b) {
    asm volatile(
        "mma.sync.aligned.m16n8k8.row.col.f32.tf32.tf32.f32 "
        "{%0,%1,%2,%3}, {%4,%5,%6,%7}, {%8,%9}, {%0,%1,%2,%3};"
        : "+f"(d[0]), "+f"(d[1]), "+f"(d[2]), "+f"(d[3])
        : "r"(__float_as_uint(a.x)), "r"(__float_as_uint(a.y)),
          "r"(__float_as_uint(a.z)), "r"(__float_as_uint(a.w)),
          "r"(__float_as_uint(b.x)), "r"(__float_as_uint(b.y)));
}

// ---------------- layer 3 (64 -> 16), vectorized broadcast reads ----------------
__device__ __forceinline__ void layer3v(
    const float* __restrict__ W3, const float* __restrict__ b3, int c,
    const float* __restrict__ hb, float* __restrict__ wb, float* __restrict__ obuf,
    int tid, int tx, int rbase)
{
    for (int t = tid; t < HD * ED / 4; t += NTHREADS)
        *(float4*)(wb + t * 4) = *(const float4*)(W3 + (size_t)c * HD * ED + t * 4);
    __syncthreads();
    float a3[8];
#pragma unroll
    for (int i = 0; i < 8; i++) a3[i] = 0.f;
#pragma unroll
    for (int kc = 0; kc < 16; ++kc) {
        float4 pv[8];
#pragma unroll
        for (int i = 0; i < 8; ++i)
            pv[i] = *(const float4*)(hb + (rbase + i) * HB2_S + kc * 4);
#pragma unroll
        for (int j = 0; j < 4; ++j) {
            float w = wb[(kc * 4 + j) * ED + tx];
#pragma unroll
            for (int i = 0; i < 8; ++i)
                a3[i] = fmaf(((const float*)&pv[i])[j], w, a3[i]);
        }
    }
    float bv = b3[c * ED + tx];
#pragma unroll
    for (int i = 0; i < 8; ++i)
        obuf[(rbase + i) * ED + tx] = a3[i] + bv;
    __syncthreads();
}

// ---------------- layer-1 staging (fp16) ----------------
// Producer row pattern: k0 = TK*16 + sel*8 + 2*q2 (TK = kp>>3, q2 = (kp>>1)&3, sel = kp&1)
__device__ __forceinline__ void stage_ldg(
    const float* __restrict__ x, const float* __restrict__ Wp,
    const float* __restrict__ Wn, int r0, int c, int kb, int tid,
    float4* xa /*4*/, float4* wv /*4*/)
{
#pragma unroll
    for (int i = 0; i < 2; ++i) {
        int item = tid + i * NTHREADS;      // 0..511
        int rp = item >> 3, cg = item & 7;
        int r = ((rp >> 3) << 4) | (rp & 7);
        const float* p = x + (size_t)(r0 + r) * INDIM + kb + cg * 4;
        xa[2 * i + 0] = *(const float4*)p;
        xa[2 * i + 1] = *(const float4*)(p + 8 * INDIM);
    }
    int kp = tid >> 4, ng = tid & 15;
    int TK = kp >> 3, q2 = (kp >> 1) & 3, sel = kp & 1;
    int k0 = TK * 16 + sel * 8 + 2 * q2;
    {
        const float* p = Wp + ((size_t)c * INDIM + kb + k0) * HD + ng * 4;
        wv[0] = *(const float4*)p;
        wv[1] = *(const float4*)(p + HD);        // row k0+1
        const float* q = Wn + ((size_t)c * INDIM + kb + k0) * HD + ng * 4;
        wv[2] = *(const float4*)q;
        wv[3] = *(const float4*)(q + HD);
    }
}

__device__ __forceinline__ void stage_sts(
    uh2* __restrict__ stg, int tid, const float4* xa, const float4* wv)
{
    // A: rows r,r+8 x 4 k -> 2 k-slots (jj = 2cg, 2cg+1), uint2 STS each
#pragma unroll
    for (int i = 0; i < 2; ++i) {
        int item = tid + i * NTHREADS;
        int rp = item >> 3, cg = item & 7;
        int tm = rp >> 3, g = rp & 7;
        const float* lo = (const float*)&xa[2 * i + 0];
        const float* hi = (const float*)&xa[2 * i + 1];
#pragma unroll
        for (int p = 0; p < 2; ++p) {
            int jj = 2 * cg + p;
            int TK = jj >> 3, q = jj & 3, h2i = (jj >> 2) & 1;
            uh2 u0 = h2p(lo[2 * p], lo[2 * p + 1]);
            uh2 u1 = h2p(hi[2 * p], hi[2 * p + 1]);
            *(uint2*)(stg + (tm * 2 + TK) * 128 + ((g * 4 + q) ^ TK) * 4 + h2i * 2) =
                make_uint2(u0, u1);
        }
    }
    // B: rows k0,k0+1 x 4 cols per bank
    int kp = tid >> 4, ng = tid & 15;
    int TK = kp >> 3, q2 = (kp >> 1) & 3, sel = kp & 1;
#pragma unroll
    for (int bw = 0; bw < 2; ++bw) {
        const float* lo = (const float*)&wv[2 * bw + 0];
        const float* hi = (const float*)&wv[2 * bw + 1];
#pragma unroll
        for (int j = 0; j < 4; ++j) {
            int n = ng * 4 + j;
            int tn = n >> 3, nn = n & 7;
            int ls = (nn * 4 + q2) ^ ((TK ^ tn) & 3);
            stg[2048 + bw * 1024 + (tn * 2 + TK) * 64 + ls * 2 + sel] = h2p(lo[j], hi[j]);
        }
    }
}

// ---------------- main kernel ----------------
__global__ __launch_bounds__(NTHREADS, 2)
void cb_kernel(
    const float* __restrict__ x,
    const float* __restrict__ posW1, const float* __restrict__ posb1,
    const float* __restrict__ posW2, const float* __restrict__ posb2,
    const float* __restrict__ posW3, const float* __restrict__ posb3,
    const float* __restrict__ negW1, const float* __restrict__ negb1,
    const float* __restrict__ negW2, const float* __restrict__ negb2,
    const float* __restrict__ negW3, const float* __restrict__ negb3,
    const float* __restrict__ cpW1,  const float* __restrict__ cpb1,
    const float* __restrict__ cpW2,  const float* __restrict__ cpb2,
    const float* __restrict__ cpW3,  const float* __restrict__ cpb3,
    float* __restrict__ out)
{
    extern __shared__ float sm[];
    float* hb_neg = sm + HBN_OFF;
    float* hb_pos = sm + HBP_OFF;
    float* wb     = sm + WB_OFF;
    float* ps     = sm + PS_OFF;
    float* ns     = sm + NS_OFF;
    float* gate   = sm + GATE_OFF;
    float* bias1  = sm + BIAS1_OFF;
    float* bias2  = sm + BIAS2_OFF;

    const int tid  = threadIdx.x;
    const int wid  = tid >> 5, lane = tid & 31;
    const int c    = blockIdx.y;
    const int r0   = blockIdx.x * TILE_R;
    const int tx    = tid & 15;
    const int rbase = (tid >> 4) * 8;

    if (tid < 64)       bias1[tid] = posb1[c * HD + tid];
    else if (tid < 128) bias1[tid] = negb1[c * HD + tid - 64];

    const int bank = wid >> 2;             // 0: pos, 1: neg
    const int tmA  = (wid & 3) * 2;
    const int tmB  = tmA + 1;
    const int gid  = lane >> 2, qid = lane & 3;

    // ---- layer 1: fp16 m16n8k16, 24 double-buffered stages ----
    float acc[2][8][4];
#pragma unroll
    for (int m = 0; m < 2; m++)
#pragma unroll
        for (int n = 0; n < 8; n++)
#pragma unroll
            for (int j = 0; j < 4; j++) acc[m][n][j] = 0.f;

    uh2* stg = (uh2*)sm;
    float4 xa[4], wv[4];
    stage_ldg(x, posW1, negW1, r0, c, 0, tid, xa, wv);
    stage_sts(stg, tid, xa, wv);
    __syncthreads();

    for (int s = 0; s < NSTAGE; ++s) {
        if (s + 1 < NSTAGE)
            stage_ldg(x, posW1, negW1, r0, c, (s + 1) * KC_T, tid, xa, wv);

        const uh2* A  = stg + (s & 1) * STG_H2;
        const uh2* Bb = A + 2048 + bank * 1024;
#pragma unroll
        for (int TK = 0; TK < 2; ++TK) {
            uint4 a0 = *(const uint4*)(A + (tmA * 2 + TK) * 128 + (lane ^ TK) * 4);
            uint4 a1 = *(const uint4*)(A + (tmB * 2 + TK) * 128 + (lane ^ TK) * 4);
#pragma unroll
            for (int tn = 0; tn < 8; ++tn) {
                uint2 bv = *(const uint2*)(Bb + (tn * 2 + TK) * 64 +
                                           (lane ^ ((TK ^ tn) & 3)) * 2);
                mma16(acc[0][tn], a0, bv);
                mma16(acc[1][tn], a1, bv);
            }
        }
        __syncthreads();
        if (s + 1 < NSTAGE) {
            stage_sts(stg + ((s + 1) & 1) * STG_H2, tid, xa, wv);
            __syncthreads();
        }
    }

    // ---- stage W2 (both banks) fp16 b-frag layout into [0,4096) h2 ----
    // (stage buffer 0 region; its last reader was stage 22, already synced past)
    {
        uh2* w2f = (uh2*)sm;
        int kp = tid >> 4, ng = tid & 15;
        int TKw = kp >> 2, q2 = kp & 3;
#pragma unroll
        for (int bw = 0; bw < 2; ++bw) {
            const float* W = bw ? negW2 : posW2;
#pragma unroll
            for (int sel = 0; sel < 2; ++sel) {
                int k0 = TKw * 16 + sel * 8 + 2 * q2;
                float4 v0 = *(const float4*)(W + ((size_t)c * HD + k0) * HD + ng * 4);
                float4 v1 = *(const float4*)(W + ((size_t)c * HD + k0 + 1) * HD + ng * 4);
                const float* l0 = (const float*)&v0;
                const float* l1 = (const float*)&v1;
#pragma unroll
                for (int j = 0; j < 4; ++j) {
                    int n = ng * 4 + j;
                    int tn = n >> 3, nn = n & 7;
                    int ls = (nn * 4 + q2) ^ ((TKw ^ tn) & 3);
                    w2f[bw * 2048 + (tn * 4 + TKw) * 64 + ls * 2 + sel] = h2p(l0[j], l1[j]);
                }
            }
        }
        if (tid < 64)       bias2[tid] = posb2[c * HD + tid];
        else if (tid < 128) bias2[tid] = negb2[c * HD + tid - 64];
    }
    __syncthreads();

    // ---- layer 2: A-fragments built directly from layer-1 acc registers ----
    float acc2[2][8][4];
#pragma unroll
    for (int m = 0; m < 2; m++)
#pragma unroll
        for (int n = 0; n < 8; n++)
#pragma unroll
            for (int j = 0; j < 4; j++) acc2[m][n][j] = 0.f;
    {
        const uh2* w2 = (const uh2*)sm + bank * 2048;
        const float* bs1 = bias1 + bank * 64;
#pragma unroll
        for (int m = 0; m < 2; ++m) {
#pragma unroll
            for (int TK2 = 0; TK2 < 4; ++TK2) {
                int t0 = 2 * TK2, t1 = t0 + 1;
                int c0 = t0 * 8 + 2 * qid, c1 = t1 * 8 + 2 * qid;
                uint4 a;
                a.x = h2p(relu_(acc[m][t0][0] + bs1[c0]),
                          relu_(acc[m][t0][1] + bs1[c0 + 1]));
                a.y = h2p(relu_(acc[m][t0][2] + bs1[c0]),
                          relu_(acc[m][t0][3] + bs1[c0 + 1]));
                a.z = h2p(relu_(acc[m][t1][0] + bs1[c1]),
                          relu_(acc[m][t1][1] + bs1[c1 + 1]));
                a.w = h2p(relu_(acc[m][t1][2] + bs1[c1]),
                          relu_(acc[m][t1][3] + bs1[c1 + 1]));
#pragma unroll
                for (int tn = 0; tn < 8; ++tn) {
                    uint2 bv = *(const uint2*)(w2 + (tn * 4 + TK2) * 64 +
                                               (lane ^ ((TK2 ^ tn) & 3)) * 2);
                    mma16(acc2[m][tn], a, bv);
                }
            }
        }
    }
    __syncthreads();   // W2F reads done before hb overwrite

    // ---- epilogue2: bias+relu -> hb row-major (stride 68) ----
    {
        float* hbT = bank ? hb_neg : hb_pos;
        const float* bs = bias2 + bank * 64;
#pragma unroll
        for (int m = 0; m < 2; ++m) {
            int row = (wid & 3) * 32 + m * 16 + gid;
#pragma unroll
            for (int tn = 0; tn < 8; ++tn) {
                int col = tn * 8 + qid * 2;
                hbT[row * HB2_S + col]           = relu_(acc2[m][tn][0] + bs[col]);
                hbT[row * HB2_S + col + 1]       = relu_(acc2[m][tn][1] + bs[col + 1]);
                hbT[(row + 8) * HB2_S + col]     = relu_(acc2[m][tn][2] + bs[col]);
                hbT[(row + 8) * HB2_S + col + 1] = relu_(acc2[m][tn][3] + bs[col + 1]);
            }
        }
    }
    __syncthreads();

    // ---- layer 3 (pos, neg) vectorized ----
    layer3v(posW3, posb3, c, hb_pos, wb, ps, tid, tx, rbase);
    layer3v(negW3, negb3, c, hb_neg, wb, ns, tid, tx, rbase);

    // ---- cp layer 1: [128 x 32] @ [32 x 64], relu -> cpa (tf32 frag layout) ----
    {
        float acc1[8][4];
#pragma unroll
        for (int i = 0; i < 8; i++)
#pragma unroll
            for (int j = 0; j < 4; j++) acc1[i][j] = 0.f;

        for (int t = tid; t < (2 * ED) * (HD / 4); t += NTHREADS)
            *(float4*)(wb + t * 4) =
                *(const float4*)(cpW1 + (size_t)c * 2 * ED * HD + t * 4);
        __syncthreads();

#pragma unroll
        for (int half = 0; half < 2; ++half) {
            const float* src = half ? ns : ps;
#pragma unroll
            for (int kc = 0; kc < 4; ++kc) {
                float4 pv[8];
#pragma unroll
                for (int i = 0; i < 8; ++i)
                    pv[i] = *(const float4*)(src + (rbase + i) * ED + kc * 4);
#pragma unroll
                for (int j = 0; j < 4; ++j) {
                    int k = half * ED + kc * 4 + j;
                    float4 w4 = *(const float4*)(wb + k * HD + tx * 4);
#pragma unroll
                    for (int i = 0; i < 8; ++i) {
                        float xv = ((const float*)&pv[i])[j];
                        acc1[i][0] = fmaf(xv, w4.x, acc1[i][0]);
                        acc1[i][1] = fmaf(xv, w4.y, acc1[i][1]);
                        acc1[i][2] = fmaf(xv, w4.z, acc1[i][2]);
                        acc1[i][3] = fmaf(xv, w4.w, acc1[i][3]);
                    }
                }
            }
        }
        __syncthreads();

        float* cpa = sm + CPA_OFF;
        float4 bv = *(const float4*)(cpb1 + c * HD + tx * 4);
#pragma unroll
        for (int i = 0; i < 8; ++i) {
            int row = rbase + i;
            int xr = 4 * (row & 7);
            float4 v;
            v.x = tf32r(relu_(acc1[i][0] + bv.x));
            v.y = tf32r(relu_(acc1[i][1] + bv.y));
            v.z = tf32r(relu_(acc1[i][2] + bv.z));
            v.w = tf32r(relu_(acc1[i][3] + bv.w));
            *(float4*)(cpa + row * 64 + ((tx * 4) ^ xr)) = v;
        }
        float* cw2 = sm + CPW2_OFF;
        for (int t = tid; t < HD * (HD / 4); t += NTHREADS) {
            int k = t >> 4, ng = t & 15;
            float4 v = *(const float4*)(cpW2 + ((size_t)c * HD + k) * HD + ng * 4);
            int n0 = (ng * 4) ^ (8 * (k & 3));
            *(float4*)(cw2 + k * 64 + n0) =
                make_float4(tf32r(v.x), tf32r(v.y), tf32r(v.z), tf32r(v.w));
        }
        if (tid < 64) bias2[tid] = cpb2[c * HD + tid];
    }
    __syncthreads();

    // ---- cp layer 2 on tensor cores (tf32): 8 warps x m16n64k64 ----
    {
        float accc[8][4];
#pragma unroll
        for (int n = 0; n < 8; n++)
#pragma unroll
            for (int j = 0; j < 4; j++) accc[n][j] = 0.f;

        const float* cpa = sm + CPA_OFF;
        const float* cw2 = sm + CPW2_OFF;
        const int rb0 = wid * 16 + gid;
        const int xA  = 4 * gid;
        const int xB  = 8 * qid;
#pragma unroll
        for (int tk = 0; tk < 8; ++tk) {
            int c0 = tk * 8 + qid;
            int c1 = c0 + 4;
            float4 a0;
            a0.x = cpa[rb0 * 64 + (c0 ^ xA)];
            a0.y = cpa[(rb0 + 8) * 64 + (c0 ^ xA)];
            a0.z = cpa[rb0 * 64 + (c1 ^ xA)];
            a0.w = cpa[(rb0 + 8) * 64 + (c1 ^ xA)];
#pragma unroll
            for (int tn = 0; tn < 8; ++tn) {
                int n = tn * 8 + gid;
                float2 bv;
                bv.x = cw2[c0 * 64 + (n ^ xB)];
                bv.y = cw2[c1 * 64 + (n ^ xB)];
                mma8(accc[tn], a0, bv);
            }
        }
        __syncthreads();

        float* cph2 = sm + CPH2_OFF;
#pragma unroll
        for (int tn = 0; tn < 8; ++tn) {
            int col = tn * 8 + qid * 2;
            cph2[rb0 * CPH_S + col]           = relu_(accc[tn][0] + bias2[col]);
            cph2[rb0 * CPH_S + col + 1]       = relu_(accc[tn][1] + bias2[col + 1]);
            cph2[(rb0 + 8) * CPH_S + col]     = relu_(accc[tn][2] + bias2[col]);
            cph2[(rb0 + 8) * CPH_S + col + 1] = relu_(accc[tn][3] + bias2[col + 1]);
        }
    }
    __syncthreads();

    // ---- cp layer 3: 64 -> 1, gate ----
    if (tid < HD) wb[tid] = cpW3[(size_t)c * HD + tid];
    __syncthreads();
    if (tid < TILE_R) {
        const float* cph2 = sm + CPH2_OFF;
        float s = cpb3[c];
#pragma unroll 4
        for (int k = 0; k < HD; ++k)
            s = fmaf(cph2[tid * CPH_S + k], wb[k], s);
        out[(size_t)BATCH * ED * NC + (size_t)(r0 + tid) * NC + c] = s;
        gate[tid] = fminf(fmaxf(s * 0.5f + 0.5f, 0.f), 1.f);
    }
    __syncthreads();

    // ---- gated embedding output ----
    for (int t = tid; t < TILE_R * ED; t += NTHREADS) {
        int r = t >> 4, e = t & 15;
        float g = gate[r];
        float v = ps[r * ED + e] * g + ns[r * ED + e] * (1.f - g);
        out[(size_t)(r0 + r) * (ED * NC) + e * NC + c] = v;
    }
}

extern "C" void kernel_launch(void* const* d_in, const int* in_sizes, int n_in,
                              void* d_out, int out_size) {
    (void)in_sizes; (void)n_in; (void)out_size;
    const int smem_bytes = SMEM_FLOATS * sizeof(float);   // 99328
    cudaFuncSetAttribute(cb_kernel, cudaFuncAttributeMaxDynamicSharedMemorySize, smem_bytes);
    dim3 grid(BATCH / TILE_R, NC);
    cb_kernel<<<grid, NTHREADS, smem_bytes>>>(
        (const float*)d_in[0],
        (const float*)d_in[1],  (const float*)d_in[2],
        (const float*)d_in[3],  (const float*)d_in[4],
        (const float*)d_in[5],  (const float*)d_in[6],
        (const float*)d_in[7],  (const float*)d_in[8],
        (const float*)d_in[9],  (const float*)d_in[10],
        (const float*)d_in[11], (const float*)d_in[12],
        (const float*)d_in[13], (const float*)d_in[14],
        (const float*)d_in[15], (const float*)d_in[16],
        (const float*)d_in[17], (const float*)d_in[18],
        (float*)d_out);
}

// round 9
// speedup vs baseline: 5.7955x; 1.4374x over previous
#include <cuda_runtime.h>
#include <cuda_fp16.h>
#include <cstdint>

// Problem constants
#define BATCH   8192
#define INDIM   768
#define NC      64
#define HD      64
#define ED      16
#define TILE_R  128
#define NTHREADS 256

#define HB2_S 68        // hb row stride (float4-aligned)
#define CPH_S 65        // cp h2 row stride

// layer-1 staging: 24 stages of K=32, fp16, cp.async 3-deep pipeline
#define KC_T   32
#define NSTAGE (INDIM / KC_T)
#define STG_H2 4096            // uh2 per stage: A 2048 + Bpos 1024 + Bneg 1024 (16KB)
#define STG_BYTES 16384

// SMEM float offsets (phased aliasing):
// Phase A (layer1): 3 stage bufs [0,12288) float-slots, bias1 [24704,24832)
// Phase B (layer2): W2F h2 [0,4096) float-slots, bias2 [24576,24704)
// Phase C (tails): hb_neg [0,8704), hb_pos [8704,17408), wb [17408,19456),
//                  ps [19456,21504), ns [21504,23552), gate [23552,23680)
// Phase D (cp): cpa [0,8192), cpw2 [8192,12288), then cph2 [0,8320)
#define BIAS2_OFF 24576
#define BIAS1_OFF 24704
#define HBN_OFF   0
#define HBP_OFF   8704
#define WB_OFF    17408
#define PS_OFF    19456
#define NS_OFF    21504
#define GATE_OFF  23552
#define CPA_OFF   0
#define CPW2_OFF  8192
#define CPH2_OFF  0
#define SMEM_FLOATS 24832      // 99328 bytes -> 2 CTAs/SM

typedef unsigned uh2;   // packed half2

// fp16 pre-converted, fragment-layout scratch (static __device__: allocation-free)
__device__ __align__(16) uh2 g_xh[(BATCH / TILE_R) * NSTAGE * 2048];   // [rblk][kblk][2048]
__device__ __align__(16) uh2 g_w1h[NC * NSTAGE * 2048];                // [c][kblk][pos1024|neg1024]

__device__ __forceinline__ float relu_(float v) { return v > 0.f ? v : 0.f; }

__device__ __forceinline__ float tf32r(float v) {
    uint32_t u;
    asm("cvt.rna.tf32.f32 %0, %1;" : "=r"(u) : "f"(v));
    return __uint_as_float(u);
}
__device__ __forceinline__ uh2 h2p(float a, float b) {
    __half2 h = __floats2half2_rn(a, b);   // x (low) = a = smaller k
    return *(uh2*)&h;
}
__device__ __forceinline__ uint32_t smem_u32(const void* p) {
    uint32_t a;
    asm("{ .reg .u64 t; cvta.to.shared.u64 t, %1; cvt.u32.u64 %0, t; }" : "=r"(a) : "l"(p));
    return a;
}

#define CP_A16(dst, src) asm volatile("cp.async.cg.shared.global [%0], [%1], 16;" :: "r"(dst), "l"(src))
#define CP_COMMIT()      asm volatile("cp.async.commit_group;" ::: "memory")
#define CP_WAIT1()       asm volatile("cp.async.wait_group 1;" ::: "memory")
#define CP_WAIT0()       asm volatile("cp.async.wait_group 0;" ::: "memory")

// fp16 m16n8k16 mma (arch-agnostic PTX)
__device__ __forceinline__ void mma16(float* d, const uint4& a, const uint2& b) {
    asm volatile(
        "mma.sync.aligned.m16n8k16.row.col.f32.f16.f16.f32 "
        "{%0,%1,%2,%3}, {%4,%5,%6,%7}, {%8,%9}, {%0,%1,%2,%3};"
        : "+f"(d[0]), "+f"(d[1]), "+f"(d[2]), "+f"(d[3])
        : "r"(a.x), "r"(a.y), "r"(a.z), "r"(a.w), "r"(b.x), "r"(b.y));
}
// tf32 m16n8k8 mma (cp path)
__device__ __forceinline__ void mma8(float* d, const float4& a, const float2& b) {
    asm volatile(
        "mma.sync.aligned.m16n8k8.row.col.f32.tf32.tf32.f32 "
        "{%0,%1,%2,%3}, {%4,%5,%6,%7}, {%8,%9}, {%0,%1,%2,%3};"
        : "+f"(d[0]), "+f"(d[1]), "+f"(d[2]), "+f"(d[3])
        : "r"(__float_as_uint(a.x)), "r"(__float_as_uint(a.y)),
          "r"(__float_as_uint(a.z)), "r"(__float_as_uint(a.w)),
          "r"(__float_as_uint(b.x)), "r"(__float_as_uint(b.y)));
}

// ---------------- prologue: build fp16 fragment-layout globals ----------------
// A-slot forward map (from the proven stage_sts): for rp=0..63,cg=0..7,p=0..1:
//   tm=rp>>3, g=rp&7, jj=2cg+p, TK=jj>>3, q=jj&3, h2i=(jj>>2)&1, k=2jj,
//   off=(tm*2+TK)*128+((g*4+q)^TK)*4+h2i*2, uint2 {row tm*16+g, row +8}
__global__ void prep_x(const float* __restrict__ x) {
    int blk  = blockIdx.x;                 // rblk*NSTAGE + kblk
    int rblk = blk / NSTAGE, kblk = blk % NSTAGE;
    int r0 = rblk * TILE_R, kb = kblk * KC_T;
    uh2* dst = g_xh + (size_t)blk * 2048;
    int t = threadIdx.x;
#pragma unroll
    for (int i = 0; i < 4; ++i) {
        int slot = (t + i * 256) * 2;      // even slot of a uint2 pair
        int tmTK = slot >> 7, tm = tmTK >> 1, TK = tmTK & 1;
        int rem = slot & 127, L = rem >> 2, h2i = (rem >> 1) & 1;
        int lane = L ^ TK, g = lane >> 2, q = lane & 3;
        int kl = 2 * (TK * 8 + h2i * 4 + q);
        const float* p = x + (size_t)(r0 + tm * 16 + g) * INDIM + kb + kl;
        float2 v0 = *(const float2*)p;
        float2 v1 = *(const float2*)(p + 8 * INDIM);
        *(uint2*)(dst + slot) = make_uint2(h2p(v0.x, v0.y), h2p(v1.x, v1.y));
    }
}

// B-slot forward map: off=(tn*2+TK)*64+ls*2+sel, ls=(nn*4+q2)^((TK^tn)&3),
//   k0=TK*16+sel*8+2q2, n=tn*8+nn, value (W[k0][n], W[k0+1][n])
__global__ void prep_w(const float* __restrict__ posW1, const float* __restrict__ negW1) {
    int blk = blockIdx.x;                  // c*NSTAGE + kblk
    int c = blk / NSTAGE, kblk = blk % NSTAGE, kb = kblk * KC_T;
    uh2* dst = g_w1h + (size_t)blk * 2048;
    int t = threadIdx.x;
#pragma unroll
    for (int i = 0; i < 8; ++i) {
        int idx = t + i * 256;             // 0..2047
        int bw = idx >> 10, slot = idx & 1023;
        int tnTK = slot >> 6, tn = tnTK >> 1, TK = tnTK & 1;
        int rem = slot & 63, ls = rem >> 1, sel = rem & 1;
        int m = ls ^ ((TK ^ tn) & 3), nn = m >> 2, q2 = m & 3;
        int n = tn * 8 + nn;
        int k0 = TK * 16 + sel * 8 + 2 * q2;
        const float* W = bw ? negW1 : posW1;
        float a = W[((size_t)c * INDIM + kb + k0) * HD + n];
        float b = W[((size_t)c * INDIM + kb + k0 + 1) * HD + n];
        dst[idx] = h2p(a, b);
    }
}

// ---------------- layer 3 (64 -> 16), vectorized broadcast reads ----------------
__device__ __forceinline__ void layer3v(
    const float* __restrict__ W3, const float* __restrict__ b3, int c,
    const float* __restrict__ hb, float* __restrict__ wb, float* __restrict__ obuf,
    int tid, int tx, int rbase)
{
    for (int t = tid; t < HD * ED / 4; t += NTHREADS)
        *(float4*)(wb + t * 4) = *(const float4*)(W3 + (size_t)c * HD * ED + t * 4);
    __syncthreads();
    float a3[8];
#pragma unroll
    for (int i = 0; i < 8; i++) a3[i] = 0.f;
#pragma unroll
    for (int kc = 0; kc < 16; ++kc) {
        float4 pv[8];
#pragma unroll
        for (int i = 0; i < 8; ++i)
            pv[i] = *(const float4*)(hb + (rbase + i) * HB2_S + kc * 4);
#pragma unroll
        for (int j = 0; j < 4; ++j) {
            float w = wb[(kc * 4 + j) * ED + tx];
#pragma unroll
            for (int i = 0; i < 8; ++i)
                a3[i] = fmaf(((const float*)&pv[i])[j], w, a3[i]);
        }
    }
    float bv = b3[c * ED + tx];
#pragma unroll
    for (int i = 0; i < 8; ++i)
        obuf[(rbase + i) * ED + tx] = a3[i] + bv;
    __syncthreads();
}

// ---------------- stage copy: 4 x 16B cp.async per thread ----------------
__device__ __forceinline__ void cp_stage(uint32_t stg_b, const uh2* gA, const uh2* gB, int tid) {
    uint32_t da = stg_b + tid * 16;
    const char* sa = (const char*)gA + tid * 16;
    CP_A16(da, sa);
    CP_A16(da + 4096, sa + 4096);
    uint32_t db = stg_b + 8192 + tid * 16;
    const char* sb = (const char*)gB + tid * 16;
    CP_A16(db, sb);
    CP_A16(db + 4096, sb + 4096);
}

// ---------------- main kernel ----------------
__global__ __launch_bounds__(NTHREADS, 2)
void cb_kernel(
    const float* __restrict__ x,
    const float* __restrict__ posW1, const float* __restrict__ posb1,
    const float* __restrict__ posW2, const float* __restrict__ posb2,
    const float* __restrict__ posW3, const float* __restrict__ posb3,
    const float* __restrict__ negW1, const float* __restrict__ negb1,
    const float* __restrict__ negW2, const float* __restrict__ negb2,
    const float* __restrict__ negW3, const float* __restrict__ negb3,
    const float* __restrict__ cpW1,  const float* __restrict__ cpb1,
    const float* __restrict__ cpW2,  const float* __restrict__ cpb2,
    const float* __restrict__ cpW3,  const float* __restrict__ cpb3,
    float* __restrict__ out)
{
    extern __shared__ float sm[];
    float* hb_neg = sm + HBN_OFF;
    float* hb_pos = sm + HBP_OFF;
    float* wb     = sm + WB_OFF;
    float* ps     = sm + PS_OFF;
    float* ns     = sm + NS_OFF;
    float* gate   = sm + GATE_OFF;
    float* bias1  = sm + BIAS1_OFF;
    float* bias2  = sm + BIAS2_OFF;

    const int tid  = threadIdx.x;
    const int wid  = tid >> 5, lane = tid & 31;
    const int c    = blockIdx.y;
    const int r0   = blockIdx.x * TILE_R;
    const int tx    = tid & 15;
    const int rbase = (tid >> 4) * 8;

    if (tid < 64)       bias1[tid] = posb1[c * HD + tid];
    else if (tid < 128) bias1[tid] = negb1[c * HD + tid - 64];

    const int bank = wid >> 2;             // 0: pos, 1: neg
    const int tmA  = (wid & 3) * 2;
    const int tmB  = tmA + 1;
    const int gid  = lane >> 2, qid = lane & 3;

    // ---- layer 1: fp16 m16n8k16, 24 stages via cp.async 3-deep pipeline ----
    float acc[2][8][4];
#pragma unroll
    for (int m = 0; m < 2; m++)
#pragma unroll
        for (int n = 0; n < 8; n++)
#pragma unroll
            for (int j = 0; j < 4; j++) acc[m][n][j] = 0.f;

    const uint32_t smb = smem_u32(sm);
    const uh2* gA = g_xh + (size_t)blockIdx.x * (NSTAGE * 2048);
    const uh2* gB = g_w1h + (size_t)c * (NSTAGE * 2048);

    cp_stage(smb, gA, gB, tid);                       CP_COMMIT();
    cp_stage(smb + STG_BYTES, gA + 2048, gB + 2048, tid); CP_COMMIT();

    for (int s = 0; s < NSTAGE; ++s) {
        if (s < NSTAGE - 1) { CP_WAIT1(); } else { CP_WAIT0(); }
        __syncthreads();
        if (s + 2 < NSTAGE) {
            cp_stage(smb + ((s + 2) % 3) * STG_BYTES,
                     gA + (s + 2) * 2048, gB + (s + 2) * 2048, tid);
            CP_COMMIT();
        }
        const uh2* A  = (const uh2*)sm + (s % 3) * STG_H2;
        const uh2* Bb = A + 2048 + bank * 1024;
#pragma unroll
        for (int TK = 0; TK < 2; ++TK) {
            uint4 a0 = *(const uint4*)(A + (tmA * 2 + TK) * 128 + (lane ^ TK) * 4);
            uint4 a1 = *(const uint4*)(A + (tmB * 2 + TK) * 128 + (lane ^ TK) * 4);
#pragma unroll
            for (int tn = 0; tn < 8; ++tn) {
                uint2 bv = *(const uint2*)(Bb + (tn * 2 + TK) * 64 +
                                           (lane ^ ((TK ^ tn) & 3)) * 2);
                mma16(acc[0][tn], a0, bv);
                mma16(acc[1][tn], a1, bv);
            }
        }
    }
    // (no sync needed: W2F below writes buf0 region [0,4096) uh2, which no warp
    //  reads during stages 22 (buf1) or 23 (buf2))

    // ---- stage W2 (both banks) fp16 b-frag layout into [0,4096) h2 ----
    {
        uh2* w2f = (uh2*)sm;
        int kp = tid >> 4, ng = tid & 15;
        int TKw = kp >> 2, q2 = kp & 3;
#pragma unroll
        for (int bw = 0; bw < 2; ++bw) {
            const float* W = bw ? negW2 : posW2;
#pragma unroll
            for (int sel = 0; sel < 2; ++sel) {
                int k0 = TKw * 16 + sel * 8 + 2 * q2;
                float4 v0 = *(const float4*)(W + ((size_t)c * HD + k0) * HD + ng * 4);
                float4 v1 = *(const float4*)(W + ((size_t)c * HD + k0 + 1) * HD + ng * 4);
                const float* l0 = (const float*)&v0;
                const float* l1 = (const float*)&v1;
#pragma unroll
                for (int j = 0; j < 4; ++j) {
                    int n = ng * 4 + j;
                    int tn = n >> 3, nn = n & 7;
                    int ls = (nn * 4 + q2) ^ ((TKw ^ tn) & 3);
                    w2f[bw * 2048 + (tn * 4 + TKw) * 64 + ls * 2 + sel] = h2p(l0[j], l1[j]);
                }
            }
        }
        if (tid < 64)       bias2[tid] = posb2[c * HD + tid];
        else if (tid < 128) bias2[tid] = negb2[c * HD + tid - 64];
    }
    __syncthreads();

    // ---- layer 2: A-fragments built directly from layer-1 acc registers ----
    float acc2[2][8][4];
#pragma unroll
    for (int m = 0; m < 2; m++)
#pragma unroll
        for (int n = 0; n < 8; n++)
#pragma unroll
            for (int j = 0; j < 4; j++) acc2[m][n][j] = 0.f;
    {
        const uh2* w2 = (const uh2*)sm + bank * 2048;
        const float* bs1 = bias1 + bank * 64;
#pragma unroll
        for (int m = 0; m < 2; ++m) {
#pragma unroll
            for (int TK2 = 0; TK2 < 4; ++TK2) {
                int t0 = 2 * TK2, t1 = t0 + 1;
                int c0 = t0 * 8 + 2 * qid, c1 = t1 * 8 + 2 * qid;
                uint4 a;
                a.x = h2p(relu_(acc[m][t0][0] + bs1[c0]),
                          relu_(acc[m][t0][1] + bs1[c0 + 1]));
                a.y = h2p(relu_(acc[m][t0][2] + bs1[c0]),
                          relu_(acc[m][t0][3] + bs1[c0 + 1]));
                a.z = h2p(relu_(acc[m][t1][0] + bs1[c1]),
                          relu_(acc[m][t1][1] + bs1[c1 + 1]));
                a.w = h2p(relu_(acc[m][t1][2] + bs1[c1]),
                          relu_(acc[m][t1][3] + bs1[c1 + 1]));
#pragma unroll
                for (int tn = 0; tn < 8; ++tn) {
                    uint2 bv = *(const uint2*)(w2 + (tn * 4 + TK2) * 64 +
                                               (lane ^ ((TK2 ^ tn) & 3)) * 2);
                    mma16(acc2[m][tn], a, bv);
                }
            }
        }
    }
    __syncthreads();   // W2F reads done before hb overwrite

    // ---- epilogue2: bias+relu -> hb row-major (stride 68) ----
    {
        float* hbT = bank ? hb_neg : hb_pos;
        const float* bs = bias2 + bank * 64;
#pragma unroll
        for (int m = 0; m < 2; ++m) {
            int row = (wid & 3) * 32 + m * 16 + gid;
#pragma unroll
            for (int tn = 0; tn < 8; ++tn) {
                int col = tn * 8 + qid * 2;
                hbT[row * HB2_S + col]           = relu_(acc2[m][tn][0] + bs[col]);
                hbT[row * HB2_S + col + 1]       = relu_(acc2[m][tn][1] + bs[col + 1]);
                hbT[(row + 8) * HB2_S + col]     = relu_(acc2[m][tn][2] + bs[col]);
                hbT[(row + 8) * HB2_S + col + 1] = relu_(acc2[m][tn][3] + bs[col + 1]);
            }
        }
    }
    __syncthreads();

    // ---- layer 3 (pos, neg) vectorized ----
    layer3v(posW3, posb3, c, hb_pos, wb, ps, tid, tx, rbase);
    layer3v(negW3, negb3, c, hb_neg, wb, ns, tid, tx, rbase);

    // ---- cp layer 1: [128 x 32] @ [32 x 64], relu -> cpa (tf32 frag layout) ----
    {
        float acc1[8][4];
#pragma unroll
        for (int i = 0; i < 8; i++)
#pragma unroll
            for (int j = 0; j < 4; j++) acc1[i][j] = 0.f;

        for (int t = tid; t < (2 * ED) * (HD / 4); t += NTHREADS)
            *(float4*)(wb + t * 4) =
                *(const float4*)(cpW1 + (size_t)c * 2 * ED * HD + t * 4);
        __syncthreads();

#pragma unroll
        for (int half = 0; half < 2; ++half) {
            const float* src = half ? ns : ps;
#pragma unroll
            for (int kc = 0; kc < 4; ++kc) {
                float4 pv[8];
#pragma unroll
                for (int i = 0; i < 8; ++i)
                    pv[i] = *(const float4*)(src + (rbase + i) * ED + kc * 4);
#pragma unroll
                for (int j = 0; j < 4; ++j) {
                    int k = half * ED + kc * 4 + j;
                    float4 w4 = *(const float4*)(wb + k * HD + tx * 4);
#pragma unroll
                    for (int i = 0; i < 8; ++i) {
                        float xv = ((const float*)&pv[i])[j];
                        acc1[i][0] = fmaf(xv, w4.x, acc1[i][0]);
                        acc1[i][1] = fmaf(xv, w4.y, acc1[i][1]);
                        acc1[i][2] = fmaf(xv, w4.z, acc1[i][2]);
                        acc1[i][3] = fmaf(xv, w4.w, acc1[i][3]);
                    }
                }
            }
        }
        __syncthreads();

        float* cpa = sm + CPA_OFF;
        float4 bv = *(const float4*)(cpb1 + c * HD + tx * 4);
#pragma unroll
        for (int i = 0; i < 8; ++i) {
            int row = rbase + i;
            int xr = 4 * (row & 7);
            float4 v;
            v.x = tf32r(relu_(acc1[i][0] + bv.x));
            v.y = tf32r(relu_(acc1[i][1] + bv.y));
            v.z = tf32r(relu_(acc1[i][2] + bv.z));
            v.w = tf32r(relu_(acc1[i][3] + bv.w));
            *(float4*)(cpa + row * 64 + ((tx * 4) ^ xr)) = v;
        }
        float* cw2 = sm + CPW2_OFF;
        for (int t = tid; t < HD * (HD / 4); t += NTHREADS) {
            int k = t >> 4, ng = t & 15;
            float4 v = *(const float4*)(cpW2 + ((size_t)c * HD + k) * HD + ng * 4);
            int n0 = (ng * 4) ^ (8 * (k & 3));
            *(float4*)(cw2 + k * 64 + n0) =
                make_float4(tf32r(v.x), tf32r(v.y), tf32r(v.z), tf32r(v.w));
        }
        if (tid < 64) bias2[tid] = cpb2[c * HD + tid];
    }
    __syncthreads();

    // ---- cp layer 2 on tensor cores (tf32): 8 warps x m16n64k64 ----
    {
        float accc[8][4];
#pragma unroll
        for (int n = 0; n < 8; n++)
#pragma unroll
            for (int j = 0; j < 4; j++) accc[n][j] = 0.f;

        const float* cpa = sm + CPA_OFF;
        const float* cw2 = sm + CPW2_OFF;
        const int rb0 = wid * 16 + gid;
        const int xA  = 4 * gid;
        const int xB  = 8 * qid;
#pragma unroll
        for (int tk = 0; tk < 8; ++tk) {
            int c0 = tk * 8 + qid;
            int c1 = c0 + 4;
            float4 a0;
            a0.x = cpa[rb0 * 64 + (c0 ^ xA)];
            a0.y = cpa[(rb0 + 8) * 64 + (c0 ^ xA)];
            a0.z = cpa[rb0 * 64 + (c1 ^ xA)];
            a0.w = cpa[(rb0 + 8) * 64 + (c1 ^ xA)];
#pragma unroll
            for (int tn = 0; tn < 8; ++tn) {
                int n = tn * 8 + gid;
                float2 bv;
                bv.x = cw2[c0 * 64 + (n ^ xB)];
                bv.y = cw2[c1 * 64 + (n ^ xB)];
                mma8(accc[tn], a0, bv);
            }
        }
        __syncthreads();

        float* cph2 = sm + CPH2_OFF;
#pragma unroll
        for (int tn = 0; tn < 8; ++tn) {
            int col = tn * 8 + qid * 2;
            cph2[rb0 * CPH_S + col]           = relu_(accc[tn][0] + bias2[col]);
            cph2[rb0 * CPH_S + col + 1]       = relu_(accc[tn][1] + bias2[col + 1]);
            cph2[(rb0 + 8) * CPH_S + col]     = relu_(accc[tn][2] + bias2[col]);
            cph2[(rb0 + 8) * CPH_S + col + 1] = relu_(accc[tn][3] + bias2[col + 1]);
        }
    }
    __syncthreads();

    // ---- cp layer 3: 64 -> 1, gate ----
    if (tid < HD) wb[tid] = cpW3[(size_t)c * HD + tid];
    __syncthreads();
    if (tid < TILE_R) {
        const float* cph2 = sm + CPH2_OFF;
        float s = cpb3[c];
#pragma unroll 4
        for (int k = 0; k < HD; ++k)
            s = fmaf(cph2[tid * CPH_S + k], wb[k], s);
        out[(size_t)BATCH * ED * NC + (size_t)(r0 + tid) * NC + c] = s;
        gate[tid] = fminf(fmaxf(s * 0.5f + 0.5f, 0.f), 1.f);
    }
    __syncthreads();

    // ---- gated embedding output ----
    for (int t = tid; t < TILE_R * ED; t += NTHREADS) {
        int r = t >> 4, e = t & 15;
        float g = gate[r];
        float v = ps[r * ED + e] * g + ns[r * ED + e] * (1.f - g);
        out[(size_t)(r0 + r) * (ED * NC) + e * NC + c] = v;
    }
}

extern "C" void kernel_launch(void* const* d_in, const int* in_sizes, int n_in,
                              void* d_out, int out_size) {
    (void)in_sizes; (void)n_in; (void)out_size;

    prep_x<<<(BATCH / TILE_R) * NSTAGE, NTHREADS>>>((const float*)d_in[0]);
    prep_w<<<NC * NSTAGE, NTHREADS>>>((const float*)d_in[1], (const float*)d_in[7]);

    const int smem_bytes = SMEM_FLOATS * sizeof(float);   // 99328
    cudaFuncSetAttribute(cb_kernel, cudaFuncAttributeMaxDynamicSharedMemorySize, smem_bytes);
    dim3 grid(BATCH / TILE_R, NC);
    cb_kernel<<<grid, NTHREADS, smem_bytes>>>(
        (const float*)d_in[0],
        (const float*)d_in[1],  (const float*)d_in[2],
        (const float*)d_in[3],  (const float*)d_in[4],
        (const float*)d_in[5],  (const float*)d_in[6],
        (const float*)d_in[7],  (const float*)d_in[8],
        (const float*)d_in[9],  (const float*)d_in[10],
        (const float*)d_in[11], (const float*)d_in[12],
        (const float*)d_in[13], (const float*)d_in[14],
        (const float*)d_in[15], (const float*)d_in[16],
        (const float*)d_in[17], (const float*)d_in[18],
        (float*)d_out);
}

// round 10
// speedup vs baseline: 6.7872x; 1.1711x over previous
#include <cuda_runtime.h>
#include <cuda_fp16.h>
#include <cstdint>

// Problem constants
#define BATCH   8192
#define INDIM   768
#define NC      64
#define HD      64
#define ED      16
#define TILE_R  128
#define NTHREADS 256

#define CPH_S 65        // cp h2 row stride

// layer-1 staging: 24 stages of K=32, fp16, cp.async 3-deep pipeline
#define KC_T   32
#define NSTAGE (INDIM / KC_T)
#define STG_H2 4096            // uh2 per stage: A 2048 + Bpos 1024 + Bneg 1024 (16KB)
#define STG_BYTES 16384

// SMEM float offsets (phased aliasing):
// Phase A (layer1): 3 stage bufs [0,12288) float-slots, bias1 [24704,24832)
// Phase B (l2/l3): W2F h2 slots [0,4096), W3F h2 slots [4096,5120),
//                  bias2 [24576,24704)
// Phase C (cp): wb [17408,19456), cpa [0,8192), cpw2 [8192,12288),
//               then cph2 [0,8320)
// Persistent: ps [19456,21504), ns [21504,23552), gate [23552,23680)
#define BIAS2_OFF 24576
#define BIAS1_OFF 24704
#define WB_OFF    17408
#define PS_OFF    19456
#define NS_OFF    21504
#define GATE_OFF  23552
#define CPA_OFF   0
#define CPW2_OFF  8192
#define CPH2_OFF  0
#define SMEM_FLOATS 24832      // 99328 bytes -> 2 CTAs/SM

typedef unsigned uh2;   // packed half2

// fp16 pre-converted, fragment-layout scratch (static __device__: allocation-free)
__device__ __align__(16) uh2 g_xh[(BATCH / TILE_R) * NSTAGE * 2048];   // [rblk][kblk][2048]
__device__ __align__(16) uh2 g_w1h[NC * NSTAGE * 2048];                // [c][kblk][pos1024|neg1024]

__device__ __forceinline__ float relu_(float v) { return v > 0.f ? v : 0.f; }

__device__ __forceinline__ float tf32r(float v) {
    uint32_t u;
    asm("cvt.rna.tf32.f32 %0, %1;" : "=r"(u) : "f"(v));
    return __uint_as_float(u);
}
__device__ __forceinline__ uh2 h2p(float a, float b) {
    __half2 h = __floats2half2_rn(a, b);   // x (low) = a = smaller k
    return *(uh2*)&h;
}
__device__ __forceinline__ uint32_t smem_u32(const void* p) {
    uint32_t a;
    asm("{ .reg .u64 t; cvta.to.shared.u64 t, %1; cvt.u32.u64 %0, t; }" : "=r"(a) : "l"(p));
    return a;
}

#define CP_A16(dst, src) asm volatile("cp.async.cg.shared.global [%0], [%1], 16;" :: "r"(dst), "l"(src))
#define CP_COMMIT()      asm volatile("cp.async.commit_group;" ::: "memory")
#define CP_WAIT1()       asm volatile("cp.async.wait_group 1;" ::: "memory")
#define CP_WAIT0()       asm volatile("cp.async.wait_group 0;" ::: "memory")

// fp16 m16n8k16 mma (arch-agnostic PTX)
__device__ __forceinline__ void mma16(float* d, const uint4& a, const uint2& b) {
    asm volatile(
        "mma.sync.aligned.m16n8k16.row.col.f32.f16.f16.f32 "
        "{%0,%1,%2,%3}, {%4,%5,%6,%7}, {%8,%9}, {%0,%1,%2,%3};"
        : "+f"(d[0]), "+f"(d[1]), "+f"(d[2]), "+f"(d[3])
        : "r"(a.x), "r"(a.y), "r"(a.z), "r"(a.w), "r"(b.x), "r"(b.y));
}
// tf32 m16n8k8 mma (cp path)
__device__ __forceinline__ void mma8(float* d, const float4& a, const float2& b) {
    asm volatile(
        "mma.sync.aligned.m16n8k8.row.col.f32.tf32.tf32.f32 "
        "{%0,%1,%2,%3}, {%4,%5,%6,%7}, {%8,%9}, {%0,%1,%2,%3};"
        : "+f"(d[0]), "+f"(d[1]), "+f"(d[2]), "+f"(d[3])
        : "r"(__float_as_uint(a.x)), "r"(__float_as_uint(a.y)),
          "r"(__float_as_uint(a.z)), "r"(__float_as_uint(a.w)),
          "r"(__float_as_uint(b.x)), "r"(__float_as_uint(b.y)));
}

// ---------------- prologue: build fp16 fragment-layout globals ----------------
__global__ void prep_x(const float* __restrict__ x) {
    int blk  = blockIdx.x;                 // rblk*NSTAGE + kblk
    int rblk = blk / NSTAGE, kblk = blk % NSTAGE;
    int r0 = rblk * TILE_R, kb = kblk * KC_T;
    uh2* dst = g_xh + (size_t)blk * 2048;
    int t = threadIdx.x;
#pragma unroll
    for (int i = 0; i < 4; ++i) {
        int slot = (t + i * 256) * 2;      // even slot of a uint2 pair
        int tmTK = slot >> 7, tm = tmTK >> 1, TK = tmTK & 1;
        int rem = slot & 127, L = rem >> 2, h2i = (rem >> 1) & 1;
        int lane = L ^ TK, g = lane >> 2, q = lane & 3;
        int kl = 2 * (TK * 8 + h2i * 4 + q);
        const float* p = x + (size_t)(r0 + tm * 16 + g) * INDIM + kb + kl;
        float2 v0 = *(const float2*)p;
        float2 v1 = *(const float2*)(p + 8 * INDIM);
        *(uint2*)(dst + slot) = make_uint2(h2p(v0.x, v0.y), h2p(v1.x, v1.y));
    }
}

__global__ void prep_w(const float* __restrict__ posW1, const float* __restrict__ negW1) {
    int blk = blockIdx.x;                  // c*NSTAGE + kblk
    int c = blk / NSTAGE, kblk = blk % NSTAGE, kb = kblk * KC_T;
    uh2* dst = g_w1h + (size_t)blk * 2048;
    int t = threadIdx.x;
#pragma unroll
    for (int i = 0; i < 8; ++i) {
        int idx = t + i * 256;             // 0..2047
        int bw = idx >> 10, slot = idx & 1023;
        int tnTK = slot >> 6, tn = tnTK >> 1, TK = tnTK & 1;
        int rem = slot & 63, ls = rem >> 1, sel = rem & 1;
        int m = ls ^ ((TK ^ tn) & 3), nn = m >> 2, q2 = m & 3;
        int n = tn * 8 + nn;
        int k0 = TK * 16 + sel * 8 + 2 * q2;
        const float* W = bw ? negW1 : posW1;
        float a = W[((size_t)c * INDIM + kb + k0) * HD + n];
        float b = W[((size_t)c * INDIM + kb + k0 + 1) * HD + n];
        dst[idx] = h2p(a, b);
    }
}

// ---------------- stage copy: 4 x 16B cp.async per thread ----------------
__device__ __forceinline__ void cp_stage(uint32_t stg_b, const uh2* gA, const uh2* gB, int tid) {
    uint32_t da = stg_b + tid * 16;
    const char* sa = (const char*)gA + tid * 16;
    CP_A16(da, sa);
    CP_A16(da + 4096, sa + 4096);
    uint32_t db = stg_b + 8192 + tid * 16;
    const char* sb = (const char*)gB + tid * 16;
    CP_A16(db, sb);
    CP_A16(db + 4096, sb + 4096);
}

// ---------------- main kernel ----------------
__global__ __launch_bounds__(NTHREADS, 2)
void cb_kernel(
    const float* __restrict__ x,
    const float* __restrict__ posW1, const float* __restrict__ posb1,
    const float* __restrict__ posW2, const float* __restrict__ posb2,
    const float* __restrict__ posW3, const float* __restrict__ posb3,
    const float* __restrict__ negW1, const float* __restrict__ negb1,
    const float* __restrict__ negW2, const float* __restrict__ negb2,
    const float* __restrict__ negW3, const float* __restrict__ negb3,
    const float* __restrict__ cpW1,  const float* __restrict__ cpb1,
    const float* __restrict__ cpW2,  const float* __restrict__ cpb2,
    const float* __restrict__ cpW3,  const float* __restrict__ cpb3,
    float* __restrict__ out)
{
    extern __shared__ float sm[];
    float* wb     = sm + WB_OFF;
    float* ps     = sm + PS_OFF;
    float* ns     = sm + NS_OFF;
    float* gate   = sm + GATE_OFF;
    float* bias1  = sm + BIAS1_OFF;
    float* bias2  = sm + BIAS2_OFF;

    const int tid  = threadIdx.x;
    const int wid  = tid >> 5, lane = tid & 31;
    const int c    = blockIdx.y;
    const int r0   = blockIdx.x * TILE_R;
    const int tx    = tid & 15;
    const int rbase = (tid >> 4) * 8;

    if (tid < 64)       bias1[tid] = posb1[c * HD + tid];
    else if (tid < 128) bias1[tid] = negb1[c * HD + tid - 64];

    const int bank = wid >> 2;             // 0: pos, 1: neg
    const int tmA  = (wid & 3) * 2;
    const int tmB  = tmA + 1;
    const int gid  = lane >> 2, qid = lane & 3;

    // ---- layer 1: fp16 m16n8k16, 24 stages via cp.async 3-deep pipeline ----
    float acc[2][8][4];
#pragma unroll
    for (int m = 0; m < 2; m++)
#pragma unroll
        for (int n = 0; n < 8; n++)
#pragma unroll
            for (int j = 0; j < 4; j++) acc[m][n][j] = 0.f;

    const uint32_t smb = smem_u32(sm);
    const uh2* gA = g_xh + (size_t)blockIdx.x * (NSTAGE * 2048);
    const uh2* gB = g_w1h + (size_t)c * (NSTAGE * 2048);

    cp_stage(smb, gA, gB, tid);                       CP_COMMIT();
    cp_stage(smb + STG_BYTES, gA + 2048, gB + 2048, tid); CP_COMMIT();

    for (int s = 0; s < NSTAGE; ++s) {
        if (s < NSTAGE - 1) { CP_WAIT1(); } else { CP_WAIT0(); }
        __syncthreads();
        if (s + 2 < NSTAGE) {
            cp_stage(smb + ((s + 2) % 3) * STG_BYTES,
                     gA + (s + 2) * 2048, gB + (s + 2) * 2048, tid);
            CP_COMMIT();
        }
        const uh2* A  = (const uh2*)sm + (s % 3) * STG_H2;
        const uh2* Bb = A + 2048 + bank * 1024;
#pragma unroll
        for (int TK = 0; TK < 2; ++TK) {
            uint4 a0 = *(const uint4*)(A + (tmA * 2 + TK) * 128 + (lane ^ TK) * 4);
            uint4 a1 = *(const uint4*)(A + (tmB * 2 + TK) * 128 + (lane ^ TK) * 4);
#pragma unroll
            for (int tn = 0; tn < 8; ++tn) {
                uint2 bv = *(const uint2*)(Bb + (tn * 2 + TK) * 64 +
                                           (lane ^ ((TK ^ tn) & 3)) * 2);
                mma16(acc[0][tn], a0, bv);
                mma16(acc[1][tn], a1, bv);
            }
        }
    }
    // (no sync needed: W2F/W3F below write buf0 [0,4096) + buf1 head [4096,5120)
    //  float-slots; buf0's last reader was stage 21, buf1's stage 22 — all warps
    //  passed the stage-23 top sync, which orders both)

    // ---- stage W2 (fp16 b-frag, [0,4096) h2) + W3 (fp16 b-frag, [4096,5120) h2) ----
    {
        uh2* w2f = (uh2*)sm;
        int kp = tid >> 4, ng = tid & 15;
        int TKw = kp >> 2, q2 = kp & 3;
#pragma unroll
        for (int bw = 0; bw < 2; ++bw) {
            const float* W = bw ? negW2 : posW2;
#pragma unroll
            for (int sel = 0; sel < 2; ++sel) {
                int k0 = TKw * 16 + sel * 8 + 2 * q2;
                float4 v0 = *(const float4*)(W + ((size_t)c * HD + k0) * HD + ng * 4);
                float4 v1 = *(const float4*)(W + ((size_t)c * HD + k0 + 1) * HD + ng * 4);
                const float* l0 = (const float*)&v0;
                const float* l1 = (const float*)&v1;
#pragma unroll
                for (int j = 0; j < 4; ++j) {
                    int n = ng * 4 + j;
                    int tn = n >> 3, nn = n & 7;
                    int ls = (nn * 4 + q2) ^ ((TKw ^ tn) & 3);
                    w2f[bw * 2048 + (tn * 4 + TKw) * 64 + ls * 2 + sel] = h2p(l0[j], l1[j]);
                }
            }
        }
        // W3F: 1024 uh2 at h2-slot 4096; slot = bw*512 + (tn*4+TK)*64 + ls*2 + sel
        uh2* w3f = (uh2*)sm + 4096;
#pragma unroll
        for (int i = 0; i < 4; ++i) {
            int idx = tid + i * 256;          // 0..1023
            int bw = idx >> 9, slot = idx & 511;
            int tnTK = slot >> 6, tn = tnTK >> 2, TK = tnTK & 3;
            int rem = slot & 63, ls = rem >> 1, sel = rem & 1;
            int m = ls ^ ((TK ^ tn) & 3), nn = m >> 2, q2w = m & 3;
            int n = tn * 8 + nn;
            int k0 = TK * 16 + sel * 8 + 2 * q2w;
            const float* W = bw ? negW3 : posW3;
            float a = W[((size_t)c * HD + k0) * ED + n];
            float b = W[((size_t)c * HD + k0 + 1) * ED + n];
            w3f[idx] = h2p(a, b);
        }
        if (tid < 64)       bias2[tid] = posb2[c * HD + tid];
        else if (tid < 128) bias2[tid] = negb2[c * HD + tid - 64];
    }
    __syncthreads();

    // ---- layer 2: A-fragments built directly from layer-1 acc registers ----
    float acc2[2][8][4];
#pragma unroll
    for (int m = 0; m < 2; m++)
#pragma unroll
        for (int n = 0; n < 8; n++)
#pragma unroll
            for (int j = 0; j < 4; j++) acc2[m][n][j] = 0.f;
    {
        const uh2* w2 = (const uh2*)sm + bank * 2048;
        const float* bs1 = bias1 + bank * 64;
#pragma unroll
        for (int m = 0; m < 2; ++m) {
#pragma unroll
            for (int TK2 = 0; TK2 < 4; ++TK2) {
                int t0 = 2 * TK2, t1 = t0 + 1;
                int c0 = t0 * 8 + 2 * qid, c1 = t1 * 8 + 2 * qid;
                uint4 a;
                a.x = h2p(relu_(acc[m][t0][0] + bs1[c0]),
                          relu_(acc[m][t0][1] + bs1[c0 + 1]));
                a.y = h2p(relu_(acc[m][t0][2] + bs1[c0]),
                          relu_(acc[m][t0][3] + bs1[c0 + 1]));
                a.z = h2p(relu_(acc[m][t1][0] + bs1[c1]),
                          relu_(acc[m][t1][1] + bs1[c1 + 1]));
                a.w = h2p(relu_(acc[m][t1][2] + bs1[c1]),
                          relu_(acc[m][t1][3] + bs1[c1 + 1]));
#pragma unroll
                for (int tn = 0; tn < 8; ++tn) {
                    uint2 bv = *(const uint2*)(w2 + (tn * 4 + TK2) * 64 +
                                               (lane ^ ((TK2 ^ tn) & 3)) * 2);
                    mma16(acc2[m][tn], a, bv);
                }
            }
        }
    }

    // ---- layer 3: A-fragments built directly from layer-2 acc registers ----
    float acc3[2][2][4];
#pragma unroll
    for (int m = 0; m < 2; m++)
#pragma unroll
        for (int n = 0; n < 2; n++)
#pragma unroll
            for (int j = 0; j < 4; j++) acc3[m][n][j] = 0.f;
    {
        const uh2* w3 = (const uh2*)sm + 4096 + bank * 512;
        const float* bs2 = bias2 + bank * 64;
#pragma unroll
        for (int m = 0; m < 2; ++m) {
#pragma unroll
            for (int TK3 = 0; TK3 < 4; ++TK3) {
                int t0 = 2 * TK3, t1 = t0 + 1;
                int c0 = t0 * 8 + 2 * qid, c1 = t1 * 8 + 2 * qid;
                uint4 a;
                a.x = h2p(relu_(acc2[m][t0][0] + bs2[c0]),
                          relu_(acc2[m][t0][1] + bs2[c0 + 1]));
                a.y = h2p(relu_(acc2[m][t0][2] + bs2[c0]),
                          relu_(acc2[m][t0][3] + bs2[c0 + 1]));
                a.z = h2p(relu_(acc2[m][t1][0] + bs2[c1]),
                          relu_(acc2[m][t1][1] + bs2[c1 + 1]));
                a.w = h2p(relu_(acc2[m][t1][2] + bs2[c1]),
                          relu_(acc2[m][t1][3] + bs2[c1 + 1]));
#pragma unroll
                for (int tn = 0; tn < 2; ++tn) {
                    uint2 bv = *(const uint2*)(w3 + (tn * 4 + TK3) * 64 +
                                               (lane ^ ((TK3 ^ tn) & 3)) * 2);
                    mma16(acc3[m][tn], a, bv);
                }
            }
        }
    }

    // ---- epilogue3: + bias3, write ps/ns [128 x 16] fp32 (no relu) ----
    {
        const float* b3g = (bank ? negb3 : posb3) + c * ED;
        float* obuf = bank ? ns : ps;
        float2 bv0 = *(const float2*)(b3g + 2 * qid);
        float2 bv1 = *(const float2*)(b3g + 8 + 2 * qid);
#pragma unroll
        for (int m = 0; m < 2; ++m) {
            int row = (wid & 3) * 32 + m * 16 + gid;
#pragma unroll
            for (int tn = 0; tn < 2; ++tn) {
                int col = tn * 8 + 2 * qid;
                float2 bv = tn ? bv1 : bv0;
                *(float2*)(obuf + row * ED + col) =
                    make_float2(acc3[m][tn][0] + bv.x, acc3[m][tn][1] + bv.y);
                *(float2*)(obuf + (row + 8) * ED + col) =
                    make_float2(acc3[m][tn][2] + bv.x, acc3[m][tn][3] + bv.y);
            }
        }
    }
    __syncthreads();

    // ---- cp layer 1: [128 x 32] (ps||ns) @ [32 x 64], relu -> cpa (tf32 frag) ----
    {
        float acc1[8][4];
#pragma unroll
        for (int i = 0; i < 8; i++)
#pragma unroll
            for (int j = 0; j < 4; j++) acc1[i][j] = 0.f;

        for (int t = tid; t < (2 * ED) * (HD / 4); t += NTHREADS)
            *(float4*)(wb + t * 4) =
                *(const float4*)(cpW1 + (size_t)c * 2 * ED * HD + t * 4);
        __syncthreads();

#pragma unroll
        for (int half = 0; half < 2; ++half) {
            const float* src = half ? ns : ps;
#pragma unroll
            for (int kc = 0; kc < 4; ++kc) {
                float4 pv[8];
#pragma unroll
                for (int i = 0; i < 8; ++i)
                    pv[i] = *(const float4*)(src + (rbase + i) * ED + kc * 4);
#pragma unroll
                for (int j = 0; j < 4; ++j) {
                    int k = half * ED + kc * 4 + j;
                    float4 w4 = *(const float4*)(wb + k * HD + tx * 4);
#pragma unroll
                    for (int i = 0; i < 8; ++i) {
                        float xv = ((const float*)&pv[i])[j];
                        acc1[i][0] = fmaf(xv, w4.x, acc1[i][0]);
                        acc1[i][1] = fmaf(xv, w4.y, acc1[i][1]);
                        acc1[i][2] = fmaf(xv, w4.z, acc1[i][2]);
                        acc1[i][3] = fmaf(xv, w4.w, acc1[i][3]);
                    }
                }
            }
        }
        __syncthreads();

        float* cpa = sm + CPA_OFF;
        float4 bv = *(const float4*)(cpb1 + c * HD + tx * 4);
#pragma unroll
        for (int i = 0; i < 8; ++i) {
            int row = rbase + i;
            int xr = 4 * (row & 7);
            float4 v;
            v.x = tf32r(relu_(acc1[i][0] + bv.x));
            v.y = tf32r(relu_(acc1[i][1] + bv.y));
            v.z = tf32r(relu_(acc1[i][2] + bv.z));
            v.w = tf32r(relu_(acc1[i][3] + bv.w));
            *(float4*)(cpa + row * 64 + ((tx * 4) ^ xr)) = v;
        }
        float* cw2 = sm + CPW2_OFF;
        for (int t = tid; t < HD * (HD / 4); t += NTHREADS) {
            int k = t >> 4, ng = t & 15;
            float4 v = *(const float4*)(cpW2 + ((size_t)c * HD + k) * HD + ng * 4);
            int n0 = (ng * 4) ^ (8 * (k & 3));
            *(float4*)(cw2 + k * 64 + n0) =
                make_float4(tf32r(v.x), tf32r(v.y), tf32r(v.z), tf32r(v.w));
        }
        if (tid < 64) bias2[tid] = cpb2[c * HD + tid];
    }
    __syncthreads();

    // ---- cp layer 2 on tensor cores (tf32): 8 warps x m16n64k64 ----
    {
        float accc[8][4];
#pragma unroll
        for (int n = 0; n < 8; n++)
#pragma unroll
            for (int j = 0; j < 4; j++) accc[n][j] = 0.f;

        const float* cpa = sm + CPA_OFF;
        const float* cw2 = sm + CPW2_OFF;
        const int rb0 = wid * 16 + gid;
        const int xA  = 4 * gid;
        const int xB  = 8 * qid;
#pragma unroll
        for (int tk = 0; tk < 8; ++tk) {
            int c0 = tk * 8 + qid;
            int c1 = c0 + 4;
            float4 a0;
            a0.x = cpa[rb0 * 64 + (c0 ^ xA)];
            a0.y = cpa[(rb0 + 8) * 64 + (c0 ^ xA)];
            a0.z = cpa[rb0 * 64 + (c1 ^ xA)];
            a0.w = cpa[(rb0 + 8) * 64 + (c1 ^ xA)];
#pragma unroll
            for (int tn = 0; tn < 8; ++tn) {
                int n = tn * 8 + gid;
                float2 bv;
                bv.x = cw2[c0 * 64 + (n ^ xB)];
                bv.y = cw2[c1 * 64 + (n ^ xB)];
                mma8(accc[tn], a0, bv);
            }
        }
        __syncthreads();

        float* cph2 = sm + CPH2_OFF;
#pragma unroll
        for (int tn = 0; tn < 8; ++tn) {
            int col = tn * 8 + qid * 2;
            cph2[rb0 * CPH_S + col]           = relu_(accc[tn][0] + bias2[col]);
            cph2[rb0 * CPH_S + col + 1]       = relu_(accc[tn][1] + bias2[col + 1]);
            cph2[(rb0 + 8) * CPH_S + col]     = relu_(accc[tn][2] + bias2[col]);
            cph2[(rb0 + 8) * CPH_S + col + 1] = relu_(accc[tn][3] + bias2[col + 1]);
        }
    }
    __syncthreads();

    // ---- cp layer 3: 64 -> 1, gate ----
    if (tid < HD) wb[tid] = cpW3[(size_t)c * HD + tid];
    __syncthreads();
    if (tid < TILE_R) {
        const float* cph2 = sm + CPH2_OFF;
        float s = cpb3[c];
#pragma unroll 4
        for (int k = 0; k < HD; ++k)
            s = fmaf(cph2[tid * CPH_S + k], wb[k], s);
        out[(size_t)BATCH * ED * NC + (size_t)(r0 + tid) * NC + c] = s;
        gate[tid] = fminf(fmaxf(s * 0.5f + 0.5f, 0.f), 1.f);
    }
    __syncthreads();

    // ---- gated embedding output ----
    for (int t = tid; t < TILE_R * ED; t += NTHREADS) {
        int r = t >> 4, e = t & 15;
        float g = gate[r];
        float v = ps[r * ED + e] * g + ns[r * ED + e] * (1.f - g);
        out[(size_t)(r0 + r) * (ED * NC) + e * NC + c] = v;
    }
}

extern "C" void kernel_launch(void* const* d_in, const int* in_sizes, int n_in,
                              void* d_out, int out_size) {
    (void)in_sizes; (void)n_in; (void)out_size;

    prep_x<<<(BATCH / TILE_R) * NSTAGE, NTHREADS>>>((const float*)d_in[0]);
    prep_w<<<NC * NSTAGE, NTHREADS>>>((const float*)d_in[1], (const float*)d_in[7]);

    const int smem_bytes = SMEM_FLOATS * sizeof(float);   // 99328
    cudaFuncSetAttribute(cb_kernel, cudaFuncAttributeMaxDynamicSharedMemorySize, smem_bytes);
    dim3 grid(BATCH / TILE_R, NC);
    cb_kernel<<<grid, NTHREADS, smem_bytes>>>(
        (const float*)d_in[0],
        (const float*)d_in[1],  (const float*)d_in[2],
        (const float*)d_in[3],  (const float*)d_in[4],
        (const float*)d_in[5],  (const float*)d_in[6],
        (const float*)d_in[7],  (const float*)d_in[8],
        (const float*)d_in[9],  (const float*)d_in[10],
        (const float*)d_in[11], (const float*)d_in[12],
        (const float*)d_in[13], (const float*)d_in[14],
        (const float*)d_in[15], (const float*)d_in[16],
        (const float*)d_in[17], (const float*)d_in[18],
        (float*)d_out);
}

// round 15
// speedup vs baseline: 7.8899x; 1.1625x over previous
#include <cuda_runtime.h>
#include <cuda_fp16.h>
#include <cstdint>

// Problem constants
#define BATCH   8192
#define INDIM   768
#define NC      64
#define HD      64
#define ED      16
#define TILE_R  128
#define NTHREADS 256

// layer-1 staging: 24 stages of K=32, fp16, cp.async 3-deep pipeline
#define KC_T   32
#define NSTAGE (INDIM / KC_T)
#define STG_H2 4096            // uh2 per stage: A 2048 + Bpos 1024 + Bneg 1024 (16KB)
#define STG_BYTES 16384

// SMEM float offsets (phased aliasing):
// Phase A (layer1): 3 stage bufs [0,12288) float-slots, bias1 [24704,24832)
// Post-mainloop staging (safe: avoids buf2 [8192,12288)):
//   W2F h2 [0,4096), W3F h2 [4096,5120), CPW1F h2 [5120,6144),
//   CPW2F h2 [6144,8192), bias2 [24576,24704), cpb1s/cpb2s/cpw3s [23680,23872)
// Epilogue3 (post-sync): psh h2 [8192,9216), nsh h2 [9216,10240)
// Persistent: ps [19456,21504), ns [21504,23552), gate [23552,23680)
#define PSH_OFF   8192
#define NSH_OFF   9216
#define CPW1_OFF  5120
#define CPW2_OFF  6144
#define PS_OFF    19456
#define NS_OFF    21504
#define GATE_OFF  23552
#define CPB1_OFF  23680
#define CPB2_OFF  23744
#define CPW3_OFF  23808
#define BIAS2_OFF 24576
#define BIAS1_OFF 24704
#define SMEM_FLOATS 24832      // 99328 bytes -> 2 CTAs/SM

typedef unsigned uh2;   // packed half2

// fp16 pre-converted, fragment-layout scratch (static __device__: allocation-free)
__device__ __align__(16) uh2 g_xh[(BATCH / TILE_R) * NSTAGE * 2048];   // [rblk][kblk][2048]
__device__ __align__(16) uh2 g_w1h[NC * NSTAGE * 2048];                // [c][kblk][pos1024|neg1024]

__device__ __forceinline__ float relu_(float v) { return v > 0.f ? v : 0.f; }

__device__ __forceinline__ uh2 h2p(float a, float b) {
    __half2 h = __floats2half2_rn(a, b);   // x (low) = a = smaller k
    return *(uh2*)&h;
}
__device__ __forceinline__ uint32_t smem_u32(const void* p) {
    uint32_t a;
    asm("{ .reg .u64 t; cvta.to.shared.u64 t, %1; cvt.u32.u64 %0, t; }" : "=r"(a) : "l"(p));
    return a;
}

#define CP_A16(dst, src) asm volatile("cp.async.cg.shared.global [%0], [%1], 16;" :: "r"(dst), "l"(src))
#define CP_COMMIT()      asm volatile("cp.async.commit_group;" ::: "memory")
#define CP_WAIT1()       asm volatile("cp.async.wait_group 1;" ::: "memory")
#define CP_WAIT0()       asm volatile("cp.async.wait_group 0;" ::: "memory")

// fp16 m16n8k16 mma (arch-agnostic PTX)
__device__ __forceinline__ void mma16(float* d, const uint4& a, const uint2& b) {
    asm volatile(
        "mma.sync.aligned.m16n8k16.row.col.f32.f16.f16.f32 "
        "{%0,%1,%2,%3}, {%4,%5,%6,%7}, {%8,%9}, {%0,%1,%2,%3};"
        : "+f"(d[0]), "+f"(d[1]), "+f"(d[2]), "+f"(d[3])
        : "r"(a.x), "r"(a.y), "r"(a.z), "r"(a.w), "r"(b.x), "r"(b.y));
}

// ---------------- prologue: build fp16 fragment-layout globals ----------------
__global__ void prep_x(const float* __restrict__ x) {
    int blk  = blockIdx.x;                 // rblk*NSTAGE + kblk
    int rblk = blk / NSTAGE, kblk = blk % NSTAGE;
    int r0 = rblk * TILE_R, kb = kblk * KC_T;
    uh2* dst = g_xh + (size_t)blk * 2048;
    int t = threadIdx.x;
#pragma unroll
    for (int i = 0; i < 4; ++i) {
        int slot = (t + i * 256) * 2;      // even slot of a uint2 pair
        int tmTK = slot >> 7, tm = tmTK >> 1, TK = tmTK & 1;
        int rem = slot & 127, L = rem >> 2, h2i = (rem >> 1) & 1;
        int lane = L ^ TK, g = lane >> 2, q = lane & 3;
        int kl = 2 * (TK * 8 + h2i * 4 + q);
        const float* p = x + (size_t)(r0 + tm * 16 + g) * INDIM + kb + kl;
        float2 v0 = *(const float2*)p;
        float2 v1 = *(const float2*)(p + 8 * INDIM);
        *(uint2*)(dst + slot) = make_uint2(h2p(v0.x, v0.y), h2p(v1.x, v1.y));
    }
}

__global__ void prep_w(const float* __restrict__ posW1, const float* __restrict__ negW1) {
    int blk = blockIdx.x;                  // c*NSTAGE + kblk
    int c = blk / NSTAGE, kblk = blk % NSTAGE, kb = kblk * KC_T;
    uh2* dst = g_w1h + (size_t)blk * 2048;
    int t = threadIdx.x;
#pragma unroll
    for (int i = 0; i < 8; ++i) {
        int idx = t + i * 256;             // 0..2047
        int bw = idx >> 10, slot = idx & 1023;
        int tnTK = slot >> 6, tn = tnTK >> 1, TK = tnTK & 1;
        int rem = slot & 63, ls = rem >> 1, sel = rem & 1;
        int m = ls ^ ((TK ^ tn) & 3), nn = m >> 2, q2 = m & 3;
        int n = tn * 8 + nn;
        int k0 = TK * 16 + sel * 8 + 2 * q2;
        const float* W = bw ? negW1 : posW1;
        float a = W[((size_t)c * INDIM + kb + k0) * HD + n];
        float b = W[((size_t)c * INDIM + kb + k0 + 1) * HD + n];
        dst[idx] = h2p(a, b);
    }
}

// ---------------- stage copy: 4 x 16B cp.async per thread ----------------
__device__ __forceinline__ void cp_stage(uint32_t stg_b, const uh2* gA, const uh2* gB, int tid) {
    uint32_t da = stg_b + tid * 16;
    const char* sa = (const char*)gA + tid * 16;
    CP_A16(da, sa);
    CP_A16(da + 4096, sa + 4096);
    uint32_t db = stg_b + 8192 + tid * 16;
    const char* sb = (const char*)gB + tid * 16;
    CP_A16(db, sb);
    CP_A16(db + 4096, sb + 4096);
}

// ---------------- main kernel ----------------
__global__ __launch_bounds__(NTHREADS, 2)
void cb_kernel(
    const float* __restrict__ x,
    const float* __restrict__ posW1, const float* __restrict__ posb1,
    const float* __restrict__ posW2, const float* __restrict__ posb2,
    const float* __restrict__ posW3, const float* __restrict__ posb3,
    const float* __restrict__ negW1, const float* __restrict__ negb1,
    const float* __restrict__ negW2, const float* __restrict__ negb2,
    const float* __restrict__ negW3, const float* __restrict__ negb3,
    const float* __restrict__ cpW1,  const float* __restrict__ cpb1,
    const float* __restrict__ cpW2,  const float* __restrict__ cpb2,
    const float* __restrict__ cpW3,  const float* __restrict__ cpb3,
    float* __restrict__ out)
{
    extern __shared__ float sm[];
    float* ps     = sm + PS_OFF;
    float* ns     = sm + NS_OFF;
    float* gate   = sm + GATE_OFF;
    float* bias1  = sm + BIAS1_OFF;
    float* bias2  = sm + BIAS2_OFF;
    float* cpb1s  = sm + CPB1_OFF;
    float* cpb2s  = sm + CPB2_OFF;
    float* cpw3s  = sm + CPW3_OFF;

    const int tid  = threadIdx.x;
    const int wid  = tid >> 5, lane = tid & 31;
    const int c    = blockIdx.y;
    const int r0   = blockIdx.x * TILE_R;

    if (tid < 64)       bias1[tid] = posb1[c * HD + tid];
    else if (tid < 128) bias1[tid] = negb1[c * HD + tid - 64];

    const int bank = wid >> 2;             // 0: pos, 1: neg
    const int tmA  = (wid & 3) * 2;
    const int tmB  = tmA + 1;
    const int gid  = lane >> 2, qid = lane & 3;

    // ---- layer 1: fp16 m16n8k16, 24 stages via cp.async 3-deep pipeline ----
    float acc[2][8][4];
#pragma unroll
    for (int m = 0; m < 2; m++)
#pragma unroll
        for (int n = 0; n < 8; n++)
#pragma unroll
            for (int j = 0; j < 4; j++) acc[m][n][j] = 0.f;

    const uint32_t smb = smem_u32(sm);
    const uh2* gA = g_xh + (size_t)blockIdx.x * (NSTAGE * 2048);
    const uh2* gB = g_w1h + (size_t)c * (NSTAGE * 2048);

    cp_stage(smb, gA, gB, tid);                       CP_COMMIT();
    cp_stage(smb + STG_BYTES, gA + 2048, gB + 2048, tid); CP_COMMIT();

    for (int s = 0; s < NSTAGE; ++s) {
        if (s < NSTAGE - 1) { CP_WAIT1(); } else { CP_WAIT0(); }
        __syncthreads();
        if (s + 2 < NSTAGE) {
            cp_stage(smb + ((s + 2) % 3) * STG_BYTES,
                     gA + (s + 2) * 2048, gB + (s + 2) * 2048, tid);
            CP_COMMIT();
        }
        const uh2* A  = (const uh2*)sm + (s % 3) * STG_H2;
        const uh2* Bb = A + 2048 + bank * 1024;
#pragma unroll
        for (int TK = 0; TK < 2; ++TK) {
            uint4 a0 = *(const uint4*)(A + (tmA * 2 + TK) * 128 + (lane ^ TK) * 4);
            uint4 a1 = *(const uint4*)(A + (tmB * 2 + TK) * 128 + (lane ^ TK) * 4);
#pragma unroll
            for (int tn = 0; tn < 8; ++tn) {
                uint2 bv = *(const uint2*)(Bb + (tn * 2 + TK) * 64 +
                                           (lane ^ ((TK ^ tn) & 3)) * 2);
                mma16(acc[0][tn], a0, bv);
                mma16(acc[1][tn], a1, bv);
            }
        }
    }
    // (post-mainloop staging writes buf0/buf1 + high slots only; buf2 [8192,12288)
    //  is the only region still read by warps finishing stage 23 — untouched here)

    // ---- stage W2/W3/cpW1/cpW2 fp16 b-frags + all biases ----
    {
        uh2* w2f = (uh2*)sm;               // [0,4096) h2
        int kp = tid >> 4, ng = tid & 15;
        int TKw = kp >> 2, q2 = kp & 3;
#pragma unroll
        for (int bw = 0; bw < 2; ++bw) {
            const float* W = bw ? negW2 : posW2;
#pragma unroll
            for (int sel = 0; sel < 2; ++sel) {
                int k0 = TKw * 16 + sel * 8 + 2 * q2;
                float4 v0 = *(const float4*)(W + ((size_t)c * HD + k0) * HD + ng * 4);
                float4 v1 = *(const float4*)(W + ((size_t)c * HD + k0 + 1) * HD + ng * 4);
                const float* l0 = (const float*)&v0;
                const float* l1 = (const float*)&v1;
#pragma unroll
                for (int j = 0; j < 4; ++j) {
                    int n = ng * 4 + j;
                    int tn = n >> 3, nn = n & 7;
                    int ls = (nn * 4 + q2) ^ ((TKw ^ tn) & 3);
                    w2f[bw * 2048 + (tn * 4 + TKw) * 64 + ls * 2 + sel] = h2p(l0[j], l1[j]);
                }
            }
        }
        // W3F: 1024 uh2 at [4096,5120)
        uh2* w3f = (uh2*)sm + 4096;
#pragma unroll
        for (int i = 0; i < 4; ++i) {
            int idx = tid + i * 256;          // 0..1023
            int bw = idx >> 9, slot = idx & 511;
            int tnTK = slot >> 6, tn = tnTK >> 2, TK = tnTK & 3;
            int rem = slot & 63, ls = rem >> 1, sel = rem & 1;
            int m = ls ^ ((TK ^ tn) & 3), nn = m >> 2, q2w = m & 3;
            int n = tn * 8 + nn;
            int k0 = TK * 16 + sel * 8 + 2 * q2w;
            const float* W = bw ? negW3 : posW3;
            float a = W[((size_t)c * HD + k0) * ED + n];
            float b = W[((size_t)c * HD + k0 + 1) * ED + n];
            w3f[idx] = h2p(a, b);
        }
        // CPW1F: 1024 uh2 at [5120,6144); K=32 (TK 0=pos e, 1=neg e), N=64
        uh2* cw1f = (uh2*)sm + CPW1_OFF;
#pragma unroll
        for (int i = 0; i < 4; ++i) {
            int idx = tid + i * 256;          // 0..1023
            int tnTK = idx >> 6, tn = tnTK >> 1, TK = tnTK & 1;
            int rem = idx & 63, ls = rem >> 1, sel = rem & 1;
            int m = ls ^ ((TK ^ tn) & 3), nn = m >> 2, q2w = m & 3;
            int n = tn * 8 + nn;
            int k0 = TK * 16 + sel * 8 + 2 * q2w;
            float a = cpW1[((size_t)c * 2 * ED + k0) * HD + n];
            float b = cpW1[((size_t)c * 2 * ED + k0 + 1) * HD + n];
            cw1f[idx] = h2p(a, b);
        }
        // CPW2F: 2048 uh2 at [6144,8192); K=64, N=64
        uh2* cw2f = (uh2*)sm + CPW2_OFF;
#pragma unroll
        for (int i = 0; i < 8; ++i) {
            int idx = tid + i * 256;          // 0..2047
            int tnTK = idx >> 6, tn = tnTK >> 2, TK = tnTK & 3;
            int rem = idx & 63, ls = rem >> 1, sel = rem & 1;
            int m = ls ^ ((TK ^ tn) & 3), nn = m >> 2, q2w = m & 3;
            int n = tn * 8 + nn;
            int k0 = TK * 16 + sel * 8 + 2 * q2w;
            float a = cpW2[((size_t)c * HD + k0) * HD + n];
            float b = cpW2[((size_t)c * HD + k0 + 1) * HD + n];
            cw2f[idx] = h2p(a, b);
        }
        if (tid < 64)        bias2[tid] = posb2[c * HD + tid];
        else if (tid < 128)  bias2[tid - 64 + 64] = negb2[c * HD + tid - 64];
        else if (tid < 192)  cpb1s[tid - 128] = cpb1[c * HD + tid - 128];
        else                 cpb2s[tid - 192] = cpb2[c * HD + tid - 192];
        if (tid < 64)        cpw3s[tid] = cpW3[(size_t)c * HD + tid];
    }
    __syncthreads();

    // ---- layer 2: A-fragments built directly from layer-1 acc registers ----
    float acc2[2][8][4];
#pragma unroll
    for (int m = 0; m < 2; m++)
#pragma unroll
        for (int n = 0; n < 8; n++)
#pragma unroll
            for (int j = 0; j < 4; j++) acc2[m][n][j] = 0.f;
    {
        const uh2* w2 = (const uh2*)sm + bank * 2048;
        const float* bs1 = bias1 + bank * 64;
#pragma unroll
        for (int m = 0; m < 2; ++m) {
#pragma unroll
            for (int TK2 = 0; TK2 < 4; ++TK2) {
                int t0 = 2 * TK2, t1 = t0 + 1;
                int c0 = t0 * 8 + 2 * qid, c1 = t1 * 8 + 2 * qid;
                uint4 a;
                a.x = h2p(relu_(acc[m][t0][0] + bs1[c0]),
                          relu_(acc[m][t0][1] + bs1[c0 + 1]));
                a.y = h2p(relu_(acc[m][t0][2] + bs1[c0]),
                          relu_(acc[m][t0][3] + bs1[c0 + 1]));
                a.z = h2p(relu_(acc[m][t1][0] + bs1[c1]),
                          relu_(acc[m][t1][1] + bs1[c1 + 1]));
                a.w = h2p(relu_(acc[m][t1][2] + bs1[c1]),
                          relu_(acc[m][t1][3] + bs1[c1 + 1]));
#pragma unroll
                for (int tn = 0; tn < 8; ++tn) {
                    uint2 bv = *(const uint2*)(w2 + (tn * 4 + TK2) * 64 +
                                               (lane ^ ((TK2 ^ tn) & 3)) * 2);
                    mma16(acc2[m][tn], a, bv);
                }
            }
        }
    }

    // ---- layer 3: A-fragments built directly from layer-2 acc registers ----
    float acc3[2][2][4];
#pragma unroll
    for (int m = 0; m < 2; m++)
#pragma unroll
        for (int n = 0; n < 2; n++)
#pragma unroll
            for (int j = 0; j < 4; j++) acc3[m][n][j] = 0.f;
    {
        const uh2* w3 = (const uh2*)sm + 4096 + bank * 512;
        const float* bs2 = bias2 + bank * 64;
#pragma unroll
        for (int m = 0; m < 2; ++m) {
#pragma unroll
            for (int TK3 = 0; TK3 < 4; ++TK3) {
                int t0 = 2 * TK3, t1 = t0 + 1;
                int c0 = t0 * 8 + 2 * qid, c1 = t1 * 8 + 2 * qid;
                uint4 a;
                a.x = h2p(relu_(acc2[m][t0][0] + bs2[c0]),
                          relu_(acc2[m][t0][1] + bs2[c0 + 1]));
                a.y = h2p(relu_(acc2[m][t0][2] + bs2[c0]),
                          relu_(acc2[m][t0][3] + bs2[c0 + 1]));
                a.z = h2p(relu_(acc2[m][t1][0] + bs2[c1]),
                          relu_(acc2[m][t1][1] + bs2[c1 + 1]));
                a.w = h2p(relu_(acc2[m][t1][2] + bs2[c1]),
                          relu_(acc2[m][t1][3] + bs2[c1 + 1]));
#pragma unroll
                for (int tn = 0; tn < 2; ++tn) {
                    uint2 bv = *(const uint2*)(w3 + (tn * 4 + TK3) * 64 +
                                               (lane ^ ((TK3 ^ tn) & 3)) * 2);
                    mma16(acc3[m][tn], a, bv);
                }
            }
        }
    }

    // ---- epilogue3: +bias3 -> ps/ns fp32 AND psh/nsh fp16 A-frag layout ----
    {
        const float* b3g = (bank ? negb3 : posb3) + c * ED;
        float* obuf = bank ? ns : ps;
        uh2* ofrag  = (uh2*)sm + (bank ? NSH_OFF : PSH_OFF);
        float2 bv0 = *(const float2*)(b3g + 2 * qid);
        float2 bv1 = *(const float2*)(b3g + 8 + 2 * qid);
#pragma unroll
        for (int m = 0; m < 2; ++m) {
            int row = (wid & 3) * 32 + m * 16 + gid;
            int tm  = 2 * (wid & 3) + m;
            float v00 = acc3[m][0][0] + bv0.x, v01 = acc3[m][0][1] + bv0.y;
            float v02 = acc3[m][0][2] + bv0.x, v03 = acc3[m][0][3] + bv0.y;
            float v10 = acc3[m][1][0] + bv1.x, v11 = acc3[m][1][1] + bv1.y;
            float v12 = acc3[m][1][2] + bv1.x, v13 = acc3[m][1][3] + bv1.y;
            *(float2*)(obuf + row * ED + 2 * qid)           = make_float2(v00, v01);
            *(float2*)(obuf + (row + 8) * ED + 2 * qid)     = make_float2(v02, v03);
            *(float2*)(obuf + row * ED + 8 + 2 * qid)       = make_float2(v10, v11);
            *(float2*)(obuf + (row + 8) * ED + 8 + 2 * qid) = make_float2(v12, v13);
            uint4 pk;
            pk.x = h2p(v00, v01);   // row g,   k=2q,2q+1
            pk.y = h2p(v02, v03);   // row g+8
            pk.z = h2p(v10, v11);   // row g,   k=8+2q
            pk.w = h2p(v12, v13);   // row g+8
            *(uint4*)(ofrag + tm * 128 + lane * 4) = pk;
        }
    }
    __syncthreads();

    // ---- cp layer 1 (fp16 mma): each warp one m16 tile, K=32 (pos||neg) ----
    float ac1[8][4];
#pragma unroll
    for (int n = 0; n < 8; n++)
#pragma unroll
        for (int j = 0; j < 4; j++) ac1[n][j] = 0.f;
    {
        const uh2* cw1 = (const uh2*)sm + CPW1_OFF;
        uint4 ap = *(const uint4*)((const uh2*)sm + PSH_OFF + wid * 128 + lane * 4);
        uint4 an = *(const uint4*)((const uh2*)sm + NSH_OFF + wid * 128 + lane * 4);
#pragma unroll
        for (int TK = 0; TK < 2; ++TK) {
            uint4 a = TK ? an : ap;
#pragma unroll
            for (int tn = 0; tn < 8; ++tn) {
                uint2 bv = *(const uint2*)(cw1 + (tn * 2 + TK) * 64 +
                                           (lane ^ ((TK ^ tn) & 3)) * 2);
                mma16(ac1[tn], a, bv);
            }
        }
    }

    // ---- cp layer 2 (fp16 mma): A-frags from ac1 registers ----
    float ac2[8][4];
#pragma unroll
    for (int n = 0; n < 8; n++)
#pragma unroll
        for (int j = 0; j < 4; j++) ac2[n][j] = 0.f;
    {
        const uh2* cw2 = (const uh2*)sm + CPW2_OFF;
#pragma unroll
        for (int TK2 = 0; TK2 < 4; ++TK2) {
            int t0 = 2 * TK2, t1 = t0 + 1;
            int c0 = t0 * 8 + 2 * qid, c1 = t1 * 8 + 2 * qid;
            uint4 a;
            a.x = h2p(relu_(ac1[t0][0] + cpb1s[c0]),
                      relu_(ac1[t0][1] + cpb1s[c0 + 1]));
            a.y = h2p(relu_(ac1[t0][2] + cpb1s[c0]),
                      relu_(ac1[t0][3] + cpb1s[c0 + 1]));
            a.z = h2p(relu_(ac1[t1][0] + cpb1s[c1]),
                      relu_(ac1[t1][1] + cpb1s[c1 + 1]));
            a.w = h2p(relu_(ac1[t1][2] + cpb1s[c1]),
                      relu_(ac1[t1][3] + cpb1s[c1 + 1]));
#pragma unroll
            for (int tn = 0; tn < 8; ++tn) {
                uint2 bv = *(const uint2*)(cw2 + (tn * 4 + TK2) * 64 +
                                           (lane ^ ((TK2 ^ tn) & 3)) * 2);
                mma16(ac2[tn], a, bv);
            }
        }
    }

    // ---- cp layer 3 in registers: dot(relu(ac2+b2), w3) + quad reduction ----
    {
        float s0 = 0.f, s1 = 0.f;
#pragma unroll
        for (int tn = 0; tn < 8; ++tn) {
            int c0 = tn * 8 + 2 * qid;
            float w0 = cpw3s[c0], w1 = cpw3s[c0 + 1];
            float b0 = cpb2s[c0], b1 = cpb2s[c0 + 1];
            s0 = fmaf(relu_(ac2[tn][0] + b0), w0, s0);
            s0 = fmaf(relu_(ac2[tn][1] + b1), w1, s0);
            s1 = fmaf(relu_(ac2[tn][2] + b0), w0, s1);
            s1 = fmaf(relu_(ac2[tn][3] + b1), w1, s1);
        }
        s0 += __shfl_xor_sync(0xFFFFFFFF, s0, 1);
        s0 += __shfl_xor_sync(0xFFFFFFFF, s0, 2);
        s1 += __shfl_xor_sync(0xFFFFFFFF, s1, 1);
        s1 += __shfl_xor_sync(0xFFFFFFFF, s1, 2);
        if (qid == 0) {
            float bb = cpb3[c];
            int row0 = wid * 16 + gid, row1 = row0 + 8;
            float c0v = s0 + bb, c1v = s1 + bb;
            out[(size_t)BATCH * ED * NC + (size_t)(r0 + row0) * NC + c] = c0v;
            out[(size_t)BATCH * ED * NC + (size_t)(r0 + row1) * NC + c] = c1v;
            gate[row0] = fminf(fmaxf(c0v * 0.5f + 0.5f, 0.f), 1.f);
            gate[row1] = fminf(fmaxf(c1v * 0.5f + 0.5f, 0.f), 1.f);
        }
    }
    __syncthreads();

    // ---- gated embedding output ----
    for (int t = tid; t < TILE_R * ED; t += NTHREADS) {
        int r = t >> 4, e = t & 15;
        float g = gate[r];
        float v = ps[r * ED + e] * g + ns[r * ED + e] * (1.f - g);
        out[(size_t)(r0 + r) * (ED * NC) + e * NC + c] = v;
    }
}

extern "C" void kernel_launch(void* const* d_in, const int* in_sizes, int n_in,
                              void* d_out, int out_size) {
    (void)in_sizes; (void)n_in; (void)out_size;

    prep_x<<<(BATCH / TILE_R) * NSTAGE, NTHREADS>>>((const float*)d_in[0]);
    prep_w<<<NC * NSTAGE, NTHREADS>>>((const float*)d_in[1], (const float*)d_in[7]);

    const int smem_bytes = SMEM_FLOATS * sizeof(float);   // 99328
    cudaFuncSetAttribute(cb_kernel, cudaFuncAttributeMaxDynamicSharedMemorySize, smem_bytes);
    dim3 grid(BATCH / TILE_R, NC);
    cb_kernel<<<grid, NTHREADS, smem_bytes>>>(
        (const float*)d_in[0],
        (const float*)d_in[1],  (const float*)d_in[2],
        (const float*)d_in[3],  (const float*)d_in[4],
        (const float*)d_in[5],  (const float*)d_in[6],
        (const float*)d_in[7],  (const float*)d_in[8],
        (const float*)d_in[9],  (const float*)d_in[10],
        (const float*)d_in[11], (const float*)d_in[12],
        (const float*)d_in[13], (const float*)d_in[14],
        (const float*)d_in[15], (const float*)d_in[16],
        (const float*)d_in[17], (const float*)d_in[18],
        (float*)d_out);
}

// round 17
// speedup vs baseline: 9.1881x; 1.1645x over previous
#include <cuda_runtime.h>
#include <cuda_fp16.h>
#include <cstdint>

// Problem constants
#define BATCH   8192
#define INDIM   768
#define NC      64
#define HD      64
#define ED      16
#define TILE_R  128
#define NTHREADS 256

// layer-1 staging: 24 stages of K=32, fp16, cp.async 3-deep pipeline
#define KC_T   32
#define NSTAGE (INDIM / KC_T)
#define STG_H2 4096            // uh2 per stage: A 2048 + Bpos 1024 + Bneg 1024 (16KB)
#define STG_BYTES 16384

// SMEM float offsets (phased aliasing):
// Phase A (layer1): 3 stage bufs [0,12288) float-slots.
// Tail weights (cp.async'd into buf0/buf1 during stages 22/23):
//   W2F h2 [0,4096), W3F h2 [4096,5120), CPW1F h2 [5120,6144), CPW2F h2 [6144,8192)
// Epilogue3 (post-mainloop): psh h2 [8192,9216), nsh h2 [9216,10240)  (buf2 region)
// Persistent (loaded at kernel start, never aliased):
//   ps [19456,21504), ns [21504,23552), gate [23552,23680),
//   cpb1s [23680,23744), cpb2s [23744,23808), cpw3s [23808,23872),
//   bias2 [24576,24704), bias1 [24704,24832)
#define PSH_OFF   8192
#define NSH_OFF   9216
#define CPW1_OFF  5120
#define CPW2_OFF  6144
#define PS_OFF    19456
#define NS_OFF    21504
#define GATE_OFF  23552
#define CPB1_OFF  23680
#define CPB2_OFF  23744
#define CPW3_OFF  23808
#define BIAS2_OFF 24576
#define BIAS1_OFF 24704
#define SMEM_FLOATS 24832      // 99328 bytes -> 2 CTAs/SM

typedef unsigned uh2;   // packed half2

// fp16 pre-converted, fragment-layout scratch (static __device__: allocation-free)
__device__ __align__(16) uh2 g_xh[(BATCH / TILE_R) * NSTAGE * 2048];   // [rblk][kblk][2048]
__device__ __align__(16) uh2 g_w1h[NC * NSTAGE * 2048];                // [c][kblk][pos1024|neg1024]
__device__ __align__(16) uh2 g_wtail[NC * 8192];                       // [c][W2F|W3F|CPW1F|CPW2F]
__device__ __align__(16) float g_emb[NC * BATCH * ED];                 // [c][b][e] coalesced staging

__device__ __forceinline__ float relu_(float v) { return v > 0.f ? v : 0.f; }

__device__ __forceinline__ uh2 h2p(float a, float b) {
    __half2 h = __floats2half2_rn(a, b);   // x (low) = a = smaller k
    return *(uh2*)&h;
}
__device__ __forceinline__ uint32_t smem_u32(const void* p) {
    uint32_t a;
    asm("{ .reg .u64 t; cvta.to.shared.u64 t, %1; cvt.u32.u64 %0, t; }" : "=r"(a) : "l"(p));
    return a;
}

#define CP_A16(dst, src) asm volatile("cp.async.cg.shared.global [%0], [%1], 16;" :: "r"(dst), "l"(src))
#define CP_COMMIT()      asm volatile("cp.async.commit_group;" ::: "memory")
#define CP_WAIT1()       asm volatile("cp.async.wait_group 1;" ::: "memory")
#define CP_WAIT0()       asm volatile("cp.async.wait_group 0;" ::: "memory")

// fp16 m16n8k16 mma (arch-agnostic PTX)
__device__ __forceinline__ void mma16(float* d, const uint4& a, const uint2& b) {
    asm volatile(
        "mma.sync.aligned.m16n8k16.row.col.f32.f16.f16.f32 "
        "{%0,%1,%2,%3}, {%4,%5,%6,%7}, {%8,%9}, {%0,%1,%2,%3};"
        : "+f"(d[0]), "+f"(d[1]), "+f"(d[2]), "+f"(d[3])
        : "r"(a.x), "r"(a.y), "r"(a.z), "r"(a.w), "r"(b.x), "r"(b.y));
}

// ---------------- prologue: build fp16 fragment-layout globals ----------------
__global__ void prep_x(const float* __restrict__ x) {
    int blk  = blockIdx.x;                 // rblk*NSTAGE + kblk
    int rblk = blk / NSTAGE, kblk = blk % NSTAGE;
    int r0 = rblk * TILE_R, kb = kblk * KC_T;
    uh2* dst = g_xh + (size_t)blk * 2048;
    int t = threadIdx.x;
#pragma unroll
    for (int i = 0; i < 4; ++i) {
        int slot = (t + i * 256) * 2;      // even slot of a uint2 pair
        int tmTK = slot >> 7, tm = tmTK >> 1, TK = tmTK & 1;
        int rem = slot & 127, L = rem >> 2, h2i = (rem >> 1) & 1;
        int lane = L ^ TK, g = lane >> 2, q = lane & 3;
        int kl = 2 * (TK * 8 + h2i * 4 + q);
        const float* p = x + (size_t)(r0 + tm * 16 + g) * INDIM + kb + kl;
        float2 v0 = *(const float2*)p;
        float2 v1 = *(const float2*)(p + 8 * INDIM);
        *(uint2*)(dst + slot) = make_uint2(h2p(v0.x, v0.y), h2p(v1.x, v1.y));
    }
}

__global__ void prep_w(const float* __restrict__ posW1, const float* __restrict__ negW1) {
    int blk = blockIdx.x;                  // c*NSTAGE + kblk
    int c = blk / NSTAGE, kblk = blk % NSTAGE, kb = kblk * KC_T;
    uh2* dst = g_w1h + (size_t)blk * 2048;
    int t = threadIdx.x;
#pragma unroll
    for (int i = 0; i < 8; ++i) {
        int idx = t + i * 256;             // 0..2047
        int bw = idx >> 10, slot = idx & 1023;
        int tnTK = slot >> 6, tn = tnTK >> 1, TK = tnTK & 1;
        int rem = slot & 63, ls = rem >> 1, sel = rem & 1;
        int m = ls ^ ((TK ^ tn) & 3), nn = m >> 2, q2 = m & 3;
        int n = tn * 8 + nn;
        int k0 = TK * 16 + sel * 8 + 2 * q2;
        const float* W = bw ? negW1 : posW1;
        float a = W[((size_t)c * INDIM + kb + k0) * HD + n];
        float b = W[((size_t)c * INDIM + kb + k0 + 1) * HD + n];
        dst[idx] = h2p(a, b);
    }
}

// Tail weights: per-concept fragment images of W2/W3/cpW1/cpW2 (inverse of the
// proven in-kernel staging maps).
__global__ void prep_wtail(const float* __restrict__ posW2, const float* __restrict__ negW2,
                           const float* __restrict__ posW3, const float* __restrict__ negW3,
                           const float* __restrict__ cpW1,  const float* __restrict__ cpW2) {
    int c = blockIdx.x;
    uh2* dst = g_wtail + (size_t)c * 8192;
    int t = threadIdx.x;
    // W2F [0,4096): K=64 (TK<4), N=64, 2 banks
#pragma unroll
    for (int i = 0; i < 16; ++i) {
        int idx = t + i * 256;
        int bw = idx >> 11, slot = idx & 2047;
        int tnTK = slot >> 6, tn = tnTK >> 2, TK = tnTK & 3;
        int rem = slot & 63, ls = rem >> 1, sel = rem & 1;
        int m = ls ^ ((TK ^ tn) & 3), nn = m >> 2, q2 = m & 3;
        int n = tn * 8 + nn, k0 = TK * 16 + sel * 8 + 2 * q2;
        const float* W = bw ? negW2 : posW2;
        dst[idx] = h2p(W[((size_t)c * HD + k0) * HD + n],
                       W[((size_t)c * HD + k0 + 1) * HD + n]);
    }
    // W3F [4096,5120): K=64, N=16, 2 banks
#pragma unroll
    for (int i = 0; i < 4; ++i) {
        int idx = t + i * 256;
        int bw = idx >> 9, slot = idx & 511;
        int tnTK = slot >> 6, tn = tnTK >> 2, TK = tnTK & 3;
        int rem = slot & 63, ls = rem >> 1, sel = rem & 1;
        int m = ls ^ ((TK ^ tn) & 3), nn = m >> 2, q2 = m & 3;
        int n = tn * 8 + nn, k0 = TK * 16 + sel * 8 + 2 * q2;
        const float* W = bw ? negW3 : posW3;
        dst[4096 + idx] = h2p(W[((size_t)c * HD + k0) * ED + n],
                              W[((size_t)c * HD + k0 + 1) * ED + n]);
    }
    // CPW1F [5120,6144): K=32 (TK<2), N=64
#pragma unroll
    for (int i = 0; i < 4; ++i) {
        int idx = t + i * 256;
        int tnTK = idx >> 6, tn = tnTK >> 1, TK = tnTK & 1;
        int rem = idx & 63, ls = rem >> 1, sel = rem & 1;
        int m = ls ^ ((TK ^ tn) & 3), nn = m >> 2, q2 = m & 3;
        int n = tn * 8 + nn, k0 = TK * 16 + sel * 8 + 2 * q2;
        dst[5120 + idx] = h2p(cpW1[((size_t)c * 2 * ED + k0) * HD + n],
                              cpW1[((size_t)c * 2 * ED + k0 + 1) * HD + n]);
    }
    // CPW2F [6144,8192): K=64, N=64
#pragma unroll
    for (int i = 0; i < 8; ++i) {
        int idx = t + i * 256;
        int tnTK = idx >> 6, tn = tnTK >> 2, TK = tnTK & 3;
        int rem = idx & 63, ls = rem >> 1, sel = rem & 1;
        int m = ls ^ ((TK ^ tn) & 3), nn = m >> 2, q2 = m & 3;
        int n = tn * 8 + nn, k0 = TK * 16 + sel * 8 + 2 * q2;
        dst[6144 + idx] = h2p(cpW2[((size_t)c * HD + k0) * HD + n],
                              cpW2[((size_t)c * HD + k0 + 1) * HD + n]);
    }
}

// ---------------- stage copy: 4 x 16B cp.async per thread ----------------
__device__ __forceinline__ void cp_stage(uint32_t stg_b, const uh2* gA, const uh2* gB, int tid) {
    uint32_t da = stg_b + tid * 16;
    const char* sa = (const char*)gA + tid * 16;
    CP_A16(da, sa);
    CP_A16(da + 4096, sa + 4096);
    uint32_t db = stg_b + 8192 + tid * 16;
    const char* sb = (const char*)gB + tid * 16;
    CP_A16(db, sb);
    CP_A16(db + 4096, sb + 4096);
}

// 16KB linear copy (tail weights half) via cp.async
__device__ __forceinline__ void cp_tail(uint32_t dst_b, const char* src, int tid) {
    uint32_t d = dst_b + tid * 64;
    const char* s = src + tid * 64;
    CP_A16(d, s);
    CP_A16(d + 16, s + 16);
    CP_A16(d + 32, s + 32);
    CP_A16(d + 48, s + 48);
}

// ---------------- final transpose: g_emb[c][b][e] -> out[b][e*64+c] ----------------
#define TRB 16
__global__ void emb_tr(float* __restrict__ out) {
    extern __shared__ float tl[];          // 64 c-blocks x (16r x 16e), pad 257
    const int b0 = blockIdx.x * TRB;
    const int t = threadIdx.x;
#pragma unroll
    for (int i = 0; i < 16; ++i) {
        int l4 = t + i * 256;              // 0..4095 float4s
        int cc = l4 >> 6, rem = (l4 & 63) * 4;
        float4 v = *(const float4*)(g_emb + (size_t)cc * (BATCH * ED) + (size_t)b0 * ED + rem);
        float* dp = tl + cc * 257 + rem;
        dp[0] = v.x; dp[1] = v.y; dp[2] = v.z; dp[3] = v.w;
    }
    __syncthreads();
#pragma unroll
    for (int i = 0; i < 64; ++i) {
        int o = t + i * 256;               // o = r*1024 + e*64 + c
        int cc = o & 63, e = (o >> 6) & 15, r = o >> 10;
        out[(size_t)b0 * 1024 + o] = tl[cc * 257 + r * 16 + e];
    }
}

// ---------------- main kernel ----------------
__global__ __launch_bounds__(NTHREADS, 2)
void cb_kernel(
    const float* __restrict__ posb1, const float* __restrict__ posb2,
    const float* __restrict__ posb3,
    const float* __restrict__ negb1, const float* __restrict__ negb2,
    const float* __restrict__ negb3,
    const float* __restrict__ cpb1,  const float* __restrict__ cpb2,
    const float* __restrict__ cpW3,  const float* __restrict__ cpb3,
    float* __restrict__ out)
{
    extern __shared__ float sm[];
    float* ps     = sm + PS_OFF;
    float* ns     = sm + NS_OFF;
    float* gate   = sm + GATE_OFF;
    float* bias1  = sm + BIAS1_OFF;
    float* bias2  = sm + BIAS2_OFF;
    float* cpb1s  = sm + CPB1_OFF;
    float* cpb2s  = sm + CPB2_OFF;
    float* cpw3s  = sm + CPW3_OFF;

    const int tid  = threadIdx.x;
    const int wid  = tid >> 5, lane = tid & 31;
    const int c    = blockIdx.y;
    const int r0   = blockIdx.x * TILE_R;

    // all small per-concept vectors up front (persistent region, never aliased)
    if (tid < 64)       { bias1[tid] = posb1[c * HD + tid];
                          bias2[tid] = posb2[c * HD + tid]; }
    else if (tid < 128) { bias1[tid] = negb1[c * HD + tid - 64];
                          bias2[tid] = negb2[c * HD + tid - 64]; }
    else if (tid < 192) { cpb1s[tid - 128] = cpb1[c * HD + tid - 128];
                          cpw3s[tid - 128] = cpW3[(size_t)c * HD + tid - 128]; }
    else                { cpb2s[tid - 192] = cpb2[c * HD + tid - 192]; }

    const int bank = wid >> 2;             // 0: pos, 1: neg
    const int tmA  = (wid & 3) * 2;
    const int tmB  = tmA + 1;
    const int gid  = lane >> 2, qid = lane & 3;

    // ---- layer 1: fp16 m16n8k16, 24 stages via cp.async 3-deep pipeline ----
    float acc[2][8][4];
#pragma unroll
    for (int m = 0; m < 2; m++)
#pragma unroll
        for (int n = 0; n < 8; n++)
#pragma unroll
            for (int j = 0; j < 4; j++) acc[m][n][j] = 0.f;

    const uint32_t smb = smem_u32(sm);
    const uh2* gA = g_xh + (size_t)blockIdx.x * (NSTAGE * 2048);
    const uh2* gB = g_w1h + (size_t)c * (NSTAGE * 2048);
    const char* gT = (const char*)(g_wtail + (size_t)c * 8192);

    cp_stage(smb, gA, gB, tid);                       CP_COMMIT();
    cp_stage(smb + STG_BYTES, gA + 2048, gB + 2048, tid); CP_COMMIT();

    for (int s = 0; s < NSTAGE; ++s) {
        CP_WAIT1();
        __syncthreads();
        if (s + 2 < NSTAGE) {
            cp_stage(smb + ((s + 2) % 3) * STG_BYTES,
                     gA + (s + 2) * 2048, gB + (s + 2) * 2048, tid);
            CP_COMMIT();
        } else if (s == NSTAGE - 2) {
            // buf0 free (all warps passed stage-21 compute): tail weights half A
            cp_tail(smb, gT, tid);
            CP_COMMIT();
        } else {                           // s == NSTAGE-1
            // buf1 free (all warps passed stage-22 compute): tail weights half B
            cp_tail(smb + STG_BYTES, gT + STG_BYTES, tid);
            CP_COMMIT();
        }
        const uh2* A  = (const uh2*)sm + (s % 3) * STG_H2;
        const uh2* Bb = A + 2048 + bank * 1024;
#pragma unroll
        for (int TK = 0; TK < 2; ++TK) {
            uint4 a0 = *(const uint4*)(A + (tmA * 2 + TK) * 128 + (lane ^ TK) * 4);
            uint4 a1 = *(const uint4*)(A + (tmB * 2 + TK) * 128 + (lane ^ TK) * 4);
#pragma unroll
            for (int tn = 0; tn < 8; ++tn) {
                uint2 bv = *(const uint2*)(Bb + (tn * 2 + TK) * 64 +
                                           (lane ^ ((TK ^ tn) & 3)) * 2);
                mma16(acc[0][tn], a0, bv);
                mma16(acc[1][tn], a1, bv);
            }
        }
    }
    CP_WAIT0();        // tail weights landed (all threads' groups)
    __syncthreads();   // ... and visible to all warps

    // ---- layer 2: A-fragments built directly from layer-1 acc registers ----
    float acc2[2][8][4];
#pragma unroll
    for (int m = 0; m < 2; m++)
#pragma unroll
        for (int n = 0; n < 8; n++)
#pragma unroll
            for (int j = 0; j < 4; j++) acc2[m][n][j] = 0.f;
    {
        const uh2* w2 = (const uh2*)sm + bank * 2048;
        const float* bs1 = bias1 + bank * 64;
#pragma unroll
        for (int m = 0; m < 2; ++m) {
#pragma unroll
            for (int TK2 = 0; TK2 < 4; ++TK2) {
                int t0 = 2 * TK2, t1 = t0 + 1;
                int c0 = t0 * 8 + 2 * qid, c1 = t1 * 8 + 2 * qid;
                uint4 a;
                a.x = h2p(relu_(acc[m][t0][0] + bs1[c0]),
                          relu_(acc[m][t0][1] + bs1[c0 + 1]));
                a.y = h2p(relu_(acc[m][t0][2] + bs1[c0]),
                          relu_(acc[m][t0][3] + bs1[c0 + 1]));
                a.z = h2p(relu_(acc[m][t1][0] + bs1[c1]),
                          relu_(acc[m][t1][1] + bs1[c1 + 1]));
                a.w = h2p(relu_(acc[m][t1][2] + bs1[c1]),
                          relu_(acc[m][t1][3] + bs1[c1 + 1]));
#pragma unroll
                for (int tn = 0; tn < 8; ++tn) {
                    uint2 bv = *(const uint2*)(w2 + (tn * 4 + TK2) * 64 +
                                               (lane ^ ((TK2 ^ tn) & 3)) * 2);
                    mma16(acc2[m][tn], a, bv);
                }
            }
        }
    }

    // ---- layer 3: A-fragments built directly from layer-2 acc registers ----
    float acc3[2][2][4];
#pragma unroll
    for (int m = 0; m < 2; m++)
#pragma unroll
        for (int n = 0; n < 2; n++)
#pragma unroll
            for (int j = 0; j < 4; j++) acc3[m][n][j] = 0.f;
    {
        const uh2* w3 = (const uh2*)sm + 4096 + bank * 512;
        const float* bs2 = bias2 + bank * 64;
#pragma unroll
        for (int m = 0; m < 2; ++m) {
#pragma unroll
            for (int TK3 = 0; TK3 < 4; ++TK3) {
                int t0 = 2 * TK3, t1 = t0 + 1;
                int c0 = t0 * 8 + 2 * qid, c1 = t1 * 8 + 2 * qid;
                uint4 a;
                a.x = h2p(relu_(acc2[m][t0][0] + bs2[c0]),
                          relu_(acc2[m][t0][1] + bs2[c0 + 1]));
                a.y = h2p(relu_(acc2[m][t0][2] + bs2[c0]),
                          relu_(acc2[m][t0][3] + bs2[c0 + 1]));
                a.z = h2p(relu_(acc2[m][t1][0] + bs2[c1]),
                          relu_(acc2[m][t1][1] + bs2[c1 + 1]));
                a.w = h2p(relu_(acc2[m][t1][2] + bs2[c1]),
                          relu_(acc2[m][t1][3] + bs2[c1 + 1]));
#pragma unroll
                for (int tn = 0; tn < 2; ++tn) {
                    uint2 bv = *(const uint2*)(w3 + (tn * 4 + TK3) * 64 +
                                               (lane ^ ((TK3 ^ tn) & 3)) * 2);
                    mma16(acc3[m][tn], a, bv);
                }
            }
        }
    }

    // ---- epilogue3: +bias3 -> ps/ns fp32 AND psh/nsh fp16 A-frag layout ----
    {
        const float* b3g = (bank ? negb3 : posb3) + c * ED;
        float* obuf = bank ? ns : ps;
        uh2* ofrag  = (uh2*)sm + (bank ? NSH_OFF : PSH_OFF);
        float2 bv0 = *(const float2*)(b3g + 2 * qid);
        float2 bv1 = *(const float2*)(b3g + 8 + 2 * qid);
#pragma unroll
        for (int m = 0; m < 2; ++m) {
            int row = (wid & 3) * 32 + m * 16 + gid;
            int tm  = 2 * (wid & 3) + m;
            float v00 = acc3[m][0][0] + bv0.x, v01 = acc3[m][0][1] + bv0.y;
            float v02 = acc3[m][0][2] + bv0.x, v03 = acc3[m][0][3] + bv0.y;
            float v10 = acc3[m][1][0] + bv1.x, v11 = acc3[m][1][1] + bv1.y;
            float v12 = acc3[m][1][2] + bv1.x, v13 = acc3[m][1][3] + bv1.y;
            *(float2*)(obuf + row * ED + 2 * qid)           = make_float2(v00, v01);
            *(float2*)(obuf + (row + 8) * ED + 2 * qid)     = make_float2(v02, v03);
            *(float2*)(obuf + row * ED + 8 + 2 * qid)       = make_float2(v10, v11);
            *(float2*)(obuf + (row + 8) * ED + 8 + 2 * qid) = make_float2(v12, v13);
            uint4 pk;
            pk.x = h2p(v00, v01);   // row g,   k=2q,2q+1
            pk.y = h2p(v02, v03);   // row g+8
            pk.z = h2p(v10, v11);   // row g,   k=8+2q
            pk.w = h2p(v12, v13);   // row g+8
            *(uint4*)(ofrag + tm * 128 + lane * 4) = pk;
        }
    }
    __syncthreads();

    // ---- cp layer 1 (fp16 mma): each warp one m16 tile, K=32 (pos||neg) ----
    float ac1[8][4];
#pragma unroll
    for (int n = 0; n < 8; n++)
#pragma unroll
        for (int j = 0; j < 4; j++) ac1[n][j] = 0.f;
    {
        const uh2* cw1 = (const uh2*)sm + CPW1_OFF;
        uint4 ap = *(const uint4*)((const uh2*)sm + PSH_OFF + wid * 128 + lane * 4);
        uint4 an = *(const uint4*)((const uh2*)sm + NSH_OFF + wid * 128 + lane * 4);
#pragma unroll
        for (int TK = 0; TK < 2; ++TK) {
            uint4 a = TK ? an : ap;
#pragma unroll
            for (int tn = 0; tn < 8; ++tn) {
                uint2 bv = *(const uint2*)(cw1 + (tn * 2 + TK) * 64 +
                                           (lane ^ ((TK ^ tn) & 3)) * 2);
                mma16(ac1[tn], a, bv);
            }
        }
    }

    // ---- cp layer 2 (fp16 mma): A-frags from ac1 registers ----
    float ac2[8][4];
#pragma unroll
    for (int n = 0; n < 8; n++)
#pragma unroll
        for (int j = 0; j < 4; j++) ac2[n][j] = 0.f;
    {
        const uh2* cw2 = (const uh2*)sm + CPW2_OFF;
#pragma unroll
        for (int TK2 = 0; TK2 < 4; ++TK2) {
            int t0 = 2 * TK2, t1 = t0 + 1;
            int c0 = t0 * 8 + 2 * qid, c1 = t1 * 8 + 2 * qid;
            uint4 a;
            a.x = h2p(relu_(ac1[t0][0] + cpb1s[c0]),
                      relu_(ac1[t0][1] + cpb1s[c0 + 1]));
            a.y = h2p(relu_(ac1[t0][2] + cpb1s[c0]),
                      relu_(ac1[t0][3] + cpb1s[c0 + 1]));
            a.z = h2p(relu_(ac1[t1][0] + cpb1s[c1]),
                      relu_(ac1[t1][1] + cpb1s[c1 + 1]));
            a.w = h2p(relu_(ac1[t1][2] + cpb1s[c1]),
                      relu_(ac1[t1][3] + cpb1s[c1 + 1]));
#pragma unroll
            for (int tn = 0; tn < 8; ++tn) {
                uint2 bv = *(const uint2*)(cw2 + (tn * 4 + TK2) * 64 +
                                           (lane ^ ((TK2 ^ tn) & 3)) * 2);
                mma16(ac2[tn], a, bv);
            }
        }
    }

    // ---- cp layer 3 in registers: dot(relu(ac2+b2), w3) + quad reduction ----
    {
        float s0 = 0.f, s1 = 0.f;
#pragma unroll
        for (int tn = 0; tn < 8; ++tn) {
            int c0 = tn * 8 + 2 * qid;
            float w0 = cpw3s[c0], w1 = cpw3s[c0 + 1];
            float b0 = cpb2s[c0], b1 = cpb2s[c0 + 1];
            s0 = fmaf(relu_(ac2[tn][0] + b0), w0, s0);
            s0 = fmaf(relu_(ac2[tn][1] + b1), w1, s0);
            s1 = fmaf(relu_(ac2[tn][2] + b0), w0, s1);
            s1 = fmaf(relu_(ac2[tn][3] + b1), w1, s1);
        }
        s0 += __shfl_xor_sync(0xFFFFFFFF, s0, 1);
        s0 += __shfl_xor_sync(0xFFFFFFFF, s0, 2);
        s1 += __shfl_xor_sync(0xFFFFFFFF, s1, 1);
        s1 += __shfl_xor_sync(0xFFFFFFFF, s1, 2);
        if (qid == 0) {
            float bb = cpb3[c];
            int row0 = wid * 16 + gid, row1 = row0 + 8;
            float c0v = s0 + bb, c1v = s1 + bb;
            out[(size_t)BATCH * ED * NC + (size_t)(r0 + row0) * NC + c] = c0v;
            out[(size_t)BATCH * ED * NC + (size_t)(r0 + row1) * NC + c] = c1v;
            gate[row0] = fminf(fmaxf(c0v * 0.5f + 0.5f, 0.f), 1.f);
            gate[row1] = fminf(fmaxf(c1v * 0.5f + 0.5f, 0.f), 1.f);
        }
    }
    __syncthreads();

    // ---- gated embedding -> g_emb[c][b][e] (fully coalesced float4) ----
    for (int t2 = tid; t2 < TILE_R * 4; t2 += NTHREADS) {
        int r = t2 >> 2, e4 = (t2 & 3) * 4;
        float g = gate[r];
        float4 p = *(const float4*)(ps + r * ED + e4);
        float4 q = *(const float4*)(ns + r * ED + e4);
        float4 v;
        v.x = p.x * g + q.x * (1.f - g);
        v.y = p.y * g + q.y * (1.f - g);
        v.z = p.z * g + q.z * (1.f - g);
        v.w = p.w * g + q.w * (1.f - g);
        *(float4*)(g_emb + (size_t)c * (BATCH * ED) + (size_t)(r0 + r) * ED + e4) = v;
    }
}

extern "C" void kernel_launch(void* const* d_in, const int* in_sizes, int n_in,
                              void* d_out, int out_size) {
    (void)in_sizes; (void)n_in; (void)out_size;

    prep_x<<<(BATCH / TILE_R) * NSTAGE, NTHREADS>>>((const float*)d_in[0]);
    prep_w<<<NC * NSTAGE, NTHREADS>>>((const float*)d_in[1], (const float*)d_in[7]);
    prep_wtail<<<NC, NTHREADS>>>((const float*)d_in[3],  (const float*)d_in[9],
                                 (const float*)d_in[5],  (const float*)d_in[11],
                                 (const float*)d_in[13], (const float*)d_in[15]);

    const int smem_bytes = SMEM_FLOATS * sizeof(float);   // 99328
    cudaFuncSetAttribute(cb_kernel, cudaFuncAttributeMaxDynamicSharedMemorySize, smem_bytes);
    dim3 grid(BATCH / TILE_R, NC);
    cb_kernel<<<grid, NTHREADS, smem_bytes>>>(
        (const float*)d_in[2],  (const float*)d_in[4],  (const float*)d_in[6],
        (const float*)d_in[8],  (const float*)d_in[10], (const float*)d_in[12],
        (const float*)d_in[14], (const float*)d_in[16],
        (const float*)d_in[17], (const float*)d_in[18],
        (float*)d_out);

    const int tr_smem = (64 * 257 + 16) * sizeof(float);  // 65856
    cudaFuncSetAttribute(emb_tr, cudaFuncAttributeMaxDynamicSharedMemorySize, tr_smem);
    emb_tr<<<BATCH / TRB, NTHREADS, tr_smem>>>((float*)d_out);
}